// round 1
// baseline (speedup 1.0000x reference)
#include <cuda_runtime.h>
#include <cuda_bf16.h>
#include <math.h>

// Problem constants
#define BS   8
#define TS   2048
#define NH   4
#define DIM  512
#define VDIM 512
#define QDIM 1024
#define KS   100
#define KN   100
#define TEMP 0.5f

#define MDIM (BS*TS)         // 16384 rows for K/V GEMMs
#define NKV  (NH*DIM)        // 2048

// ---------------- scratch (static device allocations) ----------------
__device__ float g_P[KN * (2*KS+2)];           // prefix sums [100][202]
__device__ float g_q[BS * NKV];                 // tanh(query) [8][2048]
__device__ float g_conv[BS * TS * KN];          // [16384][100]
__device__ float g_key[(size_t)MDIM * NKV];     // tanh(key)   [16384][2048] 128MB
__device__ float g_value[(size_t)MDIM * NKV];   // tanh(value) [16384][2048] 128MB
__device__ float g_loc[(size_t)MDIM * DIM];     // tanh(loc)   [16384][512]  32MB
__device__ float g_energy[BS * NH * TS];        // [32][2048]
__device__ float g_ctx[BS * NH * VDIM];         // [8][2048]

// ---------------- kernel 0: conv-weight prefix sums ----------------
__global__ void prefix_kernel(const float* __restrict__ w /*[KN][NH][201]*/,
                              float* __restrict__ P /*[KN][202]*/) {
    int k = threadIdx.x;
    if (k >= KN) return;
    float s = 0.0f;
    P[k * 202 + 0] = 0.0f;
    for (int t = 0; t < 2*KS+1; t++) {
        float ws = 0.0f;
        #pragma unroll
        for (int h = 0; h < NH; h++) ws += w[(k*NH + h)*(2*KS+1) + t];
        s += ws;
        P[k * 202 + t + 1] = s;
    }
}

// ---------------- kernel 1: query projection (warp per output) ----------------
__global__ void query_kernel(const float* __restrict__ dec, const float* __restrict__ Wq,
                             const float* __restrict__ bq, float* __restrict__ q) {
    int gw = (blockIdx.x * blockDim.x + threadIdx.x) >> 5;
    int lane = threadIdx.x & 31;
    if (gw >= BS * NKV) return;
    int b = gw >> 11, n = gw & (NKV - 1);
    const float* x = dec + b * QDIM;
    const float* w = Wq + (size_t)n * QDIM;
    float acc = 0.0f;
    for (int k = lane; k < QDIM; k += 32) acc += x[k] * w[k];
    #pragma unroll
    for (int o = 16; o; o >>= 1) acc += __shfl_xor_sync(0xffffffffu, acc, o);
    if (!lane) q[gw] = tanhf(acc + bq[n]);
}

// ---------------- kernel 2: location conv via prefix diff ----------------
__global__ void conv_kernel(const int* __restrict__ enc_len, float* __restrict__ conv) {
    int idx = blockIdx.x * blockDim.x + threadIdx.x;
    if (idx >= BS * TS * KN) return;
    int k = idx % KN;
    int t = (idx / KN) % TS;
    int b = idx / (KN * TS);
    int len = enc_len[b];
    int lo = max(0, KS - t);
    int hi = min(2*KS + 1, KS - t + len);
    float v = 0.0f;
    if (hi > lo) v = (g_P[k*202 + hi] - g_P[k*202 + lo]) / (float)len;
    conv[idx] = v;   // layout [(b*TS+t)][k]
}

// ---------------- tiled SGEMM with bias + tanh epilogue ----------------
// C[m][n] = tanh( sum_k A[m][k]*B[n][k] + bias[n] ).  M%128==0, N%128==0, K%4==0.
__global__ __launch_bounds__(256)
void gemm_tanh(const float* __restrict__ A, const float* __restrict__ B,
               const float* __restrict__ bias, float* __restrict__ C,
               int M, int N, int K) {
    const int BK = 16;
    __shared__ float As[BK][128];
    __shared__ float Bs[BK][128];
    int bm = blockIdx.y * 128;
    int bn = blockIdx.x * 128;
    int tid = threadIdx.x;
    int trow = (tid >> 4) * 8;      // 16 row-groups
    int tcol = (tid & 15) * 8;      // 16 col-groups
    float acc[8][8];
    #pragma unroll
    for (int i = 0; i < 8; i++)
        #pragma unroll
        for (int j = 0; j < 8; j++) acc[i][j] = 0.0f;

    for (int k0 = 0; k0 < K; k0 += BK) {
        // load 128x16 A-tile and B-tile (512 float4 slots each, 2 per thread)
        #pragma unroll
        for (int s = tid; s < 512; s += 256) {
            int row = s >> 2;
            int kq  = (s & 3) * 4;
            int gk  = k0 + kq;
            const float* ap = A + (size_t)(bm + row) * K + gk;
            const float* bp = B + (size_t)(bn + row) * K + gk;
            float4 va, vb;
            if (gk + 3 < K) {
                va = *(const float4*)ap;
                vb = *(const float4*)bp;
            } else {
                float ta[4], tb[4];
                #pragma unroll
                for (int i = 0; i < 4; i++) {
                    ta[i] = (gk + i < K) ? ap[i] : 0.0f;
                    tb[i] = (gk + i < K) ? bp[i] : 0.0f;
                }
                va = make_float4(ta[0], ta[1], ta[2], ta[3]);
                vb = make_float4(tb[0], tb[1], tb[2], tb[3]);
            }
            As[kq+0][row] = va.x; As[kq+1][row] = va.y;
            As[kq+2][row] = va.z; As[kq+3][row] = va.w;
            Bs[kq+0][row] = vb.x; Bs[kq+1][row] = vb.y;
            Bs[kq+2][row] = vb.z; Bs[kq+3][row] = vb.w;
        }
        __syncthreads();
        #pragma unroll
        for (int kk = 0; kk < BK; kk++) {
            float ra[8], rb[8];
            #pragma unroll
            for (int i = 0; i < 8; i++) ra[i] = As[kk][trow + i];
            #pragma unroll
            for (int j = 0; j < 8; j++) rb[j] = Bs[kk][tcol + j];
            #pragma unroll
            for (int i = 0; i < 8; i++)
                #pragma unroll
                for (int j = 0; j < 8; j++) acc[i][j] += ra[i] * rb[j];
        }
        __syncthreads();
    }

    float bj[8];
    #pragma unroll
    for (int j = 0; j < 8; j++) bj[j] = bias ? bias[bn + tcol + j] : 0.0f;
    #pragma unroll
    for (int i = 0; i < 8; i++) {
        size_t off = (size_t)(bm + trow + i) * N + bn + tcol;
        #pragma unroll
        for (int j = 0; j < 8; j++)
            C[off + j] = tanhf(acc[i][j] + bj[j]);
    }
}

// ---------------- kernel 4: additive energy (warp per (b,h,t)) ----------------
__global__ void energy_kernel(const float* __restrict__ gen_w, const float* __restrict__ gen_b) {
    int gw = (blockIdx.x * blockDim.x + threadIdx.x) >> 5;
    int lane = threadIdx.x & 31;
    if (gw >= BS * NH * TS) return;
    int t = gw & (TS - 1);
    int h = (gw >> 11) & (NH - 1);
    int b = gw >> 13;
    const float* krow = g_key + (size_t)(b * TS + t) * NKV + h * DIM;
    const float* qrow = g_q + b * NKV + h * DIM;
    const float* lrow = g_loc + (size_t)(b * TS + t) * DIM;
    float acc = 0.0f;
    for (int d = lane; d < DIM; d += 32)
        acc += gen_w[d] * tanhf(krow[d] + qrow[d] + lrow[d]);
    #pragma unroll
    for (int o = 16; o; o >>= 1) acc += __shfl_xor_sync(0xffffffffu, acc, o);
    if (!lane) g_energy[gw] = (acc + gen_b[0]) * (1.0f / TEMP);
}

// ---------------- kernel 5: masked softmax -> attn (writes d_out) ----------------
__global__ void softmax_kernel(const int* __restrict__ enc_len, float* __restrict__ attn) {
    __shared__ float red[8];
    __shared__ float bcast;
    int bh = blockIdx.x;
    int b = bh >> 2;
    int len = enc_len[b];
    const float* e = g_energy + bh * TS;
    float* a = attn + bh * TS;
    int tid = threadIdx.x, lane = tid & 31, w = tid >> 5;

    float m = -INFINITY;
    for (int t = tid; t < len; t += 256) m = fmaxf(m, e[t]);
    #pragma unroll
    for (int o = 16; o; o >>= 1) m = fmaxf(m, __shfl_xor_sync(0xffffffffu, m, o));
    if (!lane) red[w] = m;
    __syncthreads();
    if (tid < 8) {
        float x = red[tid];
        #pragma unroll
        for (int o = 4; o; o >>= 1) x = fmaxf(x, __shfl_xor_sync(0xffu, x, o));
        if (!tid) bcast = x;
    }
    __syncthreads();
    m = bcast;
    __syncthreads();

    float s = 0.0f;
    for (int t = tid; t < len; t += 256) s += expf(e[t] - m);
    #pragma unroll
    for (int o = 16; o; o >>= 1) s += __shfl_xor_sync(0xffffffffu, s, o);
    if (!lane) red[w] = s;
    __syncthreads();
    if (tid < 8) {
        float x = red[tid];
        #pragma unroll
        for (int o = 4; o; o >>= 1) x += __shfl_xor_sync(0xffu, x, o);
        if (!tid) bcast = x;
    }
    __syncthreads();
    float inv = 1.0f / bcast;
    for (int t = tid; t < TS; t += 256)
        a[t] = (t < len) ? expf(e[t] - m) * inv : 0.0f;
}

// ---------------- kernel 6: context weighted sum ----------------
__global__ void ctx_zero_kernel() {
    int i = blockIdx.x * blockDim.x + threadIdx.x;
    if (i < BS * NH * VDIM) g_ctx[i] = 0.0f;
}

__global__ void ctx_kernel(const float* __restrict__ attn, const int* __restrict__ enc_len) {
    // grid: b*NH*8 chunks, 512 threads (v)
    int chunk = blockIdx.x & 7;
    int h = (blockIdx.x >> 3) & (NH - 1);
    int b = blockIdx.x >> 5;
    int v = threadIdx.x;
    int len = enc_len[b];
    int t0 = chunk * (TS / 8);
    int t1 = min(t0 + TS / 8, len);
    if (t0 >= t1) return;
    const float* arow = attn + (b * NH + h) * TS;
    const float* vbase = g_value + (size_t)(b * TS) * NKV + h * VDIM + v;
    float acc = 0.0f;
    for (int t = t0; t < t1; t++)
        acc += arow[t] * vbase[(size_t)t * NKV];
    atomicAdd(&g_ctx[(b * NH + h) * VDIM + v], acc);
}

// ---------------- kernel 7: merge projection (warp per output) ----------------
__global__ void merge_kernel(const float* __restrict__ Wm, const float* __restrict__ bm,
                             float* __restrict__ out) {
    int gw = (blockIdx.x * blockDim.x + threadIdx.x) >> 5;
    int lane = threadIdx.x & 31;
    if (gw >= BS * VDIM) return;
    int b = gw >> 9, j = gw & (VDIM - 1);
    const float* x = g_ctx + b * (NH * VDIM);
    const float* w = Wm + (size_t)j * (NH * VDIM);
    float acc = 0.0f;
    for (int k = lane; k < NH * VDIM; k += 32) acc += x[k] * w[k];
    #pragma unroll
    for (int o = 16; o; o >>= 1) acc += __shfl_xor_sync(0xffffffffu, acc, o);
    if (!lane) out[gw] = acc + bm[j];
}

// ---------------- launch ----------------
extern "C" void kernel_launch(void* const* d_in, const int* in_sizes, int n_in,
                              void* d_out, int out_size) {
    const float* dec_state  = (const float*)d_in[0];
    const float* enc_feat   = (const float*)d_in[1];
    const int*   enc_len    = (const int*)  d_in[2];
    const float* Wq         = (const float*)d_in[3];
    const float* bq         = (const float*)d_in[4];
    const float* Wk         = (const float*)d_in[5];
    const float* bk         = (const float*)d_in[6];
    const float* Wv         = (const float*)d_in[7];
    const float* bv         = (const float*)d_in[8];
    const float* loc_conv_w = (const float*)d_in[9];
    const float* loc_proj_w = (const float*)d_in[10];
    const float* gen_w      = (const float*)d_in[11];
    const float* gen_b      = (const float*)d_in[12];
    const float* merge_w    = (const float*)d_in[13];
    const float* merge_b    = (const float*)d_in[14];

    float* out = (float*)d_out;
    float* out_attn = out;                       // [8,4,2048]
    float* out_ctx  = out + BS * NH * TS;        // [8,512]

    static float *pP = nullptr, *pQ = nullptr, *pConv = nullptr, *pKey = nullptr,
                 *pVal = nullptr, *pLoc = nullptr;
    if (!pP) {
        cudaGetSymbolAddress((void**)&pP,    g_P);
        cudaGetSymbolAddress((void**)&pQ,    g_q);
        cudaGetSymbolAddress((void**)&pConv, g_conv);
        cudaGetSymbolAddress((void**)&pKey,  g_key);
        cudaGetSymbolAddress((void**)&pVal,  g_value);
        cudaGetSymbolAddress((void**)&pLoc,  g_loc);
    }

    // 0) prefix sums of conv weights
    prefix_kernel<<<1, 128>>>(loc_conv_w, pP);

    // 1) query projection: 16384 warps
    query_kernel<<<(BS * NKV * 32 + 255) / 256, 256>>>(dec_state, Wq, bq, pQ);

    // 2) conv via prefix diff
    conv_kernel<<<(BS * TS * KN + 255) / 256, 256>>>(enc_len, pConv);

    // 3) GEMMs: key, value, loc
    {
        dim3 gk(NKV / 128, MDIM / 128);
        gemm_tanh<<<gk, 256>>>(enc_feat, Wk, bk, pKey, MDIM, NKV, VDIM);
        gemm_tanh<<<gk, 256>>>(enc_feat, Wv, bv, pVal, MDIM, NKV, VDIM);
        dim3 gl(DIM / 128, MDIM / 128);
        gemm_tanh<<<gl, 256>>>(pConv, loc_proj_w, nullptr, pLoc, MDIM, DIM, KN);
    }

    // 4) energy: 65536 warps
    energy_kernel<<<(BS * NH * TS * 32 + 127) / 128, 128>>>(gen_w, gen_b);

    // 5) softmax -> attn (d_out)
    softmax_kernel<<<BS * NH, 256>>>(enc_len, out_attn);

    // 6) context
    ctx_zero_kernel<<<(BS * NH * VDIM + 255) / 256, 256>>>();
    ctx_kernel<<<BS * NH * 8, VDIM>>>(out_attn, enc_len);

    // 7) merge -> context (d_out tail)
    merge_kernel<<<(BS * VDIM * 32 + 255) / 256, 256>>>(merge_w, merge_b, out_ctx);
}

// round 3
// speedup vs baseline: 2.9369x; 2.9369x over previous
#include <cuda_runtime.h>
#include <cuda_bf16.h>
#include <math.h>
#include <cstdint>

// Problem constants
#define BS   8
#define TS   2048
#define NH   4
#define DIM  512
#define VDIM 512
#define QDIM 1024
#define KS   100
#define KN   100
#define TEMP 0.5f

#define MDIM (BS*TS)         // 16384 rows for K/V GEMMs
#define NKV  (NH*DIM)        // 2048

// ---------------- scratch (static device allocations) ----------------
__device__ float g_P[KN * (2*KS+2)];            // prefix sums [100][202]
__device__ float g_q[BS * NKV];                 // tanh(query) [8][2048]
__device__ float g_conv[BS * TS * KN];          // [16384][100]
__device__ float g_key[(size_t)MDIM * NKV];     // tanh(key)   [16384][2048]
__device__ float g_value[(size_t)MDIM * NKV];   // tanh(value) [16384][2048]
__device__ float g_loc[(size_t)MDIM * DIM];     // tanh(loc)   [16384][512]
__device__ float g_energy[BS * NH * TS];
__device__ float g_ctx[BS * NH * VDIM];
__device__ float g_Atf[(size_t)MDIM * VDIM];    // tf32-rounded enc_feat
__device__ float g_Bk[NKV * VDIM];              // tf32-rounded Wk
__device__ float g_Bv[NKV * VDIM];              // tf32-rounded Wv

// ---------------- kernel: tf32 rounding (round-to-nearest) ----------------
__global__ void tf32_round_kernel(const float4* __restrict__ in, float4* __restrict__ outp, int n4) {
    int i = blockIdx.x * blockDim.x + threadIdx.x;
    if (i >= n4) return;
    float4 v = in[i];
    uint32_t a, b, c, d;
    asm("cvt.rna.tf32.f32 %0, %1;" : "=r"(a) : "f"(v.x));
    asm("cvt.rna.tf32.f32 %0, %1;" : "=r"(b) : "f"(v.y));
    asm("cvt.rna.tf32.f32 %0, %1;" : "=r"(c) : "f"(v.z));
    asm("cvt.rna.tf32.f32 %0, %1;" : "=r"(d) : "f"(v.w));
    outp[i] = make_float4(__uint_as_float(a), __uint_as_float(b), __uint_as_float(c), __uint_as_float(d));
}

// ================= tf32 mma.sync GEMM + bias + tanh =================
// C[m][n] = tanh( sum_k A[m][k]*B[n][k] + bias[n] )
// CTA tile 128x128, BK=32, 3-stage cp.async pipeline, warp tile 64x32.
#define GSTAGES 3
#define BKK     32
#define PADK    36                       // floats per smem row (conflict-free frags)
#define ATILE_F (128 * PADK)             // 4608 floats
#define STAGE_F (2 * ATILE_F)            // A + B per stage
#define GSMEM_BYTES (GSTAGES * STAGE_F * 4)   // 110592 B

__device__ __forceinline__ void mma_tf32(float* d,
                                         uint32_t a0, uint32_t a1, uint32_t a2, uint32_t a3,
                                         uint32_t b0, uint32_t b1) {
    asm volatile(
        "mma.sync.aligned.m16n8k8.row.col.f32.tf32.tf32.f32 "
        "{%0,%1,%2,%3}, {%4,%5,%6,%7}, {%8,%9}, {%0,%1,%2,%3};"
        : "+f"(d[0]), "+f"(d[1]), "+f"(d[2]), "+f"(d[3])
        : "r"(a0), "r"(a1), "r"(a2), "r"(a3), "r"(b0), "r"(b1));
}

__device__ __forceinline__ void cp_async16(uint32_t saddr, const void* gaddr) {
    asm volatile("cp.async.cg.shared.global [%0], [%1], 16;" :: "r"(saddr), "l"(gaddr) : "memory");
}
__device__ __forceinline__ uint32_t smem_u32(const void* p) {
    uint32_t a;
    asm("{ .reg .u64 t; cvta.to.shared.u64 t, %1; cvt.u32.u64 %0, t; }" : "=r"(a) : "l"(p));
    return a;
}

__global__ __launch_bounds__(256, 2)
void gemm_mma_tf32_tanh(const float* __restrict__ A, const float* __restrict__ B,
                        const float* __restrict__ bias, float* __restrict__ C,
                        int M, int N, int K) {
    extern __shared__ float sm[];
    const int tid = threadIdx.x;
    const int wid = tid >> 5, lane = tid & 31;
    const int wm = wid & 1, wn = wid >> 1;       // warp grid 2 x 4
    const int tr = lane >> 2, tc = lane & 3;
    const int bm = blockIdx.y * 128, bn = blockIdx.x * 128;
    const int NT = K / BKK;                       // 16 for K=512

    const uint32_t smb = smem_u32(sm);

    // per-thread load slots: 4 chunks of 16B per matrix per tile
    // chunk c (0..1023): row = c>>3, kc = c&7
    int c0 = tid;                                // + j*256

    float acc[4][4][4];
    #pragma unroll
    for (int mt = 0; mt < 4; mt++)
        #pragma unroll
        for (int nt = 0; nt < 4; nt++)
            #pragma unroll
            for (int r = 0; r < 4; r++) acc[mt][nt][r] = 0.0f;

    // prologue: load tiles 0..GSTAGES-2
    #pragma unroll
    for (int s = 0; s < GSTAGES - 1; ++s) {
        uint32_t sa = smb + (s * STAGE_F) * 4;
        uint32_t sb = sa + ATILE_F * 4;
        int kbase = s * BKK;
        #pragma unroll
        for (int j = 0; j < 4; ++j) {
            int c = c0 + j * 256;
            int row = c >> 3, kc = c & 7;
            uint32_t soff = (row * PADK + kc * 4) * 4;
            cp_async16(sa + soff, A + (size_t)(bm + row) * K + kbase + kc * 4);
            cp_async16(sb + soff, B + (size_t)(bn + row) * K + kbase + kc * 4);
        }
        asm volatile("cp.async.commit_group;" ::: "memory");
    }

    for (int kt = 0; kt < NT; ++kt) {
        asm volatile("cp.async.wait_group %0;" :: "n"(GSTAGES - 2) : "memory");
        __syncthreads();

        // issue load of tile kt+GSTAGES-1 into slot (kt+GSTAGES-1)%GSTAGES
        {
            int tl = kt + GSTAGES - 1;
            if (tl < NT) {
                int s = tl % GSTAGES;
                uint32_t sa = smb + (s * STAGE_F) * 4;
                uint32_t sb = sa + ATILE_F * 4;
                int kbase = tl * BKK;
                #pragma unroll
                for (int j = 0; j < 4; ++j) {
                    int c = c0 + j * 256;
                    int row = c >> 3, kc = c & 7;
                    uint32_t soff = (row * PADK + kc * 4) * 4;
                    cp_async16(sa + soff, A + (size_t)(bm + row) * K + kbase + kc * 4);
                    cp_async16(sb + soff, B + (size_t)(bn + row) * K + kbase + kc * 4);
                }
            }
            asm volatile("cp.async.commit_group;" ::: "memory");
        }

        // compute slot kt%GSTAGES
        const float* sa = sm + (kt % GSTAGES) * STAGE_F;
        const float* sb = sa + ATILE_F;
        #pragma unroll
        for (int k8 = 0; k8 < 4; ++k8) {
            int k0 = k8 * 8;
            uint32_t af[4][4];
            #pragma unroll
            for (int mt = 0; mt < 4; mt++) {
                const float* p = sa + (wm * 64 + mt * 16 + tr) * PADK + k0 + tc;
                af[mt][0] = __float_as_uint(p[0]);
                af[mt][1] = __float_as_uint(p[8 * PADK]);
                af[mt][2] = __float_as_uint(p[4]);
                af[mt][3] = __float_as_uint(p[8 * PADK + 4]);
            }
            uint32_t bf[4][2];
            #pragma unroll
            for (int nt = 0; nt < 4; nt++) {
                const float* p = sb + (wn * 32 + nt * 8 + tr) * PADK + k0 + tc;
                bf[nt][0] = __float_as_uint(p[0]);
                bf[nt][1] = __float_as_uint(p[4]);
            }
            #pragma unroll
            for (int mt = 0; mt < 4; mt++)
                #pragma unroll
                for (int nt = 0; nt < 4; nt++)
                    mma_tf32(acc[mt][nt], af[mt][0], af[mt][1], af[mt][2], af[mt][3],
                             bf[nt][0], bf[nt][1]);
        }
        __syncthreads();
    }

    // epilogue: bias + tanh, float2 stores
    #pragma unroll
    for (int mt = 0; mt < 4; mt++) {
        int r0 = bm + wm * 64 + mt * 16 + tr;
        #pragma unroll
        for (int nt = 0; nt < 4; nt++) {
            int cc = bn + wn * 32 + nt * 8 + tc * 2;
            float b0 = bias ? __ldg(bias + cc) : 0.0f;
            float b1 = bias ? __ldg(bias + cc + 1) : 0.0f;
            float2 v0, v1;
            v0.x = tanhf(acc[mt][nt][0] + b0);
            v0.y = tanhf(acc[mt][nt][1] + b1);
            v1.x = tanhf(acc[mt][nt][2] + b0);
            v1.y = tanhf(acc[mt][nt][3] + b1);
            *(float2*)(C + (size_t)r0 * N + cc) = v0;
            *(float2*)(C + (size_t)(r0 + 8) * N + cc) = v1;
        }
    }
}

// ---------------- kernel 0: conv-weight prefix sums ----------------
__global__ void prefix_kernel(const float* __restrict__ w,
                              float* __restrict__ P) {
    int k = threadIdx.x;
    if (k >= KN) return;
    float s = 0.0f;
    P[k * 202 + 0] = 0.0f;
    for (int t = 0; t < 2*KS+1; t++) {
        float ws = 0.0f;
        #pragma unroll
        for (int h = 0; h < NH; h++) ws += w[(k*NH + h)*(2*KS+1) + t];
        s += ws;
        P[k * 202 + t + 1] = s;
    }
}

// ---------------- kernel 1: query projection (warp per output) ----------------
__global__ void query_kernel(const float* __restrict__ dec, const float* __restrict__ Wq,
                             const float* __restrict__ bq, float* __restrict__ q) {
    int gw = (blockIdx.x * blockDim.x + threadIdx.x) >> 5;
    int lane = threadIdx.x & 31;
    if (gw >= BS * NKV) return;
    int b = gw >> 11, n = gw & (NKV - 1);
    const float* x = dec + b * QDIM;
    const float* w = Wq + (size_t)n * QDIM;
    float acc = 0.0f;
    for (int k = lane; k < QDIM; k += 32) acc += x[k] * w[k];
    #pragma unroll
    for (int o = 16; o; o >>= 1) acc += __shfl_xor_sync(0xffffffffu, acc, o);
    if (!lane) q[gw] = tanhf(acc + bq[n]);
}

// ---------------- kernel 2: location conv via prefix diff ----------------
__global__ void conv_kernel(const int* __restrict__ enc_len, float* __restrict__ conv) {
    int idx = blockIdx.x * blockDim.x + threadIdx.x;
    if (idx >= BS * TS * KN) return;
    int k = idx % KN;
    int t = (idx / KN) % TS;
    int b = idx / (KN * TS);
    int len = enc_len[b];
    int lo = max(0, KS - t);
    int hi = min(2*KS + 1, KS - t + len);
    float v = 0.0f;
    if (hi > lo) v = (g_P[k*202 + hi] - g_P[k*202 + lo]) / (float)len;
    conv[idx] = v;
}

// ---------------- fp32 tiled SGEMM (for loc projection, K=100) ----------------
__global__ __launch_bounds__(256)
void gemm_tanh(const float* __restrict__ A, const float* __restrict__ B,
               const float* __restrict__ bias, float* __restrict__ C,
               int M, int N, int K) {
    const int BK = 16;
    __shared__ float As[BK][128];
    __shared__ float Bs[BK][128];
    int bm = blockIdx.y * 128;
    int bn = blockIdx.x * 128;
    int tid = threadIdx.x;
    int trow = (tid >> 4) * 8;
    int tcol = (tid & 15) * 8;
    float acc[8][8];
    #pragma unroll
    for (int i = 0; i < 8; i++)
        #pragma unroll
        for (int j = 0; j < 8; j++) acc[i][j] = 0.0f;

    for (int k0 = 0; k0 < K; k0 += BK) {
        #pragma unroll
        for (int s = tid; s < 512; s += 256) {
            int row = s >> 2;
            int kq  = (s & 3) * 4;
            int gk  = k0 + kq;
            const float* ap = A + (size_t)(bm + row) * K + gk;
            const float* bp = B + (size_t)(bn + row) * K + gk;
            float4 va, vb;
            if (gk + 3 < K) {
                va = *(const float4*)ap;
                vb = *(const float4*)bp;
            } else {
                float ta[4], tb[4];
                #pragma unroll
                for (int i = 0; i < 4; i++) {
                    ta[i] = (gk + i < K) ? ap[i] : 0.0f;
                    tb[i] = (gk + i < K) ? bp[i] : 0.0f;
                }
                va = make_float4(ta[0], ta[1], ta[2], ta[3]);
                vb = make_float4(tb[0], tb[1], tb[2], tb[3]);
            }
            As[kq+0][row] = va.x; As[kq+1][row] = va.y;
            As[kq+2][row] = va.z; As[kq+3][row] = va.w;
            Bs[kq+0][row] = vb.x; Bs[kq+1][row] = vb.y;
            Bs[kq+2][row] = vb.z; Bs[kq+3][row] = vb.w;
        }
        __syncthreads();
        #pragma unroll
        for (int kk = 0; kk < BK; kk++) {
            float ra[8], rb[8];
            #pragma unroll
            for (int i = 0; i < 8; i++) ra[i] = As[kk][trow + i];
            #pragma unroll
            for (int j = 0; j < 8; j++) rb[j] = Bs[kk][tcol + j];
            #pragma unroll
            for (int i = 0; i < 8; i++)
                #pragma unroll
                for (int j = 0; j < 8; j++) acc[i][j] += ra[i] * rb[j];
        }
        __syncthreads();
    }

    float bj[8];
    #pragma unroll
    for (int j = 0; j < 8; j++) bj[j] = bias ? bias[bn + tcol + j] : 0.0f;
    #pragma unroll
    for (int i = 0; i < 8; i++) {
        size_t off = (size_t)(bm + trow + i) * N + bn + tcol;
        #pragma unroll
        for (int j = 0; j < 8; j++)
            C[off + j] = tanhf(acc[i][j] + bj[j]);
    }
}

// ---------------- kernel 4: additive energy (warp per (b,h,t)) ----------------
__global__ void energy_kernel(const float* __restrict__ gen_w, const float* __restrict__ gen_b) {
    int gw = (blockIdx.x * blockDim.x + threadIdx.x) >> 5;
    int lane = threadIdx.x & 31;
    if (gw >= BS * NH * TS) return;
    int t = gw & (TS - 1);
    int h = (gw >> 11) & (NH - 1);
    int b = gw >> 13;
    const float* krow = g_key + (size_t)(b * TS + t) * NKV + h * DIM;
    const float* qrow = g_q + b * NKV + h * DIM;
    const float* lrow = g_loc + (size_t)(b * TS + t) * DIM;
    float acc = 0.0f;
    for (int d = lane; d < DIM; d += 32)
        acc += gen_w[d] * tanhf(krow[d] + qrow[d] + lrow[d]);
    #pragma unroll
    for (int o = 16; o; o >>= 1) acc += __shfl_xor_sync(0xffffffffu, acc, o);
    if (!lane) g_energy[gw] = (acc + gen_b[0]) * (1.0f / TEMP);
}

// ---------------- kernel 5: masked softmax -> attn ----------------
__global__ void softmax_kernel(const int* __restrict__ enc_len, float* __restrict__ attn) {
    __shared__ float red[8];
    __shared__ float bcast;
    int bh = blockIdx.x;
    int b = bh >> 2;
    int len = enc_len[b];
    const float* e = g_energy + bh * TS;
    float* a = attn + bh * TS;
    int tid = threadIdx.x, lane = tid & 31, w = tid >> 5;

    float m = -INFINITY;
    for (int t = tid; t < len; t += 256) m = fmaxf(m, e[t]);
    #pragma unroll
    for (int o = 16; o; o >>= 1) m = fmaxf(m, __shfl_xor_sync(0xffffffffu, m, o));
    if (!lane) red[w] = m;
    __syncthreads();
    if (tid < 8) {
        float x = red[tid];
        #pragma unroll
        for (int o = 4; o; o >>= 1) x = fmaxf(x, __shfl_xor_sync(0xffu, x, o));
        if (!tid) bcast = x;
    }
    __syncthreads();
    m = bcast;
    __syncthreads();

    float s = 0.0f;
    for (int t = tid; t < len; t += 256) s += expf(e[t] - m);
    #pragma unroll
    for (int o = 16; o; o >>= 1) s += __shfl_xor_sync(0xffffffffu, s, o);
    if (!lane) red[w] = s;
    __syncthreads();
    if (tid < 8) {
        float x = red[tid];
        #pragma unroll
        for (int o = 4; o; o >>= 1) x += __shfl_xor_sync(0xffu, x, o);
        if (!tid) bcast = x;
    }
    __syncthreads();
    float inv = 1.0f / bcast;
    for (int t = tid; t < TS; t += 256)
        a[t] = (t < len) ? expf(e[t] - m) * inv : 0.0f;
}

// ---------------- kernel 6: context weighted sum ----------------
__global__ void ctx_zero_kernel() {
    int i = blockIdx.x * blockDim.x + threadIdx.x;
    if (i < BS * NH * VDIM) g_ctx[i] = 0.0f;
}

__global__ void ctx_kernel(const float* __restrict__ attn, const int* __restrict__ enc_len) {
    int chunk = blockIdx.x & 7;
    int h = (blockIdx.x >> 3) & (NH - 1);
    int b = blockIdx.x >> 5;
    int v = threadIdx.x;
    int len = enc_len[b];
    int t0 = chunk * (TS / 8);
    int t1 = min(t0 + TS / 8, len);
    if (t0 >= t1) return;
    const float* arow = attn + (b * NH + h) * TS;
    const float* vbase = g_value + (size_t)(b * TS) * NKV + h * VDIM + v;
    float acc = 0.0f;
    for (int t = t0; t < t1; t++)
        acc += arow[t] * vbase[(size_t)t * NKV];
    atomicAdd(&g_ctx[(b * NH + h) * VDIM + v], acc);
}

// ---------------- kernel 7: merge projection ----------------
__global__ void merge_kernel(const float* __restrict__ Wm, const float* __restrict__ bm,
                             float* __restrict__ out) {
    int gw = (blockIdx.x * blockDim.x + threadIdx.x) >> 5;
    int lane = threadIdx.x & 31;
    if (gw >= BS * VDIM) return;
    int b = gw >> 9, j = gw & (VDIM - 1);
    const float* x = g_ctx + b * (NH * VDIM);
    const float* w = Wm + (size_t)j * (NH * VDIM);
    float acc = 0.0f;
    for (int k = lane; k < NH * VDIM; k += 32) acc += x[k] * w[k];
    #pragma unroll
    for (int o = 16; o; o >>= 1) acc += __shfl_xor_sync(0xffffffffu, acc, o);
    if (!lane) out[gw] = acc + bm[j];
}

// ---------------- launch ----------------
extern "C" void kernel_launch(void* const* d_in, const int* in_sizes, int n_in,
                              void* d_out, int out_size) {
    const float* dec_state  = (const float*)d_in[0];
    const float* enc_feat   = (const float*)d_in[1];
    const int*   enc_len    = (const int*)  d_in[2];
    const float* Wq         = (const float*)d_in[3];
    const float* bq         = (const float*)d_in[4];
    const float* Wk         = (const float*)d_in[5];
    const float* bk         = (const float*)d_in[6];
    const float* Wv         = (const float*)d_in[7];
    const float* bv         = (const float*)d_in[8];
    const float* loc_conv_w = (const float*)d_in[9];
    const float* loc_proj_w = (const float*)d_in[10];
    const float* gen_w      = (const float*)d_in[11];
    const float* gen_b      = (const float*)d_in[12];
    const float* merge_w    = (const float*)d_in[13];
    const float* merge_b    = (const float*)d_in[14];

    float* out = (float*)d_out;
    float* out_attn = out;                       // [8,4,2048]
    float* out_ctx  = out + BS * NH * TS;        // [8,512]

    static float *pP = nullptr, *pQ = nullptr, *pConv = nullptr, *pKey = nullptr,
                 *pVal = nullptr, *pLoc = nullptr, *pAtf = nullptr, *pBk = nullptr,
                 *pBv = nullptr;
    if (!pP) {
        cudaGetSymbolAddress((void**)&pP,    g_P);
        cudaGetSymbolAddress((void**)&pQ,    g_q);
        cudaGetSymbolAddress((void**)&pConv, g_conv);
        cudaGetSymbolAddress((void**)&pKey,  g_key);
        cudaGetSymbolAddress((void**)&pVal,  g_value);
        cudaGetSymbolAddress((void**)&pLoc,  g_loc);
        cudaGetSymbolAddress((void**)&pAtf,  g_Atf);
        cudaGetSymbolAddress((void**)&pBk,   g_Bk);
        cudaGetSymbolAddress((void**)&pBv,   g_Bv);
        cudaFuncSetAttribute(gemm_mma_tf32_tanh, cudaFuncAttributeMaxDynamicSharedMemorySize, GSMEM_BYTES);
    }

    // 0) prefix sums of conv weights
    prefix_kernel<<<1, 128>>>(loc_conv_w, pP);

    // tf32 rounding of GEMM inputs
    {
        int nA4 = MDIM * VDIM / 4;
        tf32_round_kernel<<<(nA4 + 255) / 256, 256>>>((const float4*)enc_feat, (float4*)pAtf, nA4);
        int nB4 = NKV * VDIM / 4;
        tf32_round_kernel<<<(nB4 + 255) / 256, 256>>>((const float4*)Wk, (float4*)pBk, nB4);
        tf32_round_kernel<<<(nB4 + 255) / 256, 256>>>((const float4*)Wv, (float4*)pBv, nB4);
    }

    // 1) query projection
    query_kernel<<<(BS * NKV * 32 + 255) / 256, 256>>>(dec_state, Wq, bq, pQ);

    // 2) conv via prefix diff
    conv_kernel<<<(BS * TS * KN + 255) / 256, 256>>>(enc_len, pConv);

    // 3) GEMMs: key, value via tf32 mma.sync; loc via fp32
    {
        dim3 gk(NKV / 128, MDIM / 128);
        gemm_mma_tf32_tanh<<<gk, 256, GSMEM_BYTES>>>(pAtf, pBk, bk, pKey, MDIM, NKV, VDIM);
        gemm_mma_tf32_tanh<<<gk, 256, GSMEM_BYTES>>>(pAtf, pBv, bv, pVal, MDIM, NKV, VDIM);
        dim3 gl(DIM / 128, MDIM / 128);
        gemm_tanh<<<gl, 256>>>(pConv, loc_proj_w, nullptr, pLoc, MDIM, DIM, KN);
    }

    // 4) energy
    energy_kernel<<<(BS * NH * TS * 32 + 127) / 128, 128>>>(gen_w, gen_b);

    // 5) softmax -> attn (d_out)
    softmax_kernel<<<BS * NH, 256>>>(enc_len, out_attn);

    // 6) context
    ctx_zero_kernel<<<(BS * NH * VDIM + 255) / 256, 256>>>();
    ctx_kernel<<<BS * NH * 8, VDIM>>>(out_attn, enc_len);

    // 7) merge
    merge_kernel<<<(BS * VDIM * 32 + 255) / 256, 256>>>(merge_w, merge_b, out_ctx);
}

// round 4
// speedup vs baseline: 4.1480x; 1.4124x over previous
#include <cuda_runtime.h>
#include <cuda_fp16.h>
#include <math.h>
#include <cstdint>

// Problem constants
#define BS   8
#define TS   2048
#define NH   4
#define DIM  512
#define VDIM 512
#define QDIM 1024
#define KS   100
#define KN   100
#define TEMP 0.5f

#define MDIM (BS*TS)         // 16384 rows for K/V GEMMs
#define NKV  (NH*DIM)        // 2048

// ---------------- scratch (static device allocations) ----------------
__device__ float g_P[KN * (2*KS+2)];            // prefix sums [100][202]
__device__ float g_q[BS * NKV];                 // tanh(query) [8][2048]
__device__ float g_conv[BS * TS * KN];          // [16384][100]
__device__ float g_key[(size_t)MDIM * NKV];     // tanh(key)
__device__ float g_value[(size_t)MDIM * NKV];   // tanh(value)
__device__ float g_loc[(size_t)MDIM * DIM];     // tanh(loc)
__device__ float g_energy[BS * NH * TS];
__device__ float g_ctx[BS * NH * VDIM];
__device__ __half g_Ah[(size_t)MDIM * VDIM];    // fp16 enc_feat
__device__ __half g_Bkh[NKV * VDIM];            // fp16 Wk
__device__ __half g_Bvh[NKV * VDIM];            // fp16 Wv

// ---------------- kernel: fp32 -> fp16 conversion ----------------
__global__ void f16_conv_kernel(const float4* __restrict__ in, __half2* __restrict__ outp, int n4) {
    int i = blockIdx.x * blockDim.x + threadIdx.x;
    if (i >= n4) return;
    float4 v = in[i];
    outp[2*i]   = __floats2half2_rn(v.x, v.y);
    outp[2*i+1] = __floats2half2_rn(v.z, v.w);
}

// ================= fp16 mma.sync GEMM + bias + tanh =================
// C[m][n] = tanh( sum_k A[m][k]*B[n][k] + bias[n] ), fp32 accumulate.
// CTA tile 128x128, BK=32, 3-stage cp.async pipeline, warp tile 64x32.
#define GSTAGES 3
#define BKK     32
#define PADH    40                        // halfs per smem row (80 B pitch, conflict-free)
#define ATILE_H (128 * PADH)              // 5120 halfs
#define STAGE_H (2 * ATILE_H)
#define GSMEM_BYTES (GSTAGES * STAGE_H * 2)   // 61440 B

__device__ __forceinline__ void mma_f16(float* d,
                                        uint32_t a0, uint32_t a1, uint32_t a2, uint32_t a3,
                                        uint32_t b0, uint32_t b1) {
    asm volatile(
        "mma.sync.aligned.m16n8k16.row.col.f32.f16.f16.f32 "
        "{%0,%1,%2,%3}, {%4,%5,%6,%7}, {%8,%9}, {%0,%1,%2,%3};"
        : "+f"(d[0]), "+f"(d[1]), "+f"(d[2]), "+f"(d[3])
        : "r"(a0), "r"(a1), "r"(a2), "r"(a3), "r"(b0), "r"(b1));
}

__device__ __forceinline__ void cp_async16(uint32_t saddr, const void* gaddr) {
    asm volatile("cp.async.cg.shared.global [%0], [%1], 16;" :: "r"(saddr), "l"(gaddr) : "memory");
}
__device__ __forceinline__ uint32_t smem_u32(const void* p) {
    uint32_t a;
    asm("{ .reg .u64 t; cvta.to.shared.u64 t, %1; cvt.u32.u64 %0, t; }" : "=r"(a) : "l"(p));
    return a;
}

__global__ __launch_bounds__(256, 2)
void gemm_mma_f16_tanh(const __half* __restrict__ A, const __half* __restrict__ B,
                       const float* __restrict__ bias, float* __restrict__ C,
                       int M, int N, int K) {
    extern __shared__ __half smh[];
    const int tid = threadIdx.x;
    const int wid = tid >> 5, lane = tid & 31;
    const int wm = wid & 1, wn = wid >> 1;       // warp grid 2 x 4 -> 64x32 warp tiles
    const int tr = lane >> 2, tc = lane & 3;
    const int bm = blockIdx.y * 128, bn = blockIdx.x * 128;
    const int NT = K / BKK;                       // 16 for K=512

    const uint32_t smb = smem_u32(smh);

    float acc[4][4][4];
    #pragma unroll
    for (int mt = 0; mt < 4; mt++)
        #pragma unroll
        for (int nt = 0; nt < 4; nt++)
            #pragma unroll
            for (int r = 0; r < 4; r++) acc[mt][nt][r] = 0.0f;

    // cp.async: per tile 512 chunks of 16B per matrix; chunk c: row=c>>2, kc=c&3
    // prologue: stages 0..GSTAGES-2
    #pragma unroll
    for (int s = 0; s < GSTAGES - 1; ++s) {
        uint32_t sa = smb + (s * STAGE_H) * 2;
        uint32_t sb = sa + ATILE_H * 2;
        int kbase = s * BKK;
        #pragma unroll
        for (int j = 0; j < 2; ++j) {
            int c = tid + j * 256;
            int row = c >> 2, kc = c & 3;
            uint32_t soff = row * (PADH * 2) + kc * 16;
            cp_async16(sa + soff, A + (size_t)(bm + row) * K + kbase + kc * 8);
            cp_async16(sb + soff, B + (size_t)(bn + row) * K + kbase + kc * 8);
        }
        asm volatile("cp.async.commit_group;" ::: "memory");
    }

    for (int kt = 0; kt < NT; ++kt) {
        asm volatile("cp.async.wait_group %0;" :: "n"(GSTAGES - 2) : "memory");
        __syncthreads();

        // issue load of tile kt+GSTAGES-1
        {
            int tl = kt + GSTAGES - 1;
            if (tl < NT) {
                int s = tl % GSTAGES;
                uint32_t sa = smb + (s * STAGE_H) * 2;
                uint32_t sb = sa + ATILE_H * 2;
                int kbase = tl * BKK;
                #pragma unroll
                for (int j = 0; j < 2; ++j) {
                    int c = tid + j * 256;
                    int row = c >> 2, kc = c & 3;
                    uint32_t soff = row * (PADH * 2) + kc * 16;
                    cp_async16(sa + soff, A + (size_t)(bm + row) * K + kbase + kc * 8);
                    cp_async16(sb + soff, B + (size_t)(bn + row) * K + kbase + kc * 8);
                }
            }
            asm volatile("cp.async.commit_group;" ::: "memory");
        }

        // compute slot kt%GSTAGES : two k16 steps
        const __half* sa = smh + (kt % GSTAGES) * STAGE_H;
        const __half* sb = sa + ATILE_H;
        #pragma unroll
        for (int ks = 0; ks < 2; ++ks) {
            int k0 = ks * 16;
            uint32_t af[4][4];
            #pragma unroll
            for (int mt = 0; mt < 4; mt++) {
                const __half* p = sa + (wm * 64 + mt * 16 + tr) * PADH + k0 + 2 * tc;
                af[mt][0] = *(const uint32_t*)(p);
                af[mt][1] = *(const uint32_t*)(p + 8 * PADH);
                af[mt][2] = *(const uint32_t*)(p + 8);
                af[mt][3] = *(const uint32_t*)(p + 8 * PADH + 8);
            }
            uint32_t bf[4][2];
            #pragma unroll
            for (int nt = 0; nt < 4; nt++) {
                const __half* p = sb + (wn * 32 + nt * 8 + tr) * PADH + k0 + 2 * tc;
                bf[nt][0] = *(const uint32_t*)(p);
                bf[nt][1] = *(const uint32_t*)(p + 8);
            }
            #pragma unroll
            for (int mt = 0; mt < 4; mt++)
                #pragma unroll
                for (int nt = 0; nt < 4; nt++)
                    mma_f16(acc[mt][nt], af[mt][0], af[mt][1], af[mt][2], af[mt][3],
                            bf[nt][0], bf[nt][1]);
        }
        __syncthreads();
    }

    // epilogue: bias + tanh, float2 stores
    #pragma unroll
    for (int mt = 0; mt < 4; mt++) {
        int r0 = bm + wm * 64 + mt * 16 + tr;
        #pragma unroll
        for (int nt = 0; nt < 4; nt++) {
            int cc = bn + wn * 32 + nt * 8 + tc * 2;
            float b0 = bias ? __ldg(bias + cc) : 0.0f;
            float b1 = bias ? __ldg(bias + cc + 1) : 0.0f;
            float2 v0, v1;
            v0.x = tanhf(acc[mt][nt][0] + b0);
            v0.y = tanhf(acc[mt][nt][1] + b1);
            v1.x = tanhf(acc[mt][nt][2] + b0);
            v1.y = tanhf(acc[mt][nt][3] + b1);
            *(float2*)(C + (size_t)r0 * N + cc) = v0;
            *(float2*)(C + (size_t)(r0 + 8) * N + cc) = v1;
        }
    }
}

// ---------------- kernel 0: conv-weight prefix sums ----------------
__global__ void prefix_kernel(const float* __restrict__ w,
                              float* __restrict__ P) {
    int k = threadIdx.x;
    if (k >= KN) return;
    float s = 0.0f;
    P[k * 202 + 0] = 0.0f;
    for (int t = 0; t < 2*KS+1; t++) {
        float ws = 0.0f;
        #pragma unroll
        for (int h = 0; h < NH; h++) ws += w[(k*NH + h)*(2*KS+1) + t];
        s += ws;
        P[k * 202 + t + 1] = s;
    }
}

// ---------------- kernel 1: query projection (warp per output) ----------------
__global__ void query_kernel(const float* __restrict__ dec, const float* __restrict__ Wq,
                             const float* __restrict__ bq, float* __restrict__ q) {
    int gw = (blockIdx.x * blockDim.x + threadIdx.x) >> 5;
    int lane = threadIdx.x & 31;
    if (gw >= BS * NKV) return;
    int b = gw >> 11, n = gw & (NKV - 1);
    const float* x = dec + b * QDIM;
    const float* w = Wq + (size_t)n * QDIM;
    float acc = 0.0f;
    for (int k = lane; k < QDIM; k += 32) acc += x[k] * w[k];
    #pragma unroll
    for (int o = 16; o; o >>= 1) acc += __shfl_xor_sync(0xffffffffu, acc, o);
    if (!lane) q[gw] = tanhf(acc + bq[n]);
}

// ---------------- kernel 2: location conv via prefix diff ----------------
__global__ void conv_kernel(const int* __restrict__ enc_len, float* __restrict__ conv) {
    int idx = blockIdx.x * blockDim.x + threadIdx.x;
    if (idx >= BS * TS * KN) return;
    int k = idx % KN;
    int t = (idx / KN) % TS;
    int b = idx / (KN * TS);
    int len = enc_len[b];
    int lo = max(0, KS - t);
    int hi = min(2*KS + 1, KS - t + len);
    float v = 0.0f;
    if (hi > lo) v = (g_P[k*202 + hi] - g_P[k*202 + lo]) / (float)len;
    conv[idx] = v;
}

// ---------------- fp32 tiled SGEMM (for loc projection, K=100) ----------------
__global__ __launch_bounds__(256)
void gemm_tanh(const float* __restrict__ A, const float* __restrict__ B,
               const float* __restrict__ bias, float* __restrict__ C,
               int M, int N, int K) {
    const int BK = 16;
    __shared__ float As[BK][128];
    __shared__ float Bs[BK][128];
    int bm = blockIdx.y * 128;
    int bn = blockIdx.x * 128;
    int tid = threadIdx.x;
    int trow = (tid >> 4) * 8;
    int tcol = (tid & 15) * 8;
    float acc[8][8];
    #pragma unroll
    for (int i = 0; i < 8; i++)
        #pragma unroll
        for (int j = 0; j < 8; j++) acc[i][j] = 0.0f;

    for (int k0 = 0; k0 < K; k0 += BK) {
        #pragma unroll
        for (int s = tid; s < 512; s += 256) {
            int row = s >> 2;
            int kq  = (s & 3) * 4;
            int gk  = k0 + kq;
            const float* ap = A + (size_t)(bm + row) * K + gk;
            const float* bp = B + (size_t)(bn + row) * K + gk;
            float4 va, vb;
            if (gk + 3 < K) {
                va = *(const float4*)ap;
                vb = *(const float4*)bp;
            } else {
                float ta[4], tb[4];
                #pragma unroll
                for (int i = 0; i < 4; i++) {
                    ta[i] = (gk + i < K) ? ap[i] : 0.0f;
                    tb[i] = (gk + i < K) ? bp[i] : 0.0f;
                }
                va = make_float4(ta[0], ta[1], ta[2], ta[3]);
                vb = make_float4(tb[0], tb[1], tb[2], tb[3]);
            }
            As[kq+0][row] = va.x; As[kq+1][row] = va.y;
            As[kq+2][row] = va.z; As[kq+3][row] = va.w;
            Bs[kq+0][row] = vb.x; Bs[kq+1][row] = vb.y;
            Bs[kq+2][row] = vb.z; Bs[kq+3][row] = vb.w;
        }
        __syncthreads();
        #pragma unroll
        for (int kk = 0; kk < BK; kk++) {
            float ra[8], rb[8];
            #pragma unroll
            for (int i = 0; i < 8; i++) ra[i] = As[kk][trow + i];
            #pragma unroll
            for (int j = 0; j < 8; j++) rb[j] = Bs[kk][tcol + j];
            #pragma unroll
            for (int i = 0; i < 8; i++)
                #pragma unroll
                for (int j = 0; j < 8; j++) acc[i][j] += ra[i] * rb[j];
        }
        __syncthreads();
    }

    float bj[8];
    #pragma unroll
    for (int j = 0; j < 8; j++) bj[j] = bias ? bias[bn + tcol + j] : 0.0f;
    #pragma unroll
    for (int i = 0; i < 8; i++) {
        size_t off = (size_t)(bm + trow + i) * N + bn + tcol;
        #pragma unroll
        for (int j = 0; j < 8; j++)
            C[off + j] = tanhf(acc[i][j] + bj[j]);
    }
}

// ---------------- kernel 4: additive energy (warp per (b,h,t)) ----------------
__global__ void energy_kernel(const float* __restrict__ gen_w, const float* __restrict__ gen_b) {
    int gw = (blockIdx.x * blockDim.x + threadIdx.x) >> 5;
    int lane = threadIdx.x & 31;
    if (gw >= BS * NH * TS) return;
    int t = gw & (TS - 1);
    int h = (gw >> 11) & (NH - 1);
    int b = gw >> 13;
    const float4* krow = (const float4*)(g_key + (size_t)(b * TS + t) * NKV + h * DIM);
    const float4* qrow = (const float4*)(g_q + b * NKV + h * DIM);
    const float4* lrow = (const float4*)(g_loc + (size_t)(b * TS + t) * DIM);
    const float4* gw4  = (const float4*)gen_w;
    float acc = 0.0f;
    #pragma unroll
    for (int it = 0; it < 4; it++) {
        int d4 = lane + it * 32;
        float4 kv = krow[d4];
        float4 qv = qrow[d4];
        float4 lv = lrow[d4];
        float4 wv = __ldg(gw4 + d4);
        acc += wv.x * tanhf(kv.x + qv.x + lv.x);
        acc += wv.y * tanhf(kv.y + qv.y + lv.y);
        acc += wv.z * tanhf(kv.z + qv.z + lv.z);
        acc += wv.w * tanhf(kv.w + qv.w + lv.w);
    }
    #pragma unroll
    for (int o = 16; o; o >>= 1) acc += __shfl_xor_sync(0xffffffffu, acc, o);
    if (!lane) g_energy[gw] = (acc + gen_b[0]) * (1.0f / TEMP);
}

// ---------------- kernel 5: masked softmax -> attn ----------------
__global__ void softmax_kernel(const int* __restrict__ enc_len, float* __restrict__ attn) {
    __shared__ float red[8];
    __shared__ float bcast;
    int bh = blockIdx.x;
    int b = bh >> 2;
    int len = enc_len[b];
    const float* e = g_energy + bh * TS;
    float* a = attn + bh * TS;
    int tid = threadIdx.x, lane = tid & 31, w = tid >> 5;

    float m = -INFINITY;
    for (int t = tid; t < len; t += 256) m = fmaxf(m, e[t]);
    #pragma unroll
    for (int o = 16; o; o >>= 1) m = fmaxf(m, __shfl_xor_sync(0xffffffffu, m, o));
    if (!lane) red[w] = m;
    __syncthreads();
    if (tid < 8) {
        float x = red[tid];
        #pragma unroll
        for (int o = 4; o; o >>= 1) x = fmaxf(x, __shfl_xor_sync(0xffu, x, o));
        if (!tid) bcast = x;
    }
    __syncthreads();
    m = bcast;
    __syncthreads();

    float s = 0.0f;
    for (int t = tid; t < len; t += 256) s += expf(e[t] - m);
    #pragma unroll
    for (int o = 16; o; o >>= 1) s += __shfl_xor_sync(0xffffffffu, s, o);
    if (!lane) red[w] = s;
    __syncthreads();
    if (tid < 8) {
        float x = red[tid];
        #pragma unroll
        for (int o = 4; o; o >>= 1) x += __shfl_xor_sync(0xffu, x, o);
        if (!tid) bcast = x;
    }
    __syncthreads();
    float inv = 1.0f / bcast;
    for (int t = tid; t < TS; t += 256)
        a[t] = (t < len) ? expf(e[t] - m) * inv : 0.0f;
}

// ---------------- kernel 6: context weighted sum ----------------
__global__ void ctx_zero_kernel() {
    int i = blockIdx.x * blockDim.x + threadIdx.x;
    if (i < BS * NH * VDIM) g_ctx[i] = 0.0f;
}

__global__ void ctx_kernel(const float* __restrict__ attn, const int* __restrict__ enc_len) {
    int chunk = blockIdx.x & 7;
    int h = (blockIdx.x >> 3) & (NH - 1);
    int b = blockIdx.x >> 5;
    int v = threadIdx.x;
    int len = enc_len[b];
    int t0 = chunk * (TS / 8);
    int t1 = min(t0 + TS / 8, len);
    if (t0 >= t1) return;
    const float* arow = attn + (b * NH + h) * TS;
    const float* vbase = g_value + (size_t)(b * TS) * NKV + h * VDIM + v;
    float acc = 0.0f;
    for (int t = t0; t < t1; t++)
        acc += arow[t] * vbase[(size_t)t * NKV];
    atomicAdd(&g_ctx[(b * NH + h) * VDIM + v], acc);
}

// ---------------- kernel 7: merge projection ----------------
__global__ void merge_kernel(const float* __restrict__ Wm, const float* __restrict__ bm,
                             float* __restrict__ out) {
    int gw = (blockIdx.x * blockDim.x + threadIdx.x) >> 5;
    int lane = threadIdx.x & 31;
    if (gw >= BS * VDIM) return;
    int b = gw >> 9, j = gw & (VDIM - 1);
    const float* x = g_ctx + b * (NH * VDIM);
    const float* w = Wm + (size_t)j * (NH * VDIM);
    float acc = 0.0f;
    for (int k = lane; k < NH * VDIM; k += 32) acc += x[k] * w[k];
    #pragma unroll
    for (int o = 16; o; o >>= 1) acc += __shfl_xor_sync(0xffffffffu, acc, o);
    if (!lane) out[gw] = acc + bm[j];
}

// ---------------- launch ----------------
extern "C" void kernel_launch(void* const* d_in, const int* in_sizes, int n_in,
                              void* d_out, int out_size) {
    const float* dec_state  = (const float*)d_in[0];
    const float* enc_feat   = (const float*)d_in[1];
    const int*   enc_len    = (const int*)  d_in[2];
    const float* Wq         = (const float*)d_in[3];
    const float* bq         = (const float*)d_in[4];
    const float* Wk         = (const float*)d_in[5];
    const float* bk         = (const float*)d_in[6];
    const float* Wv         = (const float*)d_in[7];
    const float* bv         = (const float*)d_in[8];
    const float* loc_conv_w = (const float*)d_in[9];
    const float* loc_proj_w = (const float*)d_in[10];
    const float* gen_w      = (const float*)d_in[11];
    const float* gen_b      = (const float*)d_in[12];
    const float* merge_w    = (const float*)d_in[13];
    const float* merge_b    = (const float*)d_in[14];

    float* out = (float*)d_out;
    float* out_attn = out;                       // [8,4,2048]
    float* out_ctx  = out + BS * NH * TS;        // [8,512]

    static float *pP = nullptr, *pQ = nullptr, *pConv = nullptr, *pKey = nullptr,
                 *pVal = nullptr, *pLoc = nullptr;
    static __half *pAh = nullptr, *pBkh = nullptr, *pBvh = nullptr;
    if (!pP) {
        cudaGetSymbolAddress((void**)&pP,    g_P);
        cudaGetSymbolAddress((void**)&pQ,    g_q);
        cudaGetSymbolAddress((void**)&pConv, g_conv);
        cudaGetSymbolAddress((void**)&pKey,  g_key);
        cudaGetSymbolAddress((void**)&pVal,  g_value);
        cudaGetSymbolAddress((void**)&pLoc,  g_loc);
        cudaGetSymbolAddress((void**)&pAh,   g_Ah);
        cudaGetSymbolAddress((void**)&pBkh,  g_Bkh);
        cudaGetSymbolAddress((void**)&pBvh,  g_Bvh);
        cudaFuncSetAttribute(gemm_mma_f16_tanh, cudaFuncAttributeMaxDynamicSharedMemorySize, GSMEM_BYTES);
    }

    // 0) prefix sums of conv weights
    prefix_kernel<<<1, 128>>>(loc_conv_w, pP);

    // fp16 conversion of GEMM inputs
    {
        int nA4 = MDIM * VDIM / 4;
        f16_conv_kernel<<<(nA4 + 255) / 256, 256>>>((const float4*)enc_feat, (__half2*)pAh, nA4);
        int nB4 = NKV * VDIM / 4;
        f16_conv_kernel<<<(nB4 + 255) / 256, 256>>>((const float4*)Wk, (__half2*)pBkh, nB4);
        f16_conv_kernel<<<(nB4 + 255) / 256, 256>>>((const float4*)Wv, (__half2*)pBvh, nB4);
    }

    // 1) query projection
    query_kernel<<<(BS * NKV * 32 + 255) / 256, 256>>>(dec_state, Wq, bq, pQ);

    // 2) conv via prefix diff
    conv_kernel<<<(BS * TS * KN + 255) / 256, 256>>>(enc_len, pConv);

    // 3) GEMMs: key, value via fp16 mma.sync; loc via fp32
    {
        dim3 gk(NKV / 128, MDIM / 128);
        gemm_mma_f16_tanh<<<gk, 256, GSMEM_BYTES>>>(pAh, pBkh, bk, pKey, MDIM, NKV, VDIM);
        gemm_mma_f16_tanh<<<gk, 256, GSMEM_BYTES>>>(pAh, pBvh, bv, pVal, MDIM, NKV, VDIM);
        dim3 gl(DIM / 128, MDIM / 128);
        gemm_tanh<<<gl, 256>>>(pConv, loc_proj_w, nullptr, pLoc, MDIM, DIM, KN);
    }

    // 4) energy
    energy_kernel<<<(BS * NH * TS * 32 + 127) / 128, 128>>>(gen_w, gen_b);

    // 5) softmax -> attn (d_out)
    softmax_kernel<<<BS * NH, 256>>>(enc_len, out_attn);

    // 6) context
    ctx_zero_kernel<<<(BS * NH * VDIM + 255) / 256, 256>>>();
    ctx_kernel<<<BS * NH * 8, VDIM>>>(out_attn, enc_len);

    // 7) merge
    merge_kernel<<<(BS * VDIM * 32 + 255) / 256, 256>>>(merge_w, merge_b, out_ctx);
}

// round 5
// speedup vs baseline: 5.3530x; 1.2905x over previous
#include <cuda_runtime.h>
#include <cuda_fp16.h>
#include <math.h>
#include <cstdint>

// Problem constants
#define BS   8
#define TS   2048
#define NH   4
#define DIM  512
#define VDIM 512
#define QDIM 1024
#define KS   100
#define KN   100
#define TEMP 0.5f

#define MDIM (BS*TS)         // 16384 rows for K/V GEMMs
#define NKV  (NH*DIM)        // 2048
#define LROWS 384            // padded compact loc rows per batch (302 used)
#define MLOC (BS*LROWS)      // 3072

// ---------------- scratch (static device allocations) ----------------
__device__ float g_P[KN * (2*KS+2)];             // prefix sums [100][202]
__device__ float g_q[BS * NKV];                  // tanh(query) [8][2048]
__device__ float g_convc[MLOC * KN];             // compact conv [3072][100]
__device__ float g_locc[(size_t)MLOC * DIM];     // compact loc  [3072][512]
__device__ float g_energy[BS * NH * TS];         // raw energy partial sums
__device__ float g_ctx[BS * NH * VDIM];
__device__ __half g_Ah[(size_t)MDIM * VDIM];     // fp16 enc_feat
__device__ __half g_Bkh[NKV * VDIM];             // fp16 Wk
__device__ __half g_Bvh[NKV * VDIM];             // fp16 Wv

// compact loc row index for timestep t given len
__device__ __forceinline__ int idx_t(int t, int len) {
    if (t < KS) return t;
    if (t <= len - KS - 1) return KS;
    int j = t - (len - KS);
    if (j < 2 * KS) return KS + 1 + j;   // 101..300
    return 301;                          // zero row
}

// ---------------- zero init (energy + ctx) ----------------
__global__ void zero_kernel() {
    int i = blockIdx.x * blockDim.x + threadIdx.x;
    if (i < BS * NH * TS) g_energy[i] = 0.0f;
    if (i < BS * NH * VDIM) g_ctx[i] = 0.0f;
}

// ---------------- kernel: fp32 -> fp16 conversion ----------------
__global__ void f16_conv_kernel(const float4* __restrict__ in, __half2* __restrict__ outp, int n4) {
    int i = blockIdx.x * blockDim.x + threadIdx.x;
    if (i >= n4) return;
    float4 v = in[i];
    outp[2*i]   = __floats2half2_rn(v.x, v.y);
    outp[2*i+1] = __floats2half2_rn(v.z, v.w);
}

// ---------------- kernel 0: conv-weight prefix sums ----------------
__global__ void prefix_kernel(const float* __restrict__ w, float* __restrict__ P) {
    int k = threadIdx.x;
    if (k >= KN) return;
    float s = 0.0f;
    P[k * 202 + 0] = 0.0f;
    for (int t = 0; t < 2*KS+1; t++) {
        float ws = 0.0f;
        #pragma unroll
        for (int h = 0; h < NH; h++) ws += w[(k*NH + h)*(2*KS+1) + t];
        s += ws;
        P[k * 202 + t + 1] = s;
    }
}

// ---------------- kernel 1: query projection ----------------
__global__ void query_kernel(const float* __restrict__ dec, const float* __restrict__ Wq,
                             const float* __restrict__ bq, float* __restrict__ q) {
    int gw = (blockIdx.x * blockDim.x + threadIdx.x) >> 5;
    int lane = threadIdx.x & 31;
    if (gw >= BS * NKV) return;
    int b = gw >> 11, n = gw & (NKV - 1);
    const float* x = dec + b * QDIM;
    const float* w = Wq + (size_t)n * QDIM;
    float acc = 0.0f;
    for (int k = lane; k < QDIM; k += 32) acc += x[k] * w[k];
    #pragma unroll
    for (int o = 16; o; o >>= 1) acc += __shfl_xor_sync(0xffffffffu, acc, o);
    if (!lane) q[gw] = tanhf(acc + bq[n]);
}

// ---------------- kernel 2: compact conv via prefix diff ----------------
__global__ void convc_kernel(const int* __restrict__ enc_len, float* __restrict__ conv) {
    int idx = blockIdx.x * blockDim.x + threadIdx.x;
    if (idx >= MLOC * KN) return;
    int k = idx % KN;
    int r = (idx / KN) % LROWS;
    int b = idx / (KN * LROWS);
    int len = enc_len[b];
    float v = 0.0f;
    int lo, hi;
    if (r < KS)        { lo = KS - r; hi = 2*KS + 1; }
    else if (r == KS)  { lo = 0;      hi = 2*KS + 1; }
    else if (r <= 3*KS){ lo = 0;      hi = 2*KS - (r - KS - 1); }
    else               { conv[idx] = 0.0f; return; }
    if (hi > lo) v = (g_P[k*202 + hi] - g_P[k*202 + lo]) / (float)len;
    conv[idx] = v;
}

// ---------------- fp32 tiled SGEMM + tanh (loc projection, K=100) ----------------
__global__ __launch_bounds__(256)
void gemm_tanh(const float* __restrict__ A, const float* __restrict__ B,
               const float* __restrict__ bias, float* __restrict__ C,
               int M, int N, int K) {
    const int BK = 16;
    __shared__ float As[BK][128];
    __shared__ float Bs[BK][128];
    int bm = blockIdx.y * 128;
    int bn = blockIdx.x * 128;
    int tid = threadIdx.x;
    int trow = (tid >> 4) * 8;
    int tcol = (tid & 15) * 8;
    float acc[8][8];
    #pragma unroll
    for (int i = 0; i < 8; i++)
        #pragma unroll
        for (int j = 0; j < 8; j++) acc[i][j] = 0.0f;

    for (int k0 = 0; k0 < K; k0 += BK) {
        #pragma unroll
        for (int s = tid; s < 512; s += 256) {
            int row = s >> 2;
            int kq  = (s & 3) * 4;
            int gk  = k0 + kq;
            const float* ap = A + (size_t)(bm + row) * K + gk;
            const float* bp = B + (size_t)(bn + row) * K + gk;
            float ta[4], tb[4];
            #pragma unroll
            for (int i = 0; i < 4; i++) {
                ta[i] = (gk + i < K) ? ap[i] : 0.0f;
                tb[i] = (gk + i < K) ? bp[i] : 0.0f;
            }
            As[kq+0][row] = ta[0]; As[kq+1][row] = ta[1];
            As[kq+2][row] = ta[2]; As[kq+3][row] = ta[3];
            Bs[kq+0][row] = tb[0]; Bs[kq+1][row] = tb[1];
            Bs[kq+2][row] = tb[2]; Bs[kq+3][row] = tb[3];
        }
        __syncthreads();
        #pragma unroll
        for (int kk = 0; kk < BK; kk++) {
            float ra[8], rb[8];
            #pragma unroll
            for (int i = 0; i < 8; i++) ra[i] = As[kk][trow + i];
            #pragma unroll
            for (int j = 0; j < 8; j++) rb[j] = Bs[kk][tcol + j];
            #pragma unroll
            for (int i = 0; i < 8; i++)
                #pragma unroll
                for (int j = 0; j < 8; j++) acc[i][j] += ra[i] * rb[j];
        }
        __syncthreads();
    }

    #pragma unroll
    for (int i = 0; i < 8; i++) {
        size_t off = (size_t)(bm + trow + i) * N + bn + tcol;
        #pragma unroll
        for (int j = 0; j < 8; j++)
            C[off + j] = tanhf(acc[i][j]);
    }
}

// ================= fp16 mma GEMM core macros =================
#define GSTAGES 3
#define BKK     32
#define PADH    40                        // halfs per smem row (80 B pitch)
#define ATILE_H (128 * PADH)
#define STAGE_H (2 * ATILE_H)
#define GSMEM_BYTES (GSTAGES * STAGE_H * 2)   // 61440 B

__device__ __forceinline__ void mma_f16(float* d,
                                        uint32_t a0, uint32_t a1, uint32_t a2, uint32_t a3,
                                        uint32_t b0, uint32_t b1) {
    asm volatile(
        "mma.sync.aligned.m16n8k16.row.col.f32.f16.f16.f32 "
        "{%0,%1,%2,%3}, {%4,%5,%6,%7}, {%8,%9}, {%0,%1,%2,%3};"
        : "+f"(d[0]), "+f"(d[1]), "+f"(d[2]), "+f"(d[3])
        : "r"(a0), "r"(a1), "r"(a2), "r"(a3), "r"(b0), "r"(b1));
}
__device__ __forceinline__ void cp_async16(uint32_t saddr, const void* gaddr) {
    asm volatile("cp.async.cg.shared.global [%0], [%1], 16;" :: "r"(saddr), "l"(gaddr) : "memory");
}
__device__ __forceinline__ uint32_t smem_u32(const void* p) {
    uint32_t a;
    asm("{ .reg .u64 t; cvta.to.shared.u64 t, %1; cvt.u32.u64 %0, t; }" : "=r"(a) : "l"(p));
    return a;
}

// mainloop shared by both fused GEMMs; leaves acc[4][4][4] filled.
// rows: bm + wm*64 + mt*16 + tr (+8), cols: bn + wn*32 + nt*8 + tc*2 (+1)
#define GEMM_MAINLOOP(A, B, K)                                                         \
    const int tid = threadIdx.x;                                                       \
    const int wid = tid >> 5, lane = tid & 31;                                         \
    const int wm = wid & 1, wn = wid >> 1;                                             \
    const int tr = lane >> 2, tc = lane & 3;                                           \
    const int bm = blockIdx.y * 128, bn = blockIdx.x * 128;                            \
    const int NT = (K) / BKK;                                                          \
    const uint32_t smb = smem_u32(smh);                                                \
    float acc[4][4][4];                                                                \
    _Pragma("unroll") for (int mt = 0; mt < 4; mt++)                                   \
        _Pragma("unroll") for (int nt = 0; nt < 4; nt++)                               \
            _Pragma("unroll") for (int r = 0; r < 4; r++) acc[mt][nt][r] = 0.0f;       \
    _Pragma("unroll") for (int s = 0; s < GSTAGES - 1; ++s) {                          \
        uint32_t sa = smb + (s * STAGE_H) * 2;                                         \
        uint32_t sb = sa + ATILE_H * 2;                                                \
        int kbase = s * BKK;                                                           \
        _Pragma("unroll") for (int j = 0; j < 2; ++j) {                                \
            int c = tid + j * 256;                                                     \
            int row = c >> 2, kc = c & 3;                                              \
            uint32_t soff = row * (PADH * 2) + kc * 16;                                \
            cp_async16(sa + soff, (A) + (size_t)(bm + row) * (K) + kbase + kc * 8);    \
            cp_async16(sb + soff, (B) + (size_t)(bn + row) * (K) + kbase + kc * 8);    \
        }                                                                              \
        asm volatile("cp.async.commit_group;" ::: "memory");                           \
    }                                                                                  \
    for (int kt = 0; kt < NT; ++kt) {                                                  \
        asm volatile("cp.async.wait_group %0;" :: "n"(GSTAGES - 2) : "memory");        \
        __syncthreads();                                                               \
        {                                                                              \
            int tl = kt + GSTAGES - 1;                                                 \
            if (tl < NT) {                                                             \
                int s = tl % GSTAGES;                                                  \
                uint32_t sa = smb + (s * STAGE_H) * 2;                                 \
                uint32_t sb = sa + ATILE_H * 2;                                        \
                int kbase = tl * BKK;                                                  \
                _Pragma("unroll") for (int j = 0; j < 2; ++j) {                        \
                    int c = tid + j * 256;                                             \
                    int row = c >> 2, kc = c & 3;                                      \
                    uint32_t soff = row * (PADH * 2) + kc * 16;                        \
                    cp_async16(sa + soff, (A) + (size_t)(bm + row) * (K) + kbase + kc * 8); \
                    cp_async16(sb + soff, (B) + (size_t)(bn + row) * (K) + kbase + kc * 8); \
                }                                                                      \
            }                                                                          \
            asm volatile("cp.async.commit_group;" ::: "memory");                       \
        }                                                                              \
        const __half* sa = smh + (kt % GSTAGES) * STAGE_H;                             \
        const __half* sb = sa + ATILE_H;                                               \
        _Pragma("unroll") for (int ks = 0; ks < 2; ++ks) {                             \
            int k0 = ks * 16;                                                          \
            uint32_t af[4][4];                                                         \
            _Pragma("unroll") for (int mt = 0; mt < 4; mt++) {                         \
                const __half* p = sa + (wm * 64 + mt * 16 + tr) * PADH + k0 + 2 * tc;  \
                af[mt][0] = *(const uint32_t*)(p);                                     \
                af[mt][1] = *(const uint32_t*)(p + 8 * PADH);                          \
                af[mt][2] = *(const uint32_t*)(p + 8);                                 \
                af[mt][3] = *(const uint32_t*)(p + 8 * PADH + 8);                      \
            }                                                                          \
            uint32_t bf[4][2];                                                         \
            _Pragma("unroll") for (int nt = 0; nt < 4; nt++) {                         \
                const __half* p = sb + (wn * 32 + nt * 8 + tr) * PADH + k0 + 2 * tc;   \
                bf[nt][0] = *(const uint32_t*)(p);                                     \
                bf[nt][1] = *(const uint32_t*)(p + 8);                                 \
            }                                                                          \
            _Pragma("unroll") for (int mt = 0; mt < 4; mt++)                           \
                _Pragma("unroll") for (int nt = 0; nt < 4; nt++)                       \
                    mma_f16(acc[mt][nt], af[mt][0], af[mt][1], af[mt][2], af[mt][3],   \
                            bf[nt][0], bf[nt][1]);                                     \
        }                                                                              \
        __syncthreads();                                                               \
    }

// ---------------- key GEMM + fused energy ----------------
// energy_raw[b,h,t] += sum_n gen_w[d]*tanh( tanh(acc+bk[n]) + q[b,n] + loc[b,idx(t),d] )
__global__ __launch_bounds__(256, 2)
void gemm_key_energy(const __half* __restrict__ A, const __half* __restrict__ B,
                     const float* __restrict__ bias, const float* __restrict__ q,
                     const float* __restrict__ gen_w, const int* __restrict__ enc_len) {
    extern __shared__ __half smh[];
    GEMM_MAINLOOP(A, B, VDIM)

    const int b = bm >> 11;
    const int len = enc_len[b];
    const int h = bn >> 9;
    const int dbase = (bn & 511) + wn * 32;

    float qv[8], wv[8], bv8[8];
    #pragma unroll
    for (int nt = 0; nt < 4; nt++)
        #pragma unroll
        for (int u = 0; u < 2; u++) {
            int d = dbase + nt * 8 + tc * 2 + u;
            int n = (h << 9) + d;
            qv[nt*2+u]  = __ldg(q + b * NKV + n);
            wv[nt*2+u]  = __ldg(gen_w + d);
            bv8[nt*2+u] = __ldg(bias + n);
        }

    float rowsum[8];
    #pragma unroll
    for (int i = 0; i < 8; i++) rowsum[i] = 0.0f;

    #pragma unroll
    for (int mt = 0; mt < 4; mt++) {
        #pragma unroll
        for (int half = 0; half < 2; half++) {
            int r = bm + wm * 64 + mt * 16 + tr + half * 8;
            int t = r & (TS - 1);
            const float* locp = g_locc + (size_t)(b * LROWS + idx_t(t, len)) * DIM + dbase;
            float s = 0.0f;
            #pragma unroll
            for (int nt = 0; nt < 4; nt++)
                #pragma unroll
                for (int u = 0; u < 2; u++) {
                    float kk = tanhf(acc[mt][nt][half*2+u] + bv8[nt*2+u]);
                    float lv = locp[nt * 8 + tc * 2 + u];
                    s += wv[nt*2+u] * tanhf(kk + qv[nt*2+u] + lv);
                }
            rowsum[mt*2+half] = s;
        }
    }
    // reduce over tc (lane bits 0,1)
    #pragma unroll
    for (int i = 0; i < 8; i++) {
        rowsum[i] += __shfl_xor_sync(0xffffffffu, rowsum[i], 1);
        rowsum[i] += __shfl_xor_sync(0xffffffffu, rowsum[i], 2);
    }
    if (tc == 0) {
        #pragma unroll
        for (int mt = 0; mt < 4; mt++)
            #pragma unroll
            for (int half = 0; half < 2; half++) {
                int r = bm + wm * 64 + mt * 16 + tr + half * 8;
                int t = r & (TS - 1);
                atomicAdd(&g_energy[(b * NH + h) * TS + t], rowsum[mt*2+half]);
            }
    }
}

// ---------------- value GEMM + fused context ----------------
// ctx[b,h,d] += sum_t attn[b,h,t]*tanh(acc+bv[n])
__global__ __launch_bounds__(256, 2)
void gemm_val_ctx(const __half* __restrict__ A, const __half* __restrict__ B,
                  const float* __restrict__ bias, const float* __restrict__ attn) {
    extern __shared__ __half smh[];
    GEMM_MAINLOOP(A, B, VDIM)

    const int b = bm >> 11;
    const int h = bn >> 9;
    const int dbase = (bn & 511) + wn * 32;

    float bv8[8];
    #pragma unroll
    for (int nt = 0; nt < 4; nt++)
        #pragma unroll
        for (int u = 0; u < 2; u++)
            bv8[nt*2+u] = __ldg(bias + (h << 9) + dbase + nt * 8 + tc * 2 + u);

    float colsum[8];
    #pragma unroll
    for (int i = 0; i < 8; i++) colsum[i] = 0.0f;

    #pragma unroll
    for (int mt = 0; mt < 4; mt++) {
        #pragma unroll
        for (int half = 0; half < 2; half++) {
            int r = bm + wm * 64 + mt * 16 + tr + half * 8;
            int t = r & (TS - 1);
            float a_t = __ldg(attn + (b * NH + h) * TS + t);
            #pragma unroll
            for (int nt = 0; nt < 4; nt++)
                #pragma unroll
                for (int u = 0; u < 2; u++)
                    colsum[nt*2+u] += a_t * tanhf(acc[mt][nt][half*2+u] + bv8[nt*2+u]);
        }
    }
    // reduce over tr (lane bits 2,3,4)
    #pragma unroll
    for (int i = 0; i < 8; i++) {
        colsum[i] += __shfl_xor_sync(0xffffffffu, colsum[i], 4);
        colsum[i] += __shfl_xor_sync(0xffffffffu, colsum[i], 8);
        colsum[i] += __shfl_xor_sync(0xffffffffu, colsum[i], 16);
    }
    if (tr == 0) {
        #pragma unroll
        for (int nt = 0; nt < 4; nt++)
            #pragma unroll
            for (int u = 0; u < 2; u++)
                atomicAdd(&g_ctx[(b * NH + h) * VDIM + dbase + nt * 8 + tc * 2 + u],
                          colsum[nt*2+u]);
    }
}

// ---------------- masked softmax (applies (x+gb)/TEMP) ----------------
__global__ void softmax_kernel(const int* __restrict__ enc_len, float* __restrict__ attn,
                               const float* __restrict__ gen_b) {
    __shared__ float red[8];
    __shared__ float bcast;
    int bh = blockIdx.x;
    int b = bh >> 2;
    int len = enc_len[b];
    float gb = gen_b[0];
    const float* e = g_energy + bh * TS;
    float* a = attn + bh * TS;
    int tid = threadIdx.x, lane = tid & 31, w = tid >> 5;

    float m = -INFINITY;
    for (int t = tid; t < len; t += 256) m = fmaxf(m, (e[t] + gb) * (1.0f / TEMP));
    #pragma unroll
    for (int o = 16; o; o >>= 1) m = fmaxf(m, __shfl_xor_sync(0xffffffffu, m, o));
    if (!lane) red[w] = m;
    __syncthreads();
    if (tid < 8) {
        float x = red[tid];
        #pragma unroll
        for (int o = 4; o; o >>= 1) x = fmaxf(x, __shfl_xor_sync(0xffu, x, o));
        if (!tid) bcast = x;
    }
    __syncthreads();
    m = bcast;
    __syncthreads();

    float s = 0.0f;
    for (int t = tid; t < len; t += 256) s += expf((e[t] + gb) * (1.0f / TEMP) - m);
    #pragma unroll
    for (int o = 16; o; o >>= 1) s += __shfl_xor_sync(0xffffffffu, s, o);
    if (!lane) red[w] = s;
    __syncthreads();
    if (tid < 8) {
        float x = red[tid];
        #pragma unroll
        for (int o = 4; o; o >>= 1) x += __shfl_xor_sync(0xffu, x, o);
        if (!tid) bcast = x;
    }
    __syncthreads();
    float inv = 1.0f / bcast;
    for (int t = tid; t < TS; t += 256)
        a[t] = (t < len) ? expf((e[t] + gb) * (1.0f / TEMP) - m) * inv : 0.0f;
}

// ---------------- merge projection ----------------
__global__ void merge_kernel(const float* __restrict__ Wm, const float* __restrict__ bm,
                             float* __restrict__ out) {
    int gw = (blockIdx.x * blockDim.x + threadIdx.x) >> 5;
    int lane = threadIdx.x & 31;
    if (gw >= BS * VDIM) return;
    int b = gw >> 9, j = gw & (VDIM - 1);
    const float* x = g_ctx + b * (NH * VDIM);
    const float* w = Wm + (size_t)j * (NH * VDIM);
    float acc = 0.0f;
    for (int k = lane; k < NH * VDIM; k += 32) acc += x[k] * w[k];
    #pragma unroll
    for (int o = 16; o; o >>= 1) acc += __shfl_xor_sync(0xffffffffu, acc, o);
    if (!lane) out[gw] = acc + bm[j];
}

// ---------------- launch ----------------
extern "C" void kernel_launch(void* const* d_in, const int* in_sizes, int n_in,
                              void* d_out, int out_size) {
    const float* dec_state  = (const float*)d_in[0];
    const float* enc_feat   = (const float*)d_in[1];
    const int*   enc_len    = (const int*)  d_in[2];
    const float* Wq         = (const float*)d_in[3];
    const float* bq         = (const float*)d_in[4];
    const float* Wk         = (const float*)d_in[5];
    const float* bk         = (const float*)d_in[6];
    const float* Wv         = (const float*)d_in[7];
    const float* bv         = (const float*)d_in[8];
    const float* loc_conv_w = (const float*)d_in[9];
    const float* loc_proj_w = (const float*)d_in[10];
    const float* gen_w      = (const float*)d_in[11];
    const float* gen_b      = (const float*)d_in[12];
    const float* merge_w    = (const float*)d_in[13];
    const float* merge_b    = (const float*)d_in[14];

    float* out = (float*)d_out;
    float* out_attn = out;                       // [8,4,2048]
    float* out_ctx  = out + BS * NH * TS;        // [8,512]

    static float *pP = nullptr, *pQ = nullptr, *pConvc = nullptr, *pLocc = nullptr;
    static __half *pAh = nullptr, *pBkh = nullptr, *pBvh = nullptr;
    if (!pP) {
        cudaGetSymbolAddress((void**)&pP,     g_P);
        cudaGetSymbolAddress((void**)&pQ,     g_q);
        cudaGetSymbolAddress((void**)&pConvc, g_convc);
        cudaGetSymbolAddress((void**)&pLocc,  g_locc);
        cudaGetSymbolAddress((void**)&pAh,    g_Ah);
        cudaGetSymbolAddress((void**)&pBkh,   g_Bkh);
        cudaGetSymbolAddress((void**)&pBvh,   g_Bvh);
        cudaFuncSetAttribute(gemm_key_energy, cudaFuncAttributeMaxDynamicSharedMemorySize, GSMEM_BYTES);
        cudaFuncSetAttribute(gemm_val_ctx,    cudaFuncAttributeMaxDynamicSharedMemorySize, GSMEM_BYTES);
    }

    // 0) zero accumulators + prefix sums
    zero_kernel<<<(BS * NH * TS + 255) / 256, 256>>>();
    prefix_kernel<<<1, 128>>>(loc_conv_w, pP);

    // 1) compact conv + loc projection (M=3072, K=100)
    convc_kernel<<<(MLOC * KN + 255) / 256, 256>>>(enc_len, pConvc);
    {
        dim3 gl(DIM / 128, MLOC / 128);
        gemm_tanh<<<gl, 256>>>(pConvc, loc_proj_w, nullptr, pLocc, MLOC, DIM, KN);
    }

    // 2) fp16 conversion of GEMM inputs
    {
        int nA4 = MDIM * VDIM / 4;
        f16_conv_kernel<<<(nA4 + 255) / 256, 256>>>((const float4*)enc_feat, (__half2*)pAh, nA4);
        int nB4 = NKV * VDIM / 4;
        f16_conv_kernel<<<(nB4 + 255) / 256, 256>>>((const float4*)Wk, (__half2*)pBkh, nB4);
        f16_conv_kernel<<<(nB4 + 255) / 256, 256>>>((const float4*)Wv, (__half2*)pBvh, nB4);
    }

    // 3) query projection
    query_kernel<<<(BS * NKV * 32 + 255) / 256, 256>>>(dec_state, Wq, bq, pQ);

    // 4) key GEMM with fused energy reduction
    {
        dim3 gk(NKV / 128, MDIM / 128);
        gemm_key_energy<<<gk, 256, GSMEM_BYTES>>>(pAh, pBkh, bk, pQ, gen_w, enc_len);
    }

    // 5) softmax -> attn (d_out)
    softmax_kernel<<<BS * NH, 256>>>(enc_len, out_attn, gen_b);

    // 6) value GEMM with fused context reduction
    {
        dim3 gk(NKV / 128, MDIM / 128);
        gemm_val_ctx<<<gk, 256, GSMEM_BYTES>>>(pAh, pBvh, bv, out_attn);
    }

    // 7) merge
    merge_kernel<<<(BS * VDIM * 32 + 255) / 256, 256>>>(merge_w, merge_b, out_ctx);
}

// round 6
// speedup vs baseline: 5.6839x; 1.0618x over previous
#include <cuda_runtime.h>
#include <cuda_fp16.h>
#include <math.h>
#include <cstdint>

// Problem constants
#define BS   8
#define TS   2048
#define NH   4
#define DIM  512
#define VDIM 512
#define QDIM 1024
#define KS   100
#define KN   100
#define TEMP 0.5f

#define MDIM (BS*TS)         // 16384 rows for K/V GEMMs
#define NKV  (NH*DIM)        // 2048
#define LROWS 384            // padded compact loc rows per batch (302 used)
#define MLOC (BS*LROWS)      // 3072

// ---------------- scratch (static device allocations) ----------------
__device__ float g_P[KN * (2*KS+2)];             // prefix sums [100][202]
__device__ float g_q[BS * NKV];                  // tanh(query) [8][2048]
__device__ float g_convc[MLOC * KN];             // compact conv [3072][100]
__device__ float g_locc[(size_t)MLOC * DIM];     // compact loc  [3072][512]
__device__ float g_energy[BS * NH * TS];         // raw energy partial sums
__device__ float g_ctx[BS * NH * VDIM];
__device__ __half g_Ah[(size_t)MDIM * VDIM];     // fp16 enc_feat
__device__ __half g_Bkh[NKV * VDIM];             // fp16 Wk
__device__ __half g_Bvh[NKV * VDIM];             // fp16 Wv

// ---------------- fast tanh: 1 - 2/(e^{2x}+1), abs err ~1.2e-7 ----------------
__device__ __forceinline__ float fast_tanh(float x) {
    float e;
    asm("ex2.approx.f32 %0, %1;" : "=f"(e) : "f"(x * 2.8853900817779268f)); // 2*log2(e)
    float r;
    asm("rcp.approx.f32 %0, %1;" : "=f"(r) : "f"(e + 1.0f));
    return fmaf(-2.0f, r, 1.0f);
}

// compact loc row index for timestep t given len
__device__ __forceinline__ int idx_t(int t, int len) {
    if (t < KS) return t;
    if (t <= len - KS - 1) return KS;
    int j = t - (len - KS);
    if (j < 2 * KS) return KS + 1 + j;   // 101..300
    return 301;                          // zero row
}

// ---------------- zero init (energy + ctx) ----------------
__global__ void zero_kernel() {
    int i = blockIdx.x * blockDim.x + threadIdx.x;
    if (i < BS * NH * TS) g_energy[i] = 0.0f;
    if (i < BS * NH * VDIM) g_ctx[i] = 0.0f;
}

// ---------------- kernel: fp32 -> fp16 conversion ----------------
__global__ void f16_conv_kernel(const float4* __restrict__ in, __half2* __restrict__ outp, int n4) {
    int i = blockIdx.x * blockDim.x + threadIdx.x;
    if (i >= n4) return;
    float4 v = in[i];
    outp[2*i]   = __floats2half2_rn(v.x, v.y);
    outp[2*i+1] = __floats2half2_rn(v.z, v.w);
}

// ---------------- kernel 0: conv-weight prefix sums ----------------
__global__ void prefix_kernel(const float* __restrict__ w, float* __restrict__ P) {
    int k = threadIdx.x;
    if (k >= KN) return;
    float s = 0.0f;
    P[k * 202 + 0] = 0.0f;
    for (int t = 0; t < 2*KS+1; t++) {
        float ws = 0.0f;
        #pragma unroll
        for (int h = 0; h < NH; h++) ws += w[(k*NH + h)*(2*KS+1) + t];
        s += ws;
        P[k * 202 + t + 1] = s;
    }
}

// ---------------- kernel 1: query projection ----------------
__global__ void query_kernel(const float* __restrict__ dec, const float* __restrict__ Wq,
                             const float* __restrict__ bq, float* __restrict__ q) {
    int gw = (blockIdx.x * blockDim.x + threadIdx.x) >> 5;
    int lane = threadIdx.x & 31;
    if (gw >= BS * NKV) return;
    int b = gw >> 11, n = gw & (NKV - 1);
    const float* x = dec + b * QDIM;
    const float* w = Wq + (size_t)n * QDIM;
    float acc = 0.0f;
    for (int k = lane; k < QDIM; k += 32) acc += x[k] * w[k];
    #pragma unroll
    for (int o = 16; o; o >>= 1) acc += __shfl_xor_sync(0xffffffffu, acc, o);
    if (!lane) q[gw] = fast_tanh(acc + bq[n]);
}

// ---------------- kernel 2: compact conv via prefix diff ----------------
__global__ void convc_kernel(const int* __restrict__ enc_len, float* __restrict__ conv) {
    int idx = blockIdx.x * blockDim.x + threadIdx.x;
    if (idx >= MLOC * KN) return;
    int k = idx % KN;
    int r = (idx / KN) % LROWS;
    int b = idx / (KN * LROWS);
    int len = enc_len[b];
    float v = 0.0f;
    int lo, hi;
    if (r < KS)        { lo = KS - r; hi = 2*KS + 1; }
    else if (r == KS)  { lo = 0;      hi = 2*KS + 1; }
    else if (r <= 3*KS){ lo = 0;      hi = 2*KS - (r - KS - 1); }
    else               { conv[idx] = 0.0f; return; }
    if (hi > lo) v = (g_P[k*202 + hi] - g_P[k*202 + lo]) / (float)len;
    conv[idx] = v;
}

// ---------------- loc projection: 64x64-tile fp32 GEMM + tanh (K=100) ----------------
// C[m][n] = tanh( sum_k A[m][k]*B[n][k] ), BK=20 (5 iters), 4x4 microtile.
#define LBK 20
__global__ __launch_bounds__(256)
void gemm_tanh64(const float* __restrict__ A, const float* __restrict__ B,
                 float* __restrict__ C, int M, int N, int K) {
    __shared__ float As[LBK][68];
    __shared__ float Bs[LBK][68];
    int bm = blockIdx.y * 64;
    int bn = blockIdx.x * 64;
    int tid = threadIdx.x;
    int trow = (tid >> 4) * 4;
    int tcol = (tid & 15) * 4;
    float acc[4][4];
    #pragma unroll
    for (int i = 0; i < 4; i++)
        #pragma unroll
        for (int j = 0; j < 4; j++) acc[i][j] = 0.0f;

    for (int k0 = 0; k0 < K; k0 += LBK) {
        // 64*20 = 1280 elements per matrix, 5 per thread
        #pragma unroll
        for (int s = 0; s < 5; ++s) {
            int e = tid + s * 256;
            int row = e / LBK, kk = e % LBK;
            As[kk][row] = A[(size_t)(bm + row) * K + k0 + kk];
            Bs[kk][row] = B[(size_t)(bn + row) * K + k0 + kk];
        }
        __syncthreads();
        #pragma unroll
        for (int kk = 0; kk < LBK; kk++) {
            float ra[4], rb[4];
            #pragma unroll
            for (int i = 0; i < 4; i++) ra[i] = As[kk][trow + i];
            #pragma unroll
            for (int j = 0; j < 4; j++) rb[j] = Bs[kk][tcol + j];
            #pragma unroll
            for (int i = 0; i < 4; i++)
                #pragma unroll
                for (int j = 0; j < 4; j++) acc[i][j] += ra[i] * rb[j];
        }
        __syncthreads();
    }

    #pragma unroll
    for (int i = 0; i < 4; i++) {
        size_t off = (size_t)(bm + trow + i) * N + bn + tcol;
        #pragma unroll
        for (int j = 0; j < 4; j++)
            C[off + j] = fast_tanh(acc[i][j]);
    }
}

// ================= fp16 mma GEMM core macros =================
#define GSTAGES 3
#define BKK     32
#define PADH    40                        // halfs per smem row (80 B pitch)
#define ATILE_H (128 * PADH)
#define STAGE_H (2 * ATILE_H)
#define GSMEM_BYTES (GSTAGES * STAGE_H * 2)   // 61440 B

__device__ __forceinline__ void mma_f16(float* d,
                                        uint32_t a0, uint32_t a1, uint32_t a2, uint32_t a3,
                                        uint32_t b0, uint32_t b1) {
    asm volatile(
        "mma.sync.aligned.m16n8k16.row.col.f32.f16.f16.f32 "
        "{%0,%1,%2,%3}, {%4,%5,%6,%7}, {%8,%9}, {%0,%1,%2,%3};"
        : "+f"(d[0]), "+f"(d[1]), "+f"(d[2]), "+f"(d[3])
        : "r"(a0), "r"(a1), "r"(a2), "r"(a3), "r"(b0), "r"(b1));
}
__device__ __forceinline__ void cp_async16(uint32_t saddr, const void* gaddr) {
    asm volatile("cp.async.cg.shared.global [%0], [%1], 16;" :: "r"(saddr), "l"(gaddr) : "memory");
}
__device__ __forceinline__ uint32_t smem_u32(const void* p) {
    uint32_t a;
    asm("{ .reg .u64 t; cvta.to.shared.u64 t, %1; cvt.u32.u64 %0, t; }" : "=r"(a) : "l"(p));
    return a;
}

// mainloop shared by both fused GEMMs; leaves acc[4][4][4] filled.
// rows: bm + wm*64 + mt*16 + tr (+8), cols: bn + wn*32 + nt*8 + tc*2 (+1)
#define GEMM_MAINLOOP(A, B, K)                                                         \
    const int tid = threadIdx.x;                                                       \
    const int wid = tid >> 5, lane = tid & 31;                                         \
    const int wm = wid & 1, wn = wid >> 1;                                             \
    const int tr = lane >> 2, tc = lane & 3;                                           \
    const int bm = blockIdx.y * 128, bn = blockIdx.x * 128;                            \
    const int NT = (K) / BKK;                                                          \
    const uint32_t smb = smem_u32(smh);                                                \
    float acc[4][4][4];                                                                \
    _Pragma("unroll") for (int mt = 0; mt < 4; mt++)                                   \
        _Pragma("unroll") for (int nt = 0; nt < 4; nt++)                               \
            _Pragma("unroll") for (int r = 0; r < 4; r++) acc[mt][nt][r] = 0.0f;       \
    _Pragma("unroll") for (int s = 0; s < GSTAGES - 1; ++s) {                          \
        uint32_t sa = smb + (s * STAGE_H) * 2;                                         \
        uint32_t sb = sa + ATILE_H * 2;                                                \
        int kbase = s * BKK;                                                           \
        _Pragma("unroll") for (int j = 0; j < 2; ++j) {                                \
            int c = tid + j * 256;                                                     \
            int row = c >> 2, kc = c & 3;                                              \
            uint32_t soff = row * (PADH * 2) + kc * 16;                                \
            cp_async16(sa + soff, (A) + (size_t)(bm + row) * (K) + kbase + kc * 8);    \
            cp_async16(sb + soff, (B) + (size_t)(bn + row) * (K) + kbase + kc * 8);    \
        }                                                                              \
        asm volatile("cp.async.commit_group;" ::: "memory");                           \
    }                                                                                  \
    for (int kt = 0; kt < NT; ++kt) {                                                  \
        asm volatile("cp.async.wait_group %0;" :: "n"(GSTAGES - 2) : "memory");        \
        __syncthreads();                                                               \
        {                                                                              \
            int tl = kt + GSTAGES - 1;                                                 \
            if (tl < NT) {                                                             \
                int s = tl % GSTAGES;                                                  \
                uint32_t sa = smb + (s * STAGE_H) * 2;                                 \
                uint32_t sb = sa + ATILE_H * 2;                                        \
                int kbase = tl * BKK;                                                  \
                _Pragma("unroll") for (int j = 0; j < 2; ++j) {                        \
                    int c = tid + j * 256;                                             \
                    int row = c >> 2, kc = c & 3;                                      \
                    uint32_t soff = row * (PADH * 2) + kc * 16;                        \
                    cp_async16(sa + soff, (A) + (size_t)(bm + row) * (K) + kbase + kc * 8); \
                    cp_async16(sb + soff, (B) + (size_t)(bn + row) * (K) + kbase + kc * 8); \
                }                                                                      \
            }                                                                          \
            asm volatile("cp.async.commit_group;" ::: "memory");                       \
        }                                                                              \
        const __half* sa = smh + (kt % GSTAGES) * STAGE_H;                             \
        const __half* sb = sa + ATILE_H;                                               \
        _Pragma("unroll") for (int ks = 0; ks < 2; ++ks) {                             \
            int k0 = ks * 16;                                                          \
            uint32_t af[4][4];                                                         \
            _Pragma("unroll") for (int mt = 0; mt < 4; mt++) {                         \
                const __half* p = sa + (wm * 64 + mt * 16 + tr) * PADH + k0 + 2 * tc;  \
                af[mt][0] = *(const uint32_t*)(p);                                     \
                af[mt][1] = *(const uint32_t*)(p + 8 * PADH);                          \
                af[mt][2] = *(const uint32_t*)(p + 8);                                 \
                af[mt][3] = *(const uint32_t*)(p + 8 * PADH + 8);                      \
            }                                                                          \
            uint32_t bf[4][2];                                                         \
            _Pragma("unroll") for (int nt = 0; nt < 4; nt++) {                         \
                const __half* p = sb + (wn * 32 + nt * 8 + tr) * PADH + k0 + 2 * tc;   \
                bf[nt][0] = *(const uint32_t*)(p);                                     \
                bf[nt][1] = *(const uint32_t*)(p + 8);                                 \
            }                                                                          \
            _Pragma("unroll") for (int mt = 0; mt < 4; mt++)                           \
                _Pragma("unroll") for (int nt = 0; nt < 4; nt++)                       \
                    mma_f16(acc[mt][nt], af[mt][0], af[mt][1], af[mt][2], af[mt][3],   \
                            bf[nt][0], bf[nt][1]);                                     \
        }                                                                              \
        __syncthreads();                                                               \
    }

// ---------------- key GEMM + fused energy ----------------
// energy_raw[b,h,t] += sum_n gen_w[d]*tanh( tanh(acc+bk[n]) + q[b,n] + loc[b,idx(t),d] )
__global__ __launch_bounds__(256, 2)
void gemm_key_energy(const __half* __restrict__ A, const __half* __restrict__ B,
                     const float* __restrict__ bias, const float* __restrict__ q,
                     const float* __restrict__ gen_w, const int* __restrict__ enc_len) {
    extern __shared__ __half smh[];
    GEMM_MAINLOOP(A, B, VDIM)

    const int b = bm >> 11;
    const int len = enc_len[b];
    const int h = bn >> 9;
    const int dbase = (bn & 511) + wn * 32;

    float qv[8], wv[8], bv8[8];
    #pragma unroll
    for (int nt = 0; nt < 4; nt++)
        #pragma unroll
        for (int u = 0; u < 2; u++) {
            int d = dbase + nt * 8 + tc * 2 + u;
            int n = (h << 9) + d;
            qv[nt*2+u]  = __ldg(q + b * NKV + n);
            wv[nt*2+u]  = __ldg(gen_w + d);
            bv8[nt*2+u] = __ldg(bias + n);
        }

    float rowsum[8];
    #pragma unroll
    for (int i = 0; i < 8; i++) rowsum[i] = 0.0f;

    #pragma unroll
    for (int mt = 0; mt < 4; mt++) {
        #pragma unroll
        for (int half = 0; half < 2; half++) {
            int r = bm + wm * 64 + mt * 16 + tr + half * 8;
            int t = r & (TS - 1);
            const float* locp = g_locc + (size_t)(b * LROWS + idx_t(t, len)) * DIM + dbase;
            float s = 0.0f;
            #pragma unroll
            for (int nt = 0; nt < 4; nt++)
                #pragma unroll
                for (int u = 0; u < 2; u++) {
                    float kk = fast_tanh(acc[mt][nt][half*2+u] + bv8[nt*2+u]);
                    float lv = locp[nt * 8 + tc * 2 + u];
                    s += wv[nt*2+u] * fast_tanh(kk + qv[nt*2+u] + lv);
                }
            rowsum[mt*2+half] = s;
        }
    }
    // reduce over tc (lane bits 0,1)
    #pragma unroll
    for (int i = 0; i < 8; i++) {
        rowsum[i] += __shfl_xor_sync(0xffffffffu, rowsum[i], 1);
        rowsum[i] += __shfl_xor_sync(0xffffffffu, rowsum[i], 2);
    }
    if (tc == 0) {
        #pragma unroll
        for (int mt = 0; mt < 4; mt++)
            #pragma unroll
            for (int half = 0; half < 2; half++) {
                int r = bm + wm * 64 + mt * 16 + tr + half * 8;
                int t = r & (TS - 1);
                atomicAdd(&g_energy[(b * NH + h) * TS + t], rowsum[mt*2+half]);
            }
    }
}

// ---------------- value GEMM + fused context ----------------
// ctx[b,h,d] += sum_t attn[b,h,t]*tanh(acc+bv[n])
__global__ __launch_bounds__(256, 2)
void gemm_val_ctx(const __half* __restrict__ A, const __half* __restrict__ B,
                  const float* __restrict__ bias, const float* __restrict__ attn) {
    extern __shared__ __half smh[];
    GEMM_MAINLOOP(A, B, VDIM)

    const int b = bm >> 11;
    const int h = bn >> 9;
    const int dbase = (bn & 511) + wn * 32;

    float bv8[8];
    #pragma unroll
    for (int nt = 0; nt < 4; nt++)
        #pragma unroll
        for (int u = 0; u < 2; u++)
            bv8[nt*2+u] = __ldg(bias + (h << 9) + dbase + nt * 8 + tc * 2 + u);

    float colsum[8];
    #pragma unroll
    for (int i = 0; i < 8; i++) colsum[i] = 0.0f;

    #pragma unroll
    for (int mt = 0; mt < 4; mt++) {
        #pragma unroll
        for (int half = 0; half < 2; half++) {
            int r = bm + wm * 64 + mt * 16 + tr + half * 8;
            int t = r & (TS - 1);
            float a_t = __ldg(attn + (b * NH + h) * TS + t);
            #pragma unroll
            for (int nt = 0; nt < 4; nt++)
                #pragma unroll
                for (int u = 0; u < 2; u++)
                    colsum[nt*2+u] += a_t * fast_tanh(acc[mt][nt][half*2+u] + bv8[nt*2+u]);
        }
    }
    // reduce over tr (lane bits 2,3,4)
    #pragma unroll
    for (int i = 0; i < 8; i++) {
        colsum[i] += __shfl_xor_sync(0xffffffffu, colsum[i], 4);
        colsum[i] += __shfl_xor_sync(0xffffffffu, colsum[i], 8);
        colsum[i] += __shfl_xor_sync(0xffffffffu, colsum[i], 16);
    }
    if (tr == 0) {
        #pragma unroll
        for (int nt = 0; nt < 4; nt++)
            #pragma unroll
            for (int u = 0; u < 2; u++)
                atomicAdd(&g_ctx[(b * NH + h) * VDIM + dbase + nt * 8 + tc * 2 + u],
                          colsum[nt*2+u]);
    }
}

// ---------------- masked softmax (applies (x+gb)/TEMP) ----------------
__global__ void softmax_kernel(const int* __restrict__ enc_len, float* __restrict__ attn,
                               const float* __restrict__ gen_b) {
    __shared__ float red[8];
    __shared__ float bcast;
    int bh = blockIdx.x;
    int b = bh >> 2;
    int len = enc_len[b];
    float gb = gen_b[0];
    const float* e = g_energy + bh * TS;
    float* a = attn + bh * TS;
    int tid = threadIdx.x, lane = tid & 31, w = tid >> 5;

    float m = -INFINITY;
    for (int t = tid; t < len; t += 256) m = fmaxf(m, (e[t] + gb) * (1.0f / TEMP));
    #pragma unroll
    for (int o = 16; o; o >>= 1) m = fmaxf(m, __shfl_xor_sync(0xffffffffu, m, o));
    if (!lane) red[w] = m;
    __syncthreads();
    if (tid < 8) {
        float x = red[tid];
        #pragma unroll
        for (int o = 4; o; o >>= 1) x = fmaxf(x, __shfl_xor_sync(0xffu, x, o));
        if (!tid) bcast = x;
    }
    __syncthreads();
    m = bcast;
    __syncthreads();

    float s = 0.0f;
    for (int t = tid; t < len; t += 256) s += expf((e[t] + gb) * (1.0f / TEMP) - m);
    #pragma unroll
    for (int o = 16; o; o >>= 1) s += __shfl_xor_sync(0xffffffffu, s, o);
    if (!lane) red[w] = s;
    __syncthreads();
    if (tid < 8) {
        float x = red[tid];
        #pragma unroll
        for (int o = 4; o; o >>= 1) x += __shfl_xor_sync(0xffu, x, o);
        if (!tid) bcast = x;
    }
    __syncthreads();
    float inv = 1.0f / bcast;
    for (int t = tid; t < TS; t += 256)
        a[t] = (t < len) ? expf((e[t] + gb) * (1.0f / TEMP) - m) * inv : 0.0f;
}

// ---------------- merge projection ----------------
__global__ void merge_kernel(const float* __restrict__ Wm, const float* __restrict__ bm,
                             float* __restrict__ out) {
    int gw = (blockIdx.x * blockDim.x + threadIdx.x) >> 5;
    int lane = threadIdx.x & 31;
    if (gw >= BS * VDIM) return;
    int b = gw >> 9, j = gw & (VDIM - 1);
    const float* x = g_ctx + b * (NH * VDIM);
    const float* w = Wm + (size_t)j * (NH * VDIM);
    float acc = 0.0f;
    for (int k = lane; k < NH * VDIM; k += 32) acc += x[k] * w[k];
    #pragma unroll
    for (int o = 16; o; o >>= 1) acc += __shfl_xor_sync(0xffffffffu, acc, o);
    if (!lane) out[gw] = acc + bm[j];
}

// ---------------- launch ----------------
extern "C" void kernel_launch(void* const* d_in, const int* in_sizes, int n_in,
                              void* d_out, int out_size) {
    const float* dec_state  = (const float*)d_in[0];
    const float* enc_feat   = (const float*)d_in[1];
    const int*   enc_len    = (const int*)  d_in[2];
    const float* Wq         = (const float*)d_in[3];
    const float* bq         = (const float*)d_in[4];
    const float* Wk         = (const float*)d_in[5];
    const float* bk         = (const float*)d_in[6];
    const float* Wv         = (const float*)d_in[7];
    const float* bv         = (const float*)d_in[8];
    const float* loc_conv_w = (const float*)d_in[9];
    const float* loc_proj_w = (const float*)d_in[10];
    const float* gen_w      = (const float*)d_in[11];
    const float* gen_b      = (const float*)d_in[12];
    const float* merge_w    = (const float*)d_in[13];
    const float* merge_b    = (const float*)d_in[14];

    float* out = (float*)d_out;
    float* out_attn = out;                       // [8,4,2048]
    float* out_ctx  = out + BS * NH * TS;        // [8,512]

    static float *pP = nullptr, *pQ = nullptr, *pConvc = nullptr, *pLocc = nullptr;
    static __half *pAh = nullptr, *pBkh = nullptr, *pBvh = nullptr;
    if (!pP) {
        cudaGetSymbolAddress((void**)&pP,     g_P);
        cudaGetSymbolAddress((void**)&pQ,     g_q);
        cudaGetSymbolAddress((void**)&pConvc, g_convc);
        cudaGetSymbolAddress((void**)&pLocc,  g_locc);
        cudaGetSymbolAddress((void**)&pAh,    g_Ah);
        cudaGetSymbolAddress((void**)&pBkh,   g_Bkh);
        cudaGetSymbolAddress((void**)&pBvh,   g_Bvh);
        cudaFuncSetAttribute(gemm_key_energy, cudaFuncAttributeMaxDynamicSharedMemorySize, GSMEM_BYTES);
        cudaFuncSetAttribute(gemm_val_ctx,    cudaFuncAttributeMaxDynamicSharedMemorySize, GSMEM_BYTES);
    }

    // 0) zero accumulators + prefix sums
    zero_kernel<<<(BS * NH * TS + 255) / 256, 256>>>();
    prefix_kernel<<<1, 128>>>(loc_conv_w, pP);

    // 1) compact conv + loc projection (M=3072, K=100)
    convc_kernel<<<(MLOC * KN + 255) / 256, 256>>>(enc_len, pConvc);
    {
        dim3 gl(DIM / 64, MLOC / 64);
        gemm_tanh64<<<gl, 256>>>(pConvc, loc_proj_w, pLocc, MLOC, DIM, KN);
    }

    // 2) fp16 conversion of GEMM inputs
    {
        int nA4 = MDIM * VDIM / 4;
        f16_conv_kernel<<<(nA4 + 255) / 256, 256>>>((const float4*)enc_feat, (__half2*)pAh, nA4);
        int nB4 = NKV * VDIM / 4;
        f16_conv_kernel<<<(nB4 + 255) / 256, 256>>>((const float4*)Wk, (__half2*)pBkh, nB4);
        f16_conv_kernel<<<(nB4 + 255) / 256, 256>>>((const float4*)Wv, (__half2*)pBvh, nB4);
    }

    // 3) query projection
    query_kernel<<<(BS * NKV * 32 + 255) / 256, 256>>>(dec_state, Wq, bq, pQ);

    // 4) key GEMM with fused energy reduction
    {
        dim3 gk(NKV / 128, MDIM / 128);
        gemm_key_energy<<<gk, 256, GSMEM_BYTES>>>(pAh, pBkh, bk, pQ, gen_w, enc_len);
    }

    // 5) softmax -> attn (d_out)
    softmax_kernel<<<BS * NH, 256>>>(enc_len, out_attn, gen_b);

    // 6) value GEMM with fused context reduction
    {
        dim3 gk(NKV / 128, MDIM / 128);
        gemm_val_ctx<<<gk, 256, GSMEM_BYTES>>>(pAh, pBvh, bv, out_attn);
    }

    // 7) merge
    merge_kernel<<<(BS * VDIM * 32 + 255) / 256, 256>>>(merge_w, merge_b, out_ctx);
}

// round 7
// speedup vs baseline: 6.3826x; 1.1229x over previous
#include <cuda_runtime.h>
#include <cuda_fp16.h>
#include <math.h>
#include <cstdint>

// Problem constants
#define BS   8
#define TS   2048
#define NH   4
#define DIM  512
#define VDIM 512
#define QDIM 1024
#define KS   100
#define KN   100
#define TEMP 0.5f

#define MDIM (BS*TS)         // 16384 rows for K/V GEMMs
#define NKV  (NH*DIM)        // 2048
#define LROWS 384            // padded compact loc rows per batch (302 used)
#define MLOC (BS*LROWS)      // 3072

// ---------------- scratch (static device allocations) ----------------
__device__ float g_P[KN * (2*KS+2)];             // prefix sums [100][202]
__device__ float g_q[BS * NKV];                  // tanh(query) [8][2048]
__device__ float g_convc[MLOC * KN];             // compact conv [3072][100]
__device__ float g_locc[(size_t)MLOC * DIM];     // compact loc  [3072][512]
__device__ float g_energy[BS * NH * TS];         // raw energy partial sums
__device__ float g_ctx[BS * NH * VDIM];
__device__ __half g_Ah[(size_t)MDIM * VDIM];     // fp16 enc_feat
__device__ __half g_Bkh[NKV * VDIM];             // fp16 Wk
__device__ __half g_Bvh[NKV * VDIM];             // fp16 Wv

// ---------------- fast tanh: 1 - 2/(e^{2x}+1), abs err ~1.2e-7 ----------------
__device__ __forceinline__ float fast_tanh(float x) {
    float e;
    asm("ex2.approx.f32 %0, %1;" : "=f"(e) : "f"(x * 2.8853900817779268f)); // 2*log2(e)
    float r;
    asm("rcp.approx.f32 %0, %1;" : "=f"(r) : "f"(e + 1.0f));
    return fmaf(-2.0f, r, 1.0f);
}

// compact loc row index for timestep t given len
__device__ __forceinline__ int idx_t(int t, int len) {
    if (t < KS) return t;
    if (t <= len - KS - 1) return KS;
    int j = t - (len - KS);
    if (j < 2 * KS) return KS + 1 + j;   // 101..300
    return 301;                          // zero row
}

// ---------------- kernel: fp32 -> fp16 conversion ----------------
__global__ void f16_conv_kernel(const float4* __restrict__ in, __half2* __restrict__ outp, int n4) {
    int i = blockIdx.x * blockDim.x + threadIdx.x;
    if (i >= n4) return;
    float4 v = in[i];
    outp[2*i]   = __floats2half2_rn(v.x, v.y);
    outp[2*i+1] = __floats2half2_rn(v.z, v.w);
}

// ---------------- kernel 0: conv-weight prefix sums ----------------
__global__ void prefix_kernel(const float* __restrict__ w, float* __restrict__ P) {
    int k = threadIdx.x;
    if (k >= KN) return;
    float s = 0.0f;
    P[k * 202 + 0] = 0.0f;
    for (int t = 0; t < 2*KS+1; t++) {
        float ws = 0.0f;
        #pragma unroll
        for (int h = 0; h < NH; h++) ws += w[(k*NH + h)*(2*KS+1) + t];
        s += ws;
        P[k * 202 + t + 1] = s;
    }
}

// ---------------- kernel 1: query projection ----------------
__global__ void query_kernel(const float* __restrict__ dec, const float* __restrict__ Wq,
                             const float* __restrict__ bq, float* __restrict__ q) {
    int gw = (blockIdx.x * blockDim.x + threadIdx.x) >> 5;
    int lane = threadIdx.x & 31;
    if (gw >= BS * NKV) return;
    int b = gw >> 11, n = gw & (NKV - 1);
    const float* x = dec + b * QDIM;
    const float* w = Wq + (size_t)n * QDIM;
    float acc = 0.0f;
    for (int k = lane; k < QDIM; k += 32) acc += x[k] * w[k];
    #pragma unroll
    for (int o = 16; o; o >>= 1) acc += __shfl_xor_sync(0xffffffffu, acc, o);
    if (!lane) q[gw] = fast_tanh(acc + bq[n]);
}

// ---------------- kernel 2: compact conv via prefix diff (+ zero init) ----------------
__global__ void convc_kernel(const int* __restrict__ enc_len, float* __restrict__ conv) {
    int idx = blockIdx.x * blockDim.x + threadIdx.x;
    // fold zero-init of energy/ctx accumulators into this launch
    if (idx < BS * NH * TS) g_energy[idx] = 0.0f;
    if (idx < BS * NH * VDIM) g_ctx[idx] = 0.0f;
    if (idx >= MLOC * KN) return;
    int k = idx % KN;
    int r = (idx / KN) % LROWS;
    int b = idx / (KN * LROWS);
    int len = enc_len[b];
    float v = 0.0f;
    int lo, hi;
    if (r < KS)        { lo = KS - r; hi = 2*KS + 1; }
    else if (r == KS)  { lo = 0;      hi = 2*KS + 1; }
    else if (r <= 3*KS){ lo = 0;      hi = 2*KS - (r - KS - 1); }
    else               { conv[idx] = 0.0f; return; }
    if (hi > lo) v = (g_P[k*202 + hi] - g_P[k*202 + lo]) / (float)len;
    conv[idx] = v;
}

// ---------------- loc projection: 64x64-tile fp32 GEMM + tanh (K=100) ----------------
#define LBK 20
__global__ __launch_bounds__(256)
void gemm_tanh64(const float* __restrict__ A, const float* __restrict__ B,
                 float* __restrict__ C, int M, int N, int K) {
    __shared__ float As[LBK][68];
    __shared__ float Bs[LBK][68];
    int bm = blockIdx.y * 64;
    int bn = blockIdx.x * 64;
    int tid = threadIdx.x;
    int trow = (tid >> 4) * 4;
    int tcol = (tid & 15) * 4;
    float acc[4][4];
    #pragma unroll
    for (int i = 0; i < 4; i++)
        #pragma unroll
        for (int j = 0; j < 4; j++) acc[i][j] = 0.0f;

    for (int k0 = 0; k0 < K; k0 += LBK) {
        #pragma unroll
        for (int s = 0; s < 5; ++s) {
            int e = tid + s * 256;
            int row = e / LBK, kk = e % LBK;
            As[kk][row] = A[(size_t)(bm + row) * K + k0 + kk];
            Bs[kk][row] = B[(size_t)(bn + row) * K + k0 + kk];
        }
        __syncthreads();
        #pragma unroll
        for (int kk = 0; kk < LBK; kk++) {
            float ra[4], rb[4];
            #pragma unroll
            for (int i = 0; i < 4; i++) ra[i] = As[kk][trow + i];
            #pragma unroll
            for (int j = 0; j < 4; j++) rb[j] = Bs[kk][tcol + j];
            #pragma unroll
            for (int i = 0; i < 4; i++)
                #pragma unroll
                for (int j = 0; j < 4; j++) acc[i][j] += ra[i] * rb[j];
        }
        __syncthreads();
    }

    #pragma unroll
    for (int i = 0; i < 4; i++) {
        size_t off = (size_t)(bm + trow + i) * N + bn + tcol;
        #pragma unroll
        for (int j = 0; j < 4; j++)
            C[off + j] = fast_tanh(acc[i][j]);
    }
}

// ================= fp16 mma GEMM core macros =================
#define GSTAGES 3
#define BKK     32
#define PADH    40                        // halfs per smem row (80 B pitch)
#define ATILE_H (128 * PADH)
#define STAGE_H (2 * ATILE_H)
#define GSMEM_BYTES (GSTAGES * STAGE_H * 2)   // 61440 B

__device__ __forceinline__ void mma_f16(float* d,
                                        uint32_t a0, uint32_t a1, uint32_t a2, uint32_t a3,
                                        uint32_t b0, uint32_t b1) {
    asm volatile(
        "mma.sync.aligned.m16n8k16.row.col.f32.f16.f16.f32 "
        "{%0,%1,%2,%3}, {%4,%5,%6,%7}, {%8,%9}, {%0,%1,%2,%3};"
        : "+f"(d[0]), "+f"(d[1]), "+f"(d[2]), "+f"(d[3])
        : "r"(a0), "r"(a1), "r"(a2), "r"(a3), "r"(b0), "r"(b1));
}
__device__ __forceinline__ void cp_async16(uint32_t saddr, const void* gaddr) {
    asm volatile("cp.async.cg.shared.global [%0], [%1], 16;" :: "r"(saddr), "l"(gaddr) : "memory");
}
__device__ __forceinline__ uint32_t smem_u32(const void* p) {
    uint32_t a;
    asm("{ .reg .u64 t; cvta.to.shared.u64 t, %1; cvt.u32.u64 %0, t; }" : "=r"(a) : "l"(p));
    return a;
}

// mainloop shared by both fused GEMMs; leaves acc[4][4][4] filled.
#define GEMM_MAINLOOP(A, B, K)                                                         \
    const int tid = threadIdx.x;                                                       \
    const int wid = tid >> 5, lane = tid & 31;                                         \
    const int wm = wid & 1, wn = wid >> 1;                                             \
    const int tr = lane >> 2, tc = lane & 3;                                           \
    const int bm = blockIdx.y * 128, bn = blockIdx.x * 128;                            \
    const int NT = (K) / BKK;                                                          \
    const uint32_t smb = smem_u32(smh);                                                \
    float acc[4][4][4];                                                                \
    _Pragma("unroll") for (int mt = 0; mt < 4; mt++)                                   \
        _Pragma("unroll") for (int nt = 0; nt < 4; nt++)                               \
            _Pragma("unroll") for (int r = 0; r < 4; r++) acc[mt][nt][r] = 0.0f;       \
    _Pragma("unroll") for (int s = 0; s < GSTAGES - 1; ++s) {                          \
        uint32_t sa = smb + (s * STAGE_H) * 2;                                         \
        uint32_t sb = sa + ATILE_H * 2;                                                \
        int kbase = s * BKK;                                                           \
        _Pragma("unroll") for (int j = 0; j < 2; ++j) {                                \
            int c = tid + j * 256;                                                     \
            int row = c >> 2, kc = c & 3;                                              \
            uint32_t soff = row * (PADH * 2) + kc * 16;                                \
            cp_async16(sa + soff, (A) + (size_t)(bm + row) * (K) + kbase + kc * 8);    \
            cp_async16(sb + soff, (B) + (size_t)(bn + row) * (K) + kbase + kc * 8);    \
        }                                                                              \
        asm volatile("cp.async.commit_group;" ::: "memory");                           \
    }                                                                                  \
    for (int kt = 0; kt < NT; ++kt) {                                                  \
        asm volatile("cp.async.wait_group %0;" :: "n"(GSTAGES - 2) : "memory");        \
        __syncthreads();                                                               \
        {                                                                              \
            int tl = kt + GSTAGES - 1;                                                 \
            if (tl < NT) {                                                             \
                int s = tl % GSTAGES;                                                  \
                uint32_t sa = smb + (s * STAGE_H) * 2;                                 \
                uint32_t sb = sa + ATILE_H * 2;                                        \
                int kbase = tl * BKK;                                                  \
                _Pragma("unroll") for (int j = 0; j < 2; ++j) {                        \
                    int c = tid + j * 256;                                             \
                    int row = c >> 2, kc = c & 3;                                      \
                    uint32_t soff = row * (PADH * 2) + kc * 16;                        \
                    cp_async16(sa + soff, (A) + (size_t)(bm + row) * (K) + kbase + kc * 8); \
                    cp_async16(sb + soff, (B) + (size_t)(bn + row) * (K) + kbase + kc * 8); \
                }                                                                      \
            }                                                                          \
            asm volatile("cp.async.commit_group;" ::: "memory");                       \
        }                                                                              \
        const __half* sa = smh + (kt % GSTAGES) * STAGE_H;                             \
        const __half* sb = sa + ATILE_H;                                               \
        _Pragma("unroll") for (int ks = 0; ks < 2; ++ks) {                             \
            int k0 = ks * 16;                                                          \
            uint32_t af[4][4];                                                         \
            _Pragma("unroll") for (int mt = 0; mt < 4; mt++) {                         \
                const __half* p = sa + (wm * 64 + mt * 16 + tr) * PADH + k0 + 2 * tc;  \
                af[mt][0] = *(const uint32_t*)(p);                                     \
                af[mt][1] = *(const uint32_t*)(p + 8 * PADH);                          \
                af[mt][2] = *(const uint32_t*)(p + 8);                                 \
                af[mt][3] = *(const uint32_t*)(p + 8 * PADH + 8);                      \
            }                                                                          \
            uint32_t bf[4][2];                                                         \
            _Pragma("unroll") for (int nt = 0; nt < 4; nt++) {                         \
                const __half* p = sb + (wn * 32 + nt * 8 + tr) * PADH + k0 + 2 * tc;   \
                bf[nt][0] = *(const uint32_t*)(p);                                     \
                bf[nt][1] = *(const uint32_t*)(p + 8);                                 \
            }                                                                          \
            _Pragma("unroll") for (int mt = 0; mt < 4; mt++)                           \
                _Pragma("unroll") for (int nt = 0; nt < 4; nt++)                       \
                    mma_f16(acc[mt][nt], af[mt][0], af[mt][1], af[mt][2], af[mt][3],   \
                            bf[nt][0], bf[nt][1]);                                     \
        }                                                                              \
        __syncthreads();                                                               \
    }

// ---------------- key GEMM + fused energy (skips fully-masked tiles) ----------------
__global__ __launch_bounds__(256, 2)
void gemm_key_energy(const __half* __restrict__ A, const __half* __restrict__ B,
                     const float* __restrict__ bias, const float* __restrict__ q,
                     const float* __restrict__ gen_w, const int* __restrict__ enc_len) {
    extern __shared__ __half smh[];
    // tile skip: rows are contiguous t of one batch; t >= len contributes nothing
    {
        int b0 = (int)(blockIdx.y >> 4);
        int t0 = (int)(blockIdx.y & 15) * 128;
        if (t0 >= enc_len[b0]) return;
    }
    GEMM_MAINLOOP(A, B, VDIM)

    const int b = bm >> 11;
    const int len = enc_len[b];
    const int h = bn >> 9;
    const int dbase = (bn & 511) + wn * 32;

    float qv[8], wv[8], bv8[8];
    #pragma unroll
    for (int nt = 0; nt < 4; nt++)
        #pragma unroll
        for (int u = 0; u < 2; u++) {
            int d = dbase + nt * 8 + tc * 2 + u;
            int n = (h << 9) + d;
            qv[nt*2+u]  = __ldg(q + b * NKV + n);
            wv[nt*2+u]  = __ldg(gen_w + d);
            bv8[nt*2+u] = __ldg(bias + n);
        }

    float rowsum[8];
    #pragma unroll
    for (int i = 0; i < 8; i++) rowsum[i] = 0.0f;

    #pragma unroll
    for (int mt = 0; mt < 4; mt++) {
        #pragma unroll
        for (int half = 0; half < 2; half++) {
            int r = bm + wm * 64 + mt * 16 + tr + half * 8;
            int t = r & (TS - 1);
            const float* locp = g_locc + (size_t)(b * LROWS + idx_t(t, len)) * DIM + dbase;
            float s = 0.0f;
            #pragma unroll
            for (int nt = 0; nt < 4; nt++)
                #pragma unroll
                for (int u = 0; u < 2; u++) {
                    float kk = fast_tanh(acc[mt][nt][half*2+u] + bv8[nt*2+u]);
                    float lv = locp[nt * 8 + tc * 2 + u];
                    s += wv[nt*2+u] * fast_tanh(kk + qv[nt*2+u] + lv);
                }
            rowsum[mt*2+half] = s;
        }
    }
    #pragma unroll
    for (int i = 0; i < 8; i++) {
        rowsum[i] += __shfl_xor_sync(0xffffffffu, rowsum[i], 1);
        rowsum[i] += __shfl_xor_sync(0xffffffffu, rowsum[i], 2);
    }
    if (tc == 0) {
        #pragma unroll
        for (int mt = 0; mt < 4; mt++)
            #pragma unroll
            for (int half = 0; half < 2; half++) {
                int r = bm + wm * 64 + mt * 16 + tr + half * 8;
                int t = r & (TS - 1);
                atomicAdd(&g_energy[(b * NH + h) * TS + t], rowsum[mt*2+half]);
            }
    }
}

// ---------------- value GEMM + fused context (skips fully-masked tiles) ----------------
__global__ __launch_bounds__(256, 2)
void gemm_val_ctx(const __half* __restrict__ A, const __half* __restrict__ B,
                  const float* __restrict__ bias, const float* __restrict__ attn,
                  const int* __restrict__ enc_len) {
    extern __shared__ __half smh[];
    {
        int b0 = (int)(blockIdx.y >> 4);
        int t0 = (int)(blockIdx.y & 15) * 128;
        if (t0 >= enc_len[b0]) return;   // attn[t]=0 for all rows -> zero contribution
    }
    GEMM_MAINLOOP(A, B, VDIM)

    const int b = bm >> 11;
    const int h = bn >> 9;
    const int dbase = (bn & 511) + wn * 32;

    float bv8[8];
    #pragma unroll
    for (int nt = 0; nt < 4; nt++)
        #pragma unroll
        for (int u = 0; u < 2; u++)
            bv8[nt*2+u] = __ldg(bias + (h << 9) + dbase + nt * 8 + tc * 2 + u);

    float colsum[8];
    #pragma unroll
    for (int i = 0; i < 8; i++) colsum[i] = 0.0f;

    #pragma unroll
    for (int mt = 0; mt < 4; mt++) {
        #pragma unroll
        for (int half = 0; half < 2; half++) {
            int r = bm + wm * 64 + mt * 16 + tr + half * 8;
            int t = r & (TS - 1);
            float a_t = __ldg(attn + (b * NH + h) * TS + t);
            #pragma unroll
            for (int nt = 0; nt < 4; nt++)
                #pragma unroll
                for (int u = 0; u < 2; u++)
                    colsum[nt*2+u] += a_t * fast_tanh(acc[mt][nt][half*2+u] + bv8[nt*2+u]);
        }
    }
    #pragma unroll
    for (int i = 0; i < 8; i++) {
        colsum[i] += __shfl_xor_sync(0xffffffffu, colsum[i], 4);
        colsum[i] += __shfl_xor_sync(0xffffffffu, colsum[i], 8);
        colsum[i] += __shfl_xor_sync(0xffffffffu, colsum[i], 16);
    }
    if (tr == 0) {
        #pragma unroll
        for (int nt = 0; nt < 4; nt++)
            #pragma unroll
            for (int u = 0; u < 2; u++)
                atomicAdd(&g_ctx[(b * NH + h) * VDIM + dbase + nt * 8 + tc * 2 + u],
                          colsum[nt*2+u]);
    }
}

// ---------------- masked softmax (applies (x+gb)/TEMP) ----------------
__global__ void softmax_kernel(const int* __restrict__ enc_len, float* __restrict__ attn,
                               const float* __restrict__ gen_b) {
    __shared__ float red[8];
    __shared__ float bcast;
    int bh = blockIdx.x;
    int b = bh >> 2;
    int len = enc_len[b];
    float gb = gen_b[0];
    const float* e = g_energy + bh * TS;
    float* a = attn + bh * TS;
    int tid = threadIdx.x, lane = tid & 31, w = tid >> 5;

    float m = -INFINITY;
    for (int t = tid; t < len; t += 256) m = fmaxf(m, (e[t] + gb) * (1.0f / TEMP));
    #pragma unroll
    for (int o = 16; o; o >>= 1) m = fmaxf(m, __shfl_xor_sync(0xffffffffu, m, o));
    if (!lane) red[w] = m;
    __syncthreads();
    if (tid < 8) {
        float x = red[tid];
        #pragma unroll
        for (int o = 4; o; o >>= 1) x = fmaxf(x, __shfl_xor_sync(0xffu, x, o));
        if (!tid) bcast = x;
    }
    __syncthreads();
    m = bcast;
    __syncthreads();

    float s = 0.0f;
    for (int t = tid; t < len; t += 256) s += expf((e[t] + gb) * (1.0f / TEMP) - m);
    #pragma unroll
    for (int o = 16; o; o >>= 1) s += __shfl_xor_sync(0xffffffffu, s, o);
    if (!lane) red[w] = s;
    __syncthreads();
    if (tid < 8) {
        float x = red[tid];
        #pragma unroll
        for (int o = 4; o; o >>= 1) x += __shfl_xor_sync(0xffu, x, o);
        if (!tid) bcast = x;
    }
    __syncthreads();
    float inv = 1.0f / bcast;
    for (int t = tid; t < TS; t += 256)
        a[t] = (t < len) ? expf((e[t] + gb) * (1.0f / TEMP) - m) * inv : 0.0f;
}

// ---------------- merge projection ----------------
__global__ void merge_kernel(const float* __restrict__ Wm, const float* __restrict__ bm,
                             float* __restrict__ out) {
    int gw = (blockIdx.x * blockDim.x + threadIdx.x) >> 5;
    int lane = threadIdx.x & 31;
    if (gw >= BS * VDIM) return;
    int b = gw >> 9, j = gw & (VDIM - 1);
    const float* x = g_ctx + b * (NH * VDIM);
    const float* w = Wm + (size_t)j * (NH * VDIM);
    float acc = 0.0f;
    for (int k = lane; k < NH * VDIM; k += 32) acc += x[k] * w[k];
    #pragma unroll
    for (int o = 16; o; o >>= 1) acc += __shfl_xor_sync(0xffffffffu, acc, o);
    if (!lane) out[gw] = acc + bm[j];
}

// ---------------- launch ----------------
extern "C" void kernel_launch(void* const* d_in, const int* in_sizes, int n_in,
                              void* d_out, int out_size) {
    const float* dec_state  = (const float*)d_in[0];
    const float* enc_feat   = (const float*)d_in[1];
    const int*   enc_len    = (const int*)  d_in[2];
    const float* Wq         = (const float*)d_in[3];
    const float* bq         = (const float*)d_in[4];
    const float* Wk         = (const float*)d_in[5];
    const float* bk         = (const float*)d_in[6];
    const float* Wv         = (const float*)d_in[7];
    const float* bv         = (const float*)d_in[8];
    const float* loc_conv_w = (const float*)d_in[9];
    const float* loc_proj_w = (const float*)d_in[10];
    const float* gen_w      = (const float*)d_in[11];
    const float* gen_b      = (const float*)d_in[12];
    const float* merge_w    = (const float*)d_in[13];
    const float* merge_b    = (const float*)d_in[14];

    float* out = (float*)d_out;
    float* out_attn = out;                       // [8,4,2048]
    float* out_ctx  = out + BS * NH * TS;        // [8,512]

    static float *pP = nullptr, *pQ = nullptr, *pConvc = nullptr, *pLocc = nullptr;
    static __half *pAh = nullptr, *pBkh = nullptr, *pBvh = nullptr;
    if (!pP) {
        cudaGetSymbolAddress((void**)&pP,     g_P);
        cudaGetSymbolAddress((void**)&pQ,     g_q);
        cudaGetSymbolAddress((void**)&pConvc, g_convc);
        cudaGetSymbolAddress((void**)&pLocc,  g_locc);
        cudaGetSymbolAddress((void**)&pAh,    g_Ah);
        cudaGetSymbolAddress((void**)&pBkh,   g_Bkh);
        cudaGetSymbolAddress((void**)&pBvh,   g_Bvh);
        cudaFuncSetAttribute(gemm_key_energy, cudaFuncAttributeMaxDynamicSharedMemorySize, GSMEM_BYTES);
        cudaFuncSetAttribute(gemm_val_ctx,    cudaFuncAttributeMaxDynamicSharedMemorySize, GSMEM_BYTES);
    }

    // 0) prefix sums
    prefix_kernel<<<1, 128>>>(loc_conv_w, pP);

    // 1) compact conv (+ zero init) + loc projection (M=3072, K=100)
    convc_kernel<<<(MLOC * KN + 255) / 256, 256>>>(enc_len, pConvc);
    {
        dim3 gl(DIM / 64, MLOC / 64);
        gemm_tanh64<<<gl, 256>>>(pConvc, loc_proj_w, pLocc, MLOC, DIM, KN);
    }

    // 2) fp16 conversion of GEMM inputs
    {
        int nA4 = MDIM * VDIM / 4;
        f16_conv_kernel<<<(nA4 + 255) / 256, 256>>>((const float4*)enc_feat, (__half2*)pAh, nA4);
        int nB4 = NKV * VDIM / 4;
        f16_conv_kernel<<<(nB4 + 255) / 256, 256>>>((const float4*)Wk, (__half2*)pBkh, nB4);
        f16_conv_kernel<<<(nB4 + 255) / 256, 256>>>((const float4*)Wv, (__half2*)pBvh, nB4);
    }

    // 3) query projection
    query_kernel<<<(BS * NKV * 32 + 255) / 256, 256>>>(dec_state, Wq, bq, pQ);

    // 4) key GEMM with fused energy reduction (tile-skipping)
    {
        dim3 gk(NKV / 128, MDIM / 128);
        gemm_key_energy<<<gk, 256, GSMEM_BYTES>>>(pAh, pBkh, bk, pQ, gen_w, enc_len);
    }

    // 5) softmax -> attn (d_out)
    softmax_kernel<<<BS * NH, 256>>>(enc_len, out_attn, gen_b);

    // 6) value GEMM with fused context reduction (tile-skipping)
    {
        dim3 gk(NKV / 128, MDIM / 128);
        gemm_val_ctx<<<gk, 256, GSMEM_BYTES>>>(pAh, pBvh, bv, out_attn, enc_len);
    }

    // 7) merge
    merge_kernel<<<(BS * VDIM * 32 + 255) / 256, 256>>>(merge_w, merge_b, out_ctx);
}

// round 8
// speedup vs baseline: 6.6034x; 1.0346x over previous
#include <cuda_runtime.h>
#include <cuda_fp16.h>
#include <math.h>
#include <cstdint>

// Problem constants
#define BS   8
#define TS   2048
#define NH   4
#define DIM  512
#define VDIM 512
#define QDIM 1024
#define KS   100
#define KN   100
#define TEMP 0.5f

#define MDIM (BS*TS)         // 16384 rows for K/V GEMMs
#define NKV  (NH*DIM)        // 2048
#define LROWS 384            // padded compact loc rows per batch (302 used)
#define MLOC (BS*LROWS)      // 3072

// ---------------- scratch (static device allocations) ----------------
__device__ float g_P[KN * (2*KS+2)];             // prefix sums [100][202]
__device__ float g_q[BS * NKV];                  // tanh(query) [8][2048]
__device__ float g_convc[MLOC * KN];             // compact conv [3072][100]
__device__ float g_locc[(size_t)MLOC * DIM];     // compact loc  [3072][512]
__device__ float g_energy[BS * NH * TS];         // raw energy partial sums
__device__ float g_ctx[BS * NH * VDIM];
__device__ __half g_Ah[(size_t)MDIM * VDIM];     // fp16 enc_feat
__device__ __half g_Bkh[NKV * VDIM];             // fp16 Wk
__device__ __half g_Bvh[NKV * VDIM];             // fp16 Wv

// ---------------- fast tanh: 1 - 2/(e^{2x}+1), abs err ~1.2e-7 ----------------
__device__ __forceinline__ float fast_tanh(float x) {
    float e;
    asm("ex2.approx.f32 %0, %1;" : "=f"(e) : "f"(x * 2.8853900817779268f)); // 2*log2(e)
    float r;
    asm("rcp.approx.f32 %0, %1;" : "=f"(r) : "f"(e + 1.0f));
    return fmaf(-2.0f, r, 1.0f);
}

// compact loc row index for timestep t given len
__device__ __forceinline__ int idx_t(int t, int len) {
    if (t < KS) return t;
    if (t <= len - KS - 1) return KS;
    int j = t - (len - KS);
    if (j < 2 * KS) return KS + 1 + j;   // 101..300
    return 301;                          // zero row
}

// ---------------- kernel: fp32 -> fp16 conversion ----------------
__global__ void f16_conv_kernel(const float4* __restrict__ in, __half2* __restrict__ outp, int n4) {
    int i = blockIdx.x * blockDim.x + threadIdx.x;
    if (i >= n4) return;
    float4 v = in[i];
    outp[2*i]   = __floats2half2_rn(v.x, v.y);
    outp[2*i+1] = __floats2half2_rn(v.z, v.w);
}

// ---------------- kernel 0: conv-weight prefix sums ----------------
__global__ void prefix_kernel(const float* __restrict__ w, float* __restrict__ P) {
    int k = threadIdx.x;
    if (k >= KN) return;
    float s = 0.0f;
    P[k * 202 + 0] = 0.0f;
    for (int t = 0; t < 2*KS+1; t++) {
        float ws = 0.0f;
        #pragma unroll
        for (int h = 0; h < NH; h++) ws += w[(k*NH + h)*(2*KS+1) + t];
        s += ws;
        P[k * 202 + t + 1] = s;
    }
}

// ---------------- kernel 1: query projection ----------------
__global__ void query_kernel(const float* __restrict__ dec, const float* __restrict__ Wq,
                             const float* __restrict__ bq, float* __restrict__ q) {
    int gw = (blockIdx.x * blockDim.x + threadIdx.x) >> 5;
    int lane = threadIdx.x & 31;
    if (gw >= BS * NKV) return;
    int b = gw >> 11, n = gw & (NKV - 1);
    const float* x = dec + b * QDIM;
    const float* w = Wq + (size_t)n * QDIM;
    float acc = 0.0f;
    for (int k = lane; k < QDIM; k += 32) acc += x[k] * w[k];
    #pragma unroll
    for (int o = 16; o; o >>= 1) acc += __shfl_xor_sync(0xffffffffu, acc, o);
    if (!lane) q[gw] = fast_tanh(acc + bq[n]);
}

// ---------------- kernel 2: compact conv via prefix diff (+ zero init) ----------------
__global__ void convc_kernel(const int* __restrict__ enc_len, float* __restrict__ conv) {
    int idx = blockIdx.x * blockDim.x + threadIdx.x;
    // fold zero-init of energy/ctx accumulators into this launch
    if (idx < BS * NH * TS) g_energy[idx] = 0.0f;
    if (idx < BS * NH * VDIM) g_ctx[idx] = 0.0f;
    if (idx >= MLOC * KN) return;
    int k = idx % KN;
    int r = (idx / KN) % LROWS;
    int b = idx / (KN * LROWS);
    int len = enc_len[b];
    float v = 0.0f;
    int lo, hi;
    if (r < KS)        { lo = KS - r; hi = 2*KS + 1; }
    else if (r == KS)  { lo = 0;      hi = 2*KS + 1; }
    else if (r <= 3*KS){ lo = 0;      hi = 2*KS - (r - KS - 1); }
    else               { conv[idx] = 0.0f; return; }
    if (hi > lo) v = (g_P[k*202 + hi] - g_P[k*202 + lo]) / (float)len;
    conv[idx] = v;
}

// ---------------- loc projection: 64x64-tile fp32 GEMM + tanh (K=100) ----------------
#define LBK 20
__global__ __launch_bounds__(256)
void gemm_tanh64(const float* __restrict__ A, const float* __restrict__ B,
                 float* __restrict__ C, int M, int N, int K) {
    __shared__ float As[LBK][68];
    __shared__ float Bs[LBK][68];
    int bm = blockIdx.y * 64;
    int bn = blockIdx.x * 64;
    int tid = threadIdx.x;
    int trow = (tid >> 4) * 4;
    int tcol = (tid & 15) * 4;
    float acc[4][4];
    #pragma unroll
    for (int i = 0; i < 4; i++)
        #pragma unroll
        for (int j = 0; j < 4; j++) acc[i][j] = 0.0f;

    for (int k0 = 0; k0 < K; k0 += LBK) {
        #pragma unroll
        for (int s = 0; s < 5; ++s) {
            int e = tid + s * 256;
            int row = e / LBK, kk = e % LBK;
            As[kk][row] = A[(size_t)(bm + row) * K + k0 + kk];
            Bs[kk][row] = B[(size_t)(bn + row) * K + k0 + kk];
        }
        __syncthreads();
        #pragma unroll
        for (int kk = 0; kk < LBK; kk++) {
            float ra[4], rb[4];
            #pragma unroll
            for (int i = 0; i < 4; i++) ra[i] = As[kk][trow + i];
            #pragma unroll
            for (int j = 0; j < 4; j++) rb[j] = Bs[kk][tcol + j];
            #pragma unroll
            for (int i = 0; i < 4; i++)
                #pragma unroll
                for (int j = 0; j < 4; j++) acc[i][j] += ra[i] * rb[j];
        }
        __syncthreads();
    }

    #pragma unroll
    for (int i = 0; i < 4; i++) {
        size_t off = (size_t)(bm + trow + i) * N + bn + tcol;
        #pragma unroll
        for (int j = 0; j < 4; j++)
            C[off + j] = fast_tanh(acc[i][j]);
    }
}

// ================= fp16 mma GEMM core macros =================
#define GSTAGES 3
#define BKK     32
#define PADH    40                        // halfs per smem row (80 B pitch)
#define ATILE_H (128 * PADH)
#define STAGE_H (2 * ATILE_H)
#define GSMEM_BYTES (GSTAGES * STAGE_H * 2)   // 61440 B

__device__ __forceinline__ void mma_f16(float* d,
                                        uint32_t a0, uint32_t a1, uint32_t a2, uint32_t a3,
                                        uint32_t b0, uint32_t b1) {
    asm volatile(
        "mma.sync.aligned.m16n8k16.row.col.f32.f16.f16.f32 "
        "{%0,%1,%2,%3}, {%4,%5,%6,%7}, {%8,%9}, {%0,%1,%2,%3};"
        : "+f"(d[0]), "+f"(d[1]), "+f"(d[2]), "+f"(d[3])
        : "r"(a0), "r"(a1), "r"(a2), "r"(a3), "r"(b0), "r"(b1));
}
__device__ __forceinline__ void cp_async16(uint32_t saddr, const void* gaddr) {
    asm volatile("cp.async.cg.shared.global [%0], [%1], 16;" :: "r"(saddr), "l"(gaddr) : "memory");
}
__device__ __forceinline__ uint32_t smem_u32(const void* p) {
    uint32_t a;
    asm("{ .reg .u64 t; cvta.to.shared.u64 t, %1; cvt.u32.u64 %0, t; }" : "=r"(a) : "l"(p));
    return a;
}

// mainloop shared by both fused GEMMs; leaves acc[4][4][4] filled.
#define GEMM_MAINLOOP(A, B, K)                                                         \
    const int tid = threadIdx.x;                                                       \
    const int wid = tid >> 5, lane = tid & 31;                                         \
    const int wm = wid & 1, wn = wid >> 1;                                             \
    const int tr = lane >> 2, tc = lane & 3;                                           \
    const int bm = blockIdx.y * 128, bn = blockIdx.x * 128;                            \
    const int NT = (K) / BKK;                                                          \
    const uint32_t smb = smem_u32(smh);                                                \
    float acc[4][4][4];                                                                \
    _Pragma("unroll") for (int mt = 0; mt < 4; mt++)                                   \
        _Pragma("unroll") for (int nt = 0; nt < 4; nt++)                               \
            _Pragma("unroll") for (int r = 0; r < 4; r++) acc[mt][nt][r] = 0.0f;       \
    _Pragma("unroll") for (int s = 0; s < GSTAGES - 1; ++s) {                          \
        uint32_t sa = smb + (s * STAGE_H) * 2;                                         \
        uint32_t sb = sa + ATILE_H * 2;                                                \
        int kbase = s * BKK;                                                           \
        _Pragma("unroll") for (int j = 0; j < 2; ++j) {                                \
            int c = tid + j * 256;                                                     \
            int row = c >> 2, kc = c & 3;                                              \
            uint32_t soff = row * (PADH * 2) + kc * 16;                                \
            cp_async16(sa + soff, (A) + (size_t)(bm + row) * (K) + kbase + kc * 8);    \
            cp_async16(sb + soff, (B) + (size_t)(bn + row) * (K) + kbase + kc * 8);    \
        }                                                                              \
        asm volatile("cp.async.commit_group;" ::: "memory");                           \
    }                                                                                  \
    for (int kt = 0; kt < NT; ++kt) {                                                  \
        asm volatile("cp.async.wait_group %0;" :: "n"(GSTAGES - 2) : "memory");        \
        __syncthreads();                                                               \
        {                                                                              \
            int tl = kt + GSTAGES - 1;                                                 \
            if (tl < NT) {                                                             \
                int s = tl % GSTAGES;                                                  \
                uint32_t sa = smb + (s * STAGE_H) * 2;                                 \
                uint32_t sb = sa + ATILE_H * 2;                                        \
                int kbase = tl * BKK;                                                  \
                _Pragma("unroll") for (int j = 0; j < 2; ++j) {                        \
                    int c = tid + j * 256;                                             \
                    int row = c >> 2, kc = c & 3;                                      \
                    uint32_t soff = row * (PADH * 2) + kc * 16;                        \
                    cp_async16(sa + soff, (A) + (size_t)(bm + row) * (K) + kbase + kc * 8); \
                    cp_async16(sb + soff, (B) + (size_t)(bn + row) * (K) + kbase + kc * 8); \
                }                                                                      \
            }                                                                          \
            asm volatile("cp.async.commit_group;" ::: "memory");                       \
        }                                                                              \
        const __half* sa = smh + (kt % GSTAGES) * STAGE_H;                             \
        const __half* sb = sa + ATILE_H;                                               \
        _Pragma("unroll") for (int ks = 0; ks < 2; ++ks) {                             \
            int k0 = ks * 16;                                                          \
            uint32_t af[4][4];                                                         \
            _Pragma("unroll") for (int mt = 0; mt < 4; mt++) {                         \
                const __half* p = sa + (wm * 64 + mt * 16 + tr) * PADH + k0 + 2 * tc;  \
                af[mt][0] = *(const uint32_t*)(p);                                     \
                af[mt][1] = *(const uint32_t*)(p + 8 * PADH);                          \
                af[mt][2] = *(const uint32_t*)(p + 8);                                 \
                af[mt][3] = *(const uint32_t*)(p + 8 * PADH + 8);                      \
            }                                                                          \
            uint32_t bf[4][2];                                                         \
            _Pragma("unroll") for (int nt = 0; nt < 4; nt++) {                         \
                const __half* p = sb + (wn * 32 + nt * 8 + tr) * PADH + k0 + 2 * tc;   \
                bf[nt][0] = *(const uint32_t*)(p);                                     \
                bf[nt][1] = *(const uint32_t*)(p + 8);                                 \
            }                                                                          \
            _Pragma("unroll") for (int mt = 0; mt < 4; mt++)                           \
                _Pragma("unroll") for (int nt = 0; nt < 4; nt++)                       \
                    mma_f16(acc[mt][nt], af[mt][0], af[mt][1], af[mt][2], af[mt][3],   \
                            bf[nt][0], bf[nt][1]);                                     \
        }                                                                              \
        __syncthreads();                                                               \
    }

// ---------------- key GEMM + fused energy (skips fully-masked tiles) ----------------
__global__ __launch_bounds__(256, 2)
void gemm_key_energy(const __half* __restrict__ A, const __half* __restrict__ B,
                     const float* __restrict__ bias, const float* __restrict__ q,
                     const float* __restrict__ gen_w, const int* __restrict__ enc_len) {
    extern __shared__ __half smh[];
    {
        int b0 = (int)(blockIdx.y >> 4);
        int t0 = (int)(blockIdx.y & 15) * 128;
        if (t0 >= enc_len[b0]) return;
    }
    GEMM_MAINLOOP(A, B, VDIM)

    const int b = bm >> 11;
    const int len = enc_len[b];
    const int h = bn >> 9;
    const int dbase = (bn & 511) + wn * 32;

    float qv[8], wv[8], bv8[8];
    #pragma unroll
    for (int nt = 0; nt < 4; nt++)
        #pragma unroll
        for (int u = 0; u < 2; u++) {
            int d = dbase + nt * 8 + tc * 2 + u;
            int n = (h << 9) + d;
            qv[nt*2+u]  = __ldg(q + b * NKV + n);
            wv[nt*2+u]  = __ldg(gen_w + d);
            bv8[nt*2+u] = __ldg(bias + n);
        }

    float rowsum[8];
    #pragma unroll
    for (int i = 0; i < 8; i++) rowsum[i] = 0.0f;

    #pragma unroll
    for (int mt = 0; mt < 4; mt++) {
        #pragma unroll
        for (int half = 0; half < 2; half++) {
            int r = bm + wm * 64 + mt * 16 + tr + half * 8;
            int t = r & (TS - 1);
            const float* locp = g_locc + (size_t)(b * LROWS + idx_t(t, len)) * DIM + dbase;
            float s = 0.0f;
            #pragma unroll
            for (int nt = 0; nt < 4; nt++)
                #pragma unroll
                for (int u = 0; u < 2; u++) {
                    float kk = fast_tanh(acc[mt][nt][half*2+u] + bv8[nt*2+u]);
                    float lv = locp[nt * 8 + tc * 2 + u];
                    s += wv[nt*2+u] * fast_tanh(kk + qv[nt*2+u] + lv);
                }
            rowsum[mt*2+half] = s;
        }
    }
    #pragma unroll
    for (int i = 0; i < 8; i++) {
        rowsum[i] += __shfl_xor_sync(0xffffffffu, rowsum[i], 1);
        rowsum[i] += __shfl_xor_sync(0xffffffffu, rowsum[i], 2);
    }
    if (tc == 0) {
        #pragma unroll
        for (int mt = 0; mt < 4; mt++)
            #pragma unroll
            for (int half = 0; half < 2; half++) {
                int r = bm + wm * 64 + mt * 16 + tr + half * 8;
                int t = r & (TS - 1);
                atomicAdd(&g_energy[(b * NH + h) * TS + t], rowsum[mt*2+half]);
            }
    }
}

// ---------------- value GEMM + fused context (skips fully-masked tiles) ----------------
__global__ __launch_bounds__(256, 2)
void gemm_val_ctx(const __half* __restrict__ A, const __half* __restrict__ B,
                  const float* __restrict__ bias, const float* __restrict__ attn,
                  const int* __restrict__ enc_len) {
    extern __shared__ __half smh[];
    {
        int b0 = (int)(blockIdx.y >> 4);
        int t0 = (int)(blockIdx.y & 15) * 128;
        if (t0 >= enc_len[b0]) return;
    }
    GEMM_MAINLOOP(A, B, VDIM)

    const int b = bm >> 11;
    const int h = bn >> 9;
    const int dbase = (bn & 511) + wn * 32;

    float bv8[8];
    #pragma unroll
    for (int nt = 0; nt < 4; nt++)
        #pragma unroll
        for (int u = 0; u < 2; u++)
            bv8[nt*2+u] = __ldg(bias + (h << 9) + dbase + nt * 8 + tc * 2 + u);

    float colsum[8];
    #pragma unroll
    for (int i = 0; i < 8; i++) colsum[i] = 0.0f;

    #pragma unroll
    for (int mt = 0; mt < 4; mt++) {
        #pragma unroll
        for (int half = 0; half < 2; half++) {
            int r = bm + wm * 64 + mt * 16 + tr + half * 8;
            int t = r & (TS - 1);
            float a_t = __ldg(attn + (b * NH + h) * TS + t);
            #pragma unroll
            for (int nt = 0; nt < 4; nt++)
                #pragma unroll
                for (int u = 0; u < 2; u++)
                    colsum[nt*2+u] += a_t * fast_tanh(acc[mt][nt][half*2+u] + bv8[nt*2+u]);
        }
    }
    #pragma unroll
    for (int i = 0; i < 8; i++) {
        colsum[i] += __shfl_xor_sync(0xffffffffu, colsum[i], 4);
        colsum[i] += __shfl_xor_sync(0xffffffffu, colsum[i], 8);
        colsum[i] += __shfl_xor_sync(0xffffffffu, colsum[i], 16);
    }
    if (tr == 0) {
        #pragma unroll
        for (int nt = 0; nt < 4; nt++)
            #pragma unroll
            for (int u = 0; u < 2; u++)
                atomicAdd(&g_ctx[(b * NH + h) * VDIM + dbase + nt * 8 + tc * 2 + u],
                          colsum[nt*2+u]);
    }
}

// ---------------- masked softmax (applies (x+gb)/TEMP) ----------------
__global__ void softmax_kernel(const int* __restrict__ enc_len, float* __restrict__ attn,
                               const float* __restrict__ gen_b) {
    __shared__ float red[8];
    __shared__ float bcast;
    int bh = blockIdx.x;
    int b = bh >> 2;
    int len = enc_len[b];
    float gb = gen_b[0];
    const float* e = g_energy + bh * TS;
    float* a = attn + bh * TS;
    int tid = threadIdx.x, lane = tid & 31, w = tid >> 5;

    float m = -INFINITY;
    for (int t = tid; t < len; t += 256) m = fmaxf(m, (e[t] + gb) * (1.0f / TEMP));
    #pragma unroll
    for (int o = 16; o; o >>= 1) m = fmaxf(m, __shfl_xor_sync(0xffffffffu, m, o));
    if (!lane) red[w] = m;
    __syncthreads();
    if (tid < 8) {
        float x = red[tid];
        #pragma unroll
        for (int o = 4; o; o >>= 1) x = fmaxf(x, __shfl_xor_sync(0xffu, x, o));
        if (!tid) bcast = x;
    }
    __syncthreads();
    m = bcast;
    __syncthreads();

    float s = 0.0f;
    for (int t = tid; t < len; t += 256) s += expf((e[t] + gb) * (1.0f / TEMP) - m);
    #pragma unroll
    for (int o = 16; o; o >>= 1) s += __shfl_xor_sync(0xffffffffu, s, o);
    if (!lane) red[w] = s;
    __syncthreads();
    if (tid < 8) {
        float x = red[tid];
        #pragma unroll
        for (int o = 4; o; o >>= 1) x += __shfl_xor_sync(0xffu, x, o);
        if (!tid) bcast = x;
    }
    __syncthreads();
    float inv = 1.0f / bcast;
    for (int t = tid; t < TS; t += 256)
        a[t] = (t < len) ? expf((e[t] + gb) * (1.0f / TEMP) - m) * inv : 0.0f;
}

// ---------------- merge projection ----------------
__global__ void merge_kernel(const float* __restrict__ Wm, const float* __restrict__ bm,
                             float* __restrict__ out) {
    int gw = (blockIdx.x * blockDim.x + threadIdx.x) >> 5;
    int lane = threadIdx.x & 31;
    if (gw >= BS * VDIM) return;
    int b = gw >> 9, j = gw & (VDIM - 1);
    const float* x = g_ctx + b * (NH * VDIM);
    const float* w = Wm + (size_t)j * (NH * VDIM);
    float acc = 0.0f;
    for (int k = lane; k < NH * VDIM; k += 32) acc += x[k] * w[k];
    #pragma unroll
    for (int o = 16; o; o >>= 1) acc += __shfl_xor_sync(0xffffffffu, acc, o);
    if (!lane) out[gw] = acc + bm[j];
}

// ---------------- launch ----------------
extern "C" void kernel_launch(void* const* d_in, const int* in_sizes, int n_in,
                              void* d_out, int out_size) {
    const float* dec_state  = (const float*)d_in[0];
    const float* enc_feat   = (const float*)d_in[1];
    const int*   enc_len    = (const int*)  d_in[2];
    const float* Wq         = (const float*)d_in[3];
    const float* bq         = (const float*)d_in[4];
    const float* Wk         = (const float*)d_in[5];
    const float* bk         = (const float*)d_in[6];
    const float* Wv         = (const float*)d_in[7];
    const float* bv         = (const float*)d_in[8];
    const float* loc_conv_w = (const float*)d_in[9];
    const float* loc_proj_w = (const float*)d_in[10];
    const float* gen_w      = (const float*)d_in[11];
    const float* gen_b      = (const float*)d_in[12];
    const float* merge_w    = (const float*)d_in[13];
    const float* merge_b    = (const float*)d_in[14];

    float* out = (float*)d_out;
    float* out_attn = out;                       // [8,4,2048]
    float* out_ctx  = out + BS * NH * TS;        // [8,512]

    static float *pP = nullptr, *pQ = nullptr, *pConvc = nullptr, *pLocc = nullptr;
    static __half *pAh = nullptr, *pBkh = nullptr, *pBvh = nullptr;
    static cudaStream_t sB = nullptr, sC = nullptr;
    static cudaEvent_t evRoot = nullptr, evB = nullptr, evC = nullptr;
    if (!pP) {
        cudaGetSymbolAddress((void**)&pP,     g_P);
        cudaGetSymbolAddress((void**)&pQ,     g_q);
        cudaGetSymbolAddress((void**)&pConvc, g_convc);
        cudaGetSymbolAddress((void**)&pLocc,  g_locc);
        cudaGetSymbolAddress((void**)&pAh,    g_Ah);
        cudaGetSymbolAddress((void**)&pBkh,   g_Bkh);
        cudaGetSymbolAddress((void**)&pBvh,   g_Bvh);
        cudaFuncSetAttribute(gemm_key_energy, cudaFuncAttributeMaxDynamicSharedMemorySize, GSMEM_BYTES);
        cudaFuncSetAttribute(gemm_val_ctx,    cudaFuncAttributeMaxDynamicSharedMemorySize, GSMEM_BYTES);
        cudaStreamCreateWithFlags(&sB, cudaStreamNonBlocking);
        cudaStreamCreateWithFlags(&sC, cudaStreamNonBlocking);
        cudaEventCreateWithFlags(&evRoot, cudaEventDisableTiming);
        cudaEventCreateWithFlags(&evB, cudaEventDisableTiming);
        cudaEventCreateWithFlags(&evC, cudaEventDisableTiming);
    }

    // ---- fork: three independent prologue branches ----
    cudaEventRecord(evRoot, 0);
    cudaStreamWaitEvent(sB, evRoot, 0);
    cudaStreamWaitEvent(sC, evRoot, 0);

    // branch B (stream sB): fp16 conversions
    {
        int nA4 = MDIM * VDIM / 4;
        f16_conv_kernel<<<(nA4 + 255) / 256, 256, 0, sB>>>((const float4*)enc_feat, (__half2*)pAh, nA4);
        int nB4 = NKV * VDIM / 4;
        f16_conv_kernel<<<(nB4 + 255) / 256, 256, 0, sB>>>((const float4*)Wk, (__half2*)pBkh, nB4);
        f16_conv_kernel<<<(nB4 + 255) / 256, 256, 0, sB>>>((const float4*)Wv, (__half2*)pBvh, nB4);
        cudaEventRecord(evB, sB);
    }

    // branch C (stream sC): query projection
    {
        query_kernel<<<(BS * NKV * 32 + 255) / 256, 256, 0, sC>>>(dec_state, Wq, bq, pQ);
        cudaEventRecord(evC, sC);
    }

    // main stream: loc path (prefix -> compact conv + zero init -> loc GEMM)
    prefix_kernel<<<1, 128>>>(loc_conv_w, pP);
    convc_kernel<<<(MLOC * KN + 255) / 256, 256>>>(enc_len, pConvc);
    {
        dim3 gl(DIM / 64, MLOC / 64);
        gemm_tanh64<<<gl, 256>>>(pConvc, loc_proj_w, pLocc, MLOC, DIM, KN);
    }

    // ---- join ----
    cudaStreamWaitEvent(0, evB, 0);
    cudaStreamWaitEvent(0, evC, 0);

    // key GEMM with fused energy reduction (tile-skipping)
    {
        dim3 gk(NKV / 128, MDIM / 128);
        gemm_key_energy<<<gk, 256, GSMEM_BYTES>>>(pAh, pBkh, bk, pQ, gen_w, enc_len);
    }

    // softmax -> attn (d_out)
    softmax_kernel<<<BS * NH, 256>>>(enc_len, out_attn, gen_b);

    // value GEMM with fused context reduction (tile-skipping)
    {
        dim3 gk(NKV / 128, MDIM / 128);
        gemm_val_ctx<<<gk, 256, GSMEM_BYTES>>>(pAh, pBvh, bv, out_attn, enc_len);
    }

    // merge
    merge_kernel<<<(BS * VDIM * 32 + 255) / 256, 256>>>(merge_w, merge_b, out_ctx);
}

// round 9
// speedup vs baseline: 7.5904x; 1.1495x over previous
#include <cuda_runtime.h>
#include <cuda_fp16.h>
#include <math.h>
#include <cstdint>

// Problem constants
#define BS   8
#define TS   2048
#define NH   4
#define DIM  512
#define VDIM 512
#define QDIM 1024
#define KS   100
#define KN   100
#define TEMP 0.5f

#define MDIM (BS*TS)         // 16384 rows for K/V GEMMs
#define NKV  (NH*DIM)        // 2048
#define LROWS 384            // padded compact loc rows per batch (302 used)
#define MLOC (BS*LROWS)      // 3072

// ---------------- scratch (static device allocations) ----------------
__device__ float g_P[KN * (2*KS+2)];             // prefix sums [100][202]
__device__ float g_q[BS * NKV];                  // tanh(query) [8][2048]
__device__ float g_convc[MLOC * KN];             // compact conv [3072][100]
__device__ float g_locc[(size_t)MLOC * DIM];     // compact loc  [3072][512]
__device__ float g_energy[BS * NH * TS];         // raw energy partial sums
__device__ float g_ctx[BS * NH * VDIM];
__device__ __half g_Ah[(size_t)MDIM * VDIM];     // fp16 enc_feat
__device__ __half g_Bkh[NKV * VDIM];             // fp16 Wk
__device__ __half g_Bvh[NKV * VDIM];             // fp16 Wv

// ---------------- fast tanh: 1 - 2/(e^{2x}+1), abs err ~1.2e-7 ----------------
__device__ __forceinline__ float fast_tanh(float x) {
    float e;
    asm("ex2.approx.f32 %0, %1;" : "=f"(e) : "f"(x * 2.8853900817779268f)); // 2*log2(e)
    float r;
    asm("rcp.approx.f32 %0, %1;" : "=f"(r) : "f"(e + 1.0f));
    return fmaf(-2.0f, r, 1.0f);
}

// compact loc row index for timestep t given len
__device__ __forceinline__ int idx_t(int t, int len) {
    if (t < KS) return t;
    if (t <= len - KS - 1) return KS;
    int j = t - (len - KS);
    if (j < 2 * KS) return KS + 1 + j;   // 101..300
    return 301;                          // zero row
}

// ---------------- kernel: fp32 -> fp16 conversion ----------------
__global__ void f16_conv_kernel(const float4* __restrict__ in, __half2* __restrict__ outp, int n4) {
    int i = blockIdx.x * blockDim.x + threadIdx.x;
    if (i >= n4) return;
    float4 v = in[i];
    outp[2*i]   = __floats2half2_rn(v.x, v.y);
    outp[2*i+1] = __floats2half2_rn(v.z, v.w);
}

// ---------------- kernel 0: conv-weight prefix sums ----------------
__global__ void prefix_kernel(const float* __restrict__ w, float* __restrict__ P) {
    int k = threadIdx.x;
    if (k >= KN) return;
    float s = 0.0f;
    P[k * 202 + 0] = 0.0f;
    for (int t = 0; t < 2*KS+1; t++) {
        float ws = 0.0f;
        #pragma unroll
        for (int h = 0; h < NH; h++) ws += w[(k*NH + h)*(2*KS+1) + t];
        s += ws;
        P[k * 202 + t + 1] = s;
    }
}

// ---------------- kernel 1: query projection ----------------
__global__ void query_kernel(const float* __restrict__ dec, const float* __restrict__ Wq,
                             const float* __restrict__ bq, float* __restrict__ q) {
    int gw = (blockIdx.x * blockDim.x + threadIdx.x) >> 5;
    int lane = threadIdx.x & 31;
    if (gw >= BS * NKV) return;
    int b = gw >> 11, n = gw & (NKV - 1);
    const float* x = dec + b * QDIM;
    const float* w = Wq + (size_t)n * QDIM;
    float acc = 0.0f;
    for (int k = lane; k < QDIM; k += 32) acc += x[k] * w[k];
    #pragma unroll
    for (int o = 16; o; o >>= 1) acc += __shfl_xor_sync(0xffffffffu, acc, o);
    if (!lane) q[gw] = fast_tanh(acc + bq[n]);
}

// ---------------- kernel 2: compact conv via prefix diff (+ zero init) ----------------
__global__ void convc_kernel(const int* __restrict__ enc_len, float* __restrict__ conv) {
    int idx = blockIdx.x * blockDim.x + threadIdx.x;
    if (idx < BS * NH * TS) g_energy[idx] = 0.0f;
    if (idx < BS * NH * VDIM) g_ctx[idx] = 0.0f;
    if (idx >= MLOC * KN) return;
    int k = idx % KN;
    int r = (idx / KN) % LROWS;
    int b = idx / (KN * LROWS);
    int len = enc_len[b];
    float v = 0.0f;
    int lo, hi;
    if (r < KS)        { lo = KS - r; hi = 2*KS + 1; }
    else if (r == KS)  { lo = 0;      hi = 2*KS + 1; }
    else if (r <= 3*KS){ lo = 0;      hi = 2*KS - (r - KS - 1); }
    else               { conv[idx] = 0.0f; return; }
    if (hi > lo) v = (g_P[k*202 + hi] - g_P[k*202 + lo]) / (float)len;
    conv[idx] = v;
}

// ---------------- loc projection: 64x64-tile fp32 GEMM + tanh (K=100) ----------------
#define LBK 20
__global__ __launch_bounds__(256)
void gemm_tanh64(const float* __restrict__ A, const float* __restrict__ B,
                 float* __restrict__ C, int M, int N, int K) {
    __shared__ float As[LBK][68];
    __shared__ float Bs[LBK][68];
    int bm = blockIdx.y * 64;
    int bn = blockIdx.x * 64;
    int tid = threadIdx.x;
    int trow = (tid >> 4) * 4;
    int tcol = (tid & 15) * 4;
    float acc[4][4];
    #pragma unroll
    for (int i = 0; i < 4; i++)
        #pragma unroll
        for (int j = 0; j < 4; j++) acc[i][j] = 0.0f;

    for (int k0 = 0; k0 < K; k0 += LBK) {
        #pragma unroll
        for (int s = 0; s < 5; ++s) {
            int e = tid + s * 256;
            int row = e / LBK, kk = e % LBK;
            As[kk][row] = A[(size_t)(bm + row) * K + k0 + kk];
            Bs[kk][row] = B[(size_t)(bn + row) * K + k0 + kk];
        }
        __syncthreads();
        #pragma unroll
        for (int kk = 0; kk < LBK; kk++) {
            float ra[4], rb[4];
            #pragma unroll
            for (int i = 0; i < 4; i++) ra[i] = As[kk][trow + i];
            #pragma unroll
            for (int j = 0; j < 4; j++) rb[j] = Bs[kk][tcol + j];
            #pragma unroll
            for (int i = 0; i < 4; i++)
                #pragma unroll
                for (int j = 0; j < 4; j++) acc[i][j] += ra[i] * rb[j];
        }
        __syncthreads();
    }

    #pragma unroll
    for (int i = 0; i < 4; i++) {
        size_t off = (size_t)(bm + trow + i) * N + bn + tcol;
        #pragma unroll
        for (int j = 0; j < 4; j++)
            C[off + j] = fast_tanh(acc[i][j]);
    }
}

// ================= fp16 mma GEMM core macros =================
#define GSTAGES 3
#define BKK     32
#define PADH    40                        // halfs per smem row (80 B pitch)
#define ATILE_H (128 * PADH)
#define STAGE_H (2 * ATILE_H)
#define GSMEM_BYTES (GSTAGES * STAGE_H * 2)   // 61440 B

__device__ __forceinline__ void mma_f16(float* d,
                                        uint32_t a0, uint32_t a1, uint32_t a2, uint32_t a3,
                                        uint32_t b0, uint32_t b1) {
    asm volatile(
        "mma.sync.aligned.m16n8k16.row.col.f32.f16.f16.f32 "
        "{%0,%1,%2,%3}, {%4,%5,%6,%7}, {%8,%9}, {%0,%1,%2,%3};"
        : "+f"(d[0]), "+f"(d[1]), "+f"(d[2]), "+f"(d[3])
        : "r"(a0), "r"(a1), "r"(a2), "r"(a3), "r"(b0), "r"(b1));
}
__device__ __forceinline__ void cp_async16(uint32_t saddr, const void* gaddr) {
    asm volatile("cp.async.cg.shared.global [%0], [%1], 16;" :: "r"(saddr), "l"(gaddr) : "memory");
}
__device__ __forceinline__ uint32_t smem_u32(const void* p) {
    uint32_t a;
    asm("{ .reg .u64 t; cvta.to.shared.u64 t, %1; cvt.u32.u64 %0, t; }" : "=r"(a) : "l"(p));
    return a;
}
__device__ __forceinline__ void ldsm_x4(uint32_t& r0, uint32_t& r1, uint32_t& r2, uint32_t& r3,
                                        uint32_t addr) {
    asm volatile("ldmatrix.sync.aligned.m8n8.x4.shared.b16 {%0,%1,%2,%3}, [%4];"
                 : "=r"(r0), "=r"(r1), "=r"(r2), "=r"(r3) : "r"(addr));
}
__device__ __forceinline__ void ldsm_x2(uint32_t& r0, uint32_t& r1, uint32_t addr) {
    asm volatile("ldmatrix.sync.aligned.m8n8.x2.shared.b16 {%0,%1}, [%2];"
                 : "=r"(r0), "=r"(r1) : "r"(addr));
}

// mainloop shared by both fused GEMMs; leaves acc[4][4][4] filled.
// rows: bm + wm*64 + mt*16 + tr (+8), cols: bn + wn*32 + nt*8 + tc*2 (+1)
// Fragment loads via ldmatrix:
//  A x4: lanes 0-7 -> (m + r, k0), 8-15 -> (m+8+r, k0), 16-23 -> (m+r, k0+8), 24-31 -> (m+8+r, k0+8)
//  B x2: lanes 0-7 -> (n + r, k0), 8-15 -> (n + r, k0+8)
#define GEMM_MAINLOOP(A, B, K)                                                         \
    const int tid = threadIdx.x;                                                       \
    const int wid = tid >> 5, lane = tid & 31;                                         \
    const int wm = wid & 1, wn = wid >> 1;                                             \
    const int tr = lane >> 2, tc = lane & 3;                                           \
    const int bm = blockIdx.y * 128, bn = blockIdx.x * 128;                            \
    const int NT = (K) / BKK;                                                          \
    const uint32_t smb = smem_u32(smh);                                                \
    /* per-thread ldmatrix base addresses (byte offsets within a stage) */             \
    const int aRow = wm * 64 + (lane & 7) + ((lane >> 3) & 1) * 8;                     \
    const int aKh  = (lane >> 4) * 8;                                                  \
    const uint32_t aBase = smb + aRow * (PADH * 2) + aKh * 2;                          \
    const int lB   = lane & 15;                                                        \
    const int bRow = wn * 32 + (lB & 7);                                               \
    const int bKh  = (lB >> 3) * 8;                                                    \
    const uint32_t bBase = smb + ATILE_H * 2 + bRow * (PADH * 2) + bKh * 2;            \
    float acc[4][4][4];                                                                \
    _Pragma("unroll") for (int mt = 0; mt < 4; mt++)                                   \
        _Pragma("unroll") for (int nt = 0; nt < 4; nt++)                               \
            _Pragma("unroll") for (int r = 0; r < 4; r++) acc[mt][nt][r] = 0.0f;       \
    _Pragma("unroll") for (int s = 0; s < GSTAGES - 1; ++s) {                          \
        uint32_t sa = smb + s * (STAGE_H * 2);                                         \
        uint32_t sb = sa + ATILE_H * 2;                                                \
        int kbase = s * BKK;                                                           \
        _Pragma("unroll") for (int j = 0; j < 2; ++j) {                                \
            int c = tid + j * 256;                                                     \
            int row = c >> 2, kc = c & 3;                                              \
            uint32_t soff = row * (PADH * 2) + kc * 16;                                \
            cp_async16(sa + soff, (A) + (size_t)(bm + row) * (K) + kbase + kc * 8);    \
            cp_async16(sb + soff, (B) + (size_t)(bn + row) * (K) + kbase + kc * 8);    \
        }                                                                              \
        asm volatile("cp.async.commit_group;" ::: "memory");                           \
    }                                                                                  \
    for (int kt = 0; kt < NT; ++kt) {                                                  \
        asm volatile("cp.async.wait_group %0;" :: "n"(GSTAGES - 2) : "memory");        \
        __syncthreads();                                                               \
        {                                                                              \
            int tl = kt + GSTAGES - 1;                                                 \
            if (tl < NT) {                                                             \
                int s = tl % GSTAGES;                                                  \
                uint32_t sa = smb + s * (STAGE_H * 2);                                 \
                uint32_t sb = sa + ATILE_H * 2;                                        \
                int kbase = tl * BKK;                                                  \
                _Pragma("unroll") for (int j = 0; j < 2; ++j) {                        \
                    int c = tid + j * 256;                                             \
                    int row = c >> 2, kc = c & 3;                                      \
                    uint32_t soff = row * (PADH * 2) + kc * 16;                        \
                    cp_async16(sa + soff, (A) + (size_t)(bm + row) * (K) + kbase + kc * 8); \
                    cp_async16(sb + soff, (B) + (size_t)(bn + row) * (K) + kbase + kc * 8); \
                }                                                                      \
            }                                                                          \
            asm volatile("cp.async.commit_group;" ::: "memory");                       \
        }                                                                              \
        const uint32_t stOff = (uint32_t)(kt % GSTAGES) * (STAGE_H * 2);               \
        _Pragma("unroll") for (int ks = 0; ks < 2; ++ks) {                             \
            uint32_t af[4][4];                                                         \
            _Pragma("unroll") for (int mt = 0; mt < 4; mt++)                           \
                ldsm_x4(af[mt][0], af[mt][1], af[mt][2], af[mt][3],                    \
                        aBase + stOff + mt * (16 * PADH * 2) + ks * 32);               \
            uint32_t bf[4][2];                                                         \
            _Pragma("unroll") for (int nt = 0; nt < 4; nt++)                           \
                ldsm_x2(bf[nt][0], bf[nt][1],                                          \
                        bBase + stOff + nt * (8 * PADH * 2) + ks * 32);                \
            _Pragma("unroll") for (int mt = 0; mt < 4; mt++)                           \
                _Pragma("unroll") for (int nt = 0; nt < 4; nt++)                       \
                    mma_f16(acc[mt][nt], af[mt][0], af[mt][1], af[mt][2], af[mt][3],   \
                            bf[nt][0], bf[nt][1]);                                     \
        }                                                                              \
        __syncthreads();                                                               \
    }

// ---------------- key GEMM + fused energy (skips fully-masked tiles) ----------------
__global__ __launch_bounds__(256, 2)
void gemm_key_energy(const __half* __restrict__ A, const __half* __restrict__ B,
                     const float* __restrict__ bias, const float* __restrict__ q,
                     const float* __restrict__ gen_w, const int* __restrict__ enc_len) {
    extern __shared__ __half smh[];
    {
        int b0 = (int)(blockIdx.y >> 4);
        int t0 = (int)(blockIdx.y & 15) * 128;
        if (t0 >= enc_len[b0]) return;
    }
    GEMM_MAINLOOP(A, B, VDIM)

    const int b = bm >> 11;
    const int len = enc_len[b];
    const int h = bn >> 9;
    const int dbase = (bn & 511) + wn * 32;

    float qv[8], wv[8], bv8[8];
    #pragma unroll
    for (int nt = 0; nt < 4; nt++)
        #pragma unroll
        for (int u = 0; u < 2; u++) {
            int d = dbase + nt * 8 + tc * 2 + u;
            int n = (h << 9) + d;
            qv[nt*2+u]  = __ldg(q + b * NKV + n);
            wv[nt*2+u]  = __ldg(gen_w + d);
            bv8[nt*2+u] = __ldg(bias + n);
        }

    float rowsum[8];
    #pragma unroll
    for (int i = 0; i < 8; i++) rowsum[i] = 0.0f;

    #pragma unroll
    for (int mt = 0; mt < 4; mt++) {
        #pragma unroll
        for (int half = 0; half < 2; half++) {
            int r = bm + wm * 64 + mt * 16 + tr + half * 8;
            int t = r & (TS - 1);
            const float* locp = g_locc + (size_t)(b * LROWS + idx_t(t, len)) * DIM + dbase;
            float s = 0.0f;
            #pragma unroll
            for (int nt = 0; nt < 4; nt++)
                #pragma unroll
                for (int u = 0; u < 2; u++) {
                    float kk = fast_tanh(acc[mt][nt][half*2+u] + bv8[nt*2+u]);
                    float lv = locp[nt * 8 + tc * 2 + u];
                    s += wv[nt*2+u] * fast_tanh(kk + qv[nt*2+u] + lv);
                }
            rowsum[mt*2+half] = s;
        }
    }
    #pragma unroll
    for (int i = 0; i < 8; i++) {
        rowsum[i] += __shfl_xor_sync(0xffffffffu, rowsum[i], 1);
        rowsum[i] += __shfl_xor_sync(0xffffffffu, rowsum[i], 2);
    }
    if (tc == 0) {
        #pragma unroll
        for (int mt = 0; mt < 4; mt++)
            #pragma unroll
            for (int half = 0; half < 2; half++) {
                int r = bm + wm * 64 + mt * 16 + tr + half * 8;
                int t = r & (TS - 1);
                atomicAdd(&g_energy[(b * NH + h) * TS + t], rowsum[mt*2+half]);
            }
    }
}

// ---------------- value GEMM + fused context (skips fully-masked tiles) ----------------
__global__ __launch_bounds__(256, 2)
void gemm_val_ctx(const __half* __restrict__ A, const __half* __restrict__ B,
                  const float* __restrict__ bias, const float* __restrict__ attn,
                  const int* __restrict__ enc_len) {
    extern __shared__ __half smh[];
    {
        int b0 = (int)(blockIdx.y >> 4);
        int t0 = (int)(blockIdx.y & 15) * 128;
        if (t0 >= enc_len[b0]) return;
    }
    GEMM_MAINLOOP(A, B, VDIM)

    const int b = bm >> 11;
    const int h = bn >> 9;
    const int dbase = (bn & 511) + wn * 32;

    float bv8[8];
    #pragma unroll
    for (int nt = 0; nt < 4; nt++)
        #pragma unroll
        for (int u = 0; u < 2; u++)
            bv8[nt*2+u] = __ldg(bias + (h << 9) + dbase + nt * 8 + tc * 2 + u);

    float colsum[8];
    #pragma unroll
    for (int i = 0; i < 8; i++) colsum[i] = 0.0f;

    #pragma unroll
    for (int mt = 0; mt < 4; mt++) {
        #pragma unroll
        for (int half = 0; half < 2; half++) {
            int r = bm + wm * 64 + mt * 16 + tr + half * 8;
            int t = r & (TS - 1);
            float a_t = __ldg(attn + (b * NH + h) * TS + t);
            #pragma unroll
            for (int nt = 0; nt < 4; nt++)
                #pragma unroll
                for (int u = 0; u < 2; u++)
                    colsum[nt*2+u] += a_t * fast_tanh(acc[mt][nt][half*2+u] + bv8[nt*2+u]);
        }
    }
    #pragma unroll
    for (int i = 0; i < 8; i++) {
        colsum[i] += __shfl_xor_sync(0xffffffffu, colsum[i], 4);
        colsum[i] += __shfl_xor_sync(0xffffffffu, colsum[i], 8);
        colsum[i] += __shfl_xor_sync(0xffffffffu, colsum[i], 16);
    }
    if (tr == 0) {
        #pragma unroll
        for (int nt = 0; nt < 4; nt++)
            #pragma unroll
            for (int u = 0; u < 2; u++)
                atomicAdd(&g_ctx[(b * NH + h) * VDIM + dbase + nt * 8 + tc * 2 + u],
                          colsum[nt*2+u]);
    }
}

// ---------------- masked softmax (applies (x+gb)/TEMP) ----------------
__global__ void softmax_kernel(const int* __restrict__ enc_len, float* __restrict__ attn,
                               const float* __restrict__ gen_b) {
    __shared__ float red[8];
    __shared__ float bcast;
    int bh = blockIdx.x;
    int b = bh >> 2;
    int len = enc_len[b];
    float gb = gen_b[0];
    const float* e = g_energy + bh * TS;
    float* a = attn + bh * TS;
    int tid = threadIdx.x, lane = tid & 31, w = tid >> 5;

    float m = -INFINITY;
    for (int t = tid; t < len; t += 256) m = fmaxf(m, (e[t] + gb) * (1.0f / TEMP));
    #pragma unroll
    for (int o = 16; o; o >>= 1) m = fmaxf(m, __shfl_xor_sync(0xffffffffu, m, o));
    if (!lane) red[w] = m;
    __syncthreads();
    if (tid < 8) {
        float x = red[tid];
        #pragma unroll
        for (int o = 4; o; o >>= 1) x = fmaxf(x, __shfl_xor_sync(0xffu, x, o));
        if (!tid) bcast = x;
    }
    __syncthreads();
    m = bcast;
    __syncthreads();

    float s = 0.0f;
    for (int t = tid; t < len; t += 256) s += expf((e[t] + gb) * (1.0f / TEMP) - m);
    #pragma unroll
    for (int o = 16; o; o >>= 1) s += __shfl_xor_sync(0xffffffffu, s, o);
    if (!lane) red[w] = s;
    __syncthreads();
    if (tid < 8) {
        float x = red[tid];
        #pragma unroll
        for (int o = 4; o; o >>= 1) x += __shfl_xor_sync(0xffu, x, o);
        if (!tid) bcast = x;
    }
    __syncthreads();
    float inv = 1.0f / bcast;
    for (int t = tid; t < TS; t += 256)
        a[t] = (t < len) ? expf((e[t] + gb) * (1.0f / TEMP) - m) * inv : 0.0f;
}

// ---------------- merge projection ----------------
__global__ void merge_kernel(const float* __restrict__ Wm, const float* __restrict__ bm,
                             float* __restrict__ out) {
    int gw = (blockIdx.x * blockDim.x + threadIdx.x) >> 5;
    int lane = threadIdx.x & 31;
    if (gw >= BS * VDIM) return;
    int b = gw >> 9, j = gw & (VDIM - 1);
    const float* x = g_ctx + b * (NH * VDIM);
    const float* w = Wm + (size_t)j * (NH * VDIM);
    float acc = 0.0f;
    for (int k = lane; k < NH * VDIM; k += 32) acc += x[k] * w[k];
    #pragma unroll
    for (int o = 16; o; o >>= 1) acc += __shfl_xor_sync(0xffffffffu, acc, o);
    if (!lane) out[gw] = acc + bm[j];
}

// ---------------- launch ----------------
extern "C" void kernel_launch(void* const* d_in, const int* in_sizes, int n_in,
                              void* d_out, int out_size) {
    const float* dec_state  = (const float*)d_in[0];
    const float* enc_feat   = (const float*)d_in[1];
    const int*   enc_len    = (const int*)  d_in[2];
    const float* Wq         = (const float*)d_in[3];
    const float* bq         = (const float*)d_in[4];
    const float* Wk         = (const float*)d_in[5];
    const float* bk         = (const float*)d_in[6];
    const float* Wv         = (const float*)d_in[7];
    const float* bv         = (const float*)d_in[8];
    const float* loc_conv_w = (const float*)d_in[9];
    const float* loc_proj_w = (const float*)d_in[10];
    const float* gen_w      = (const float*)d_in[11];
    const float* gen_b      = (const float*)d_in[12];
    const float* merge_w    = (const float*)d_in[13];
    const float* merge_b    = (const float*)d_in[14];

    float* out = (float*)d_out;
    float* out_attn = out;                       // [8,4,2048]
    float* out_ctx  = out + BS * NH * TS;        // [8,512]

    static float *pP = nullptr, *pQ = nullptr, *pConvc = nullptr, *pLocc = nullptr;
    static __half *pAh = nullptr, *pBkh = nullptr, *pBvh = nullptr;
    static cudaStream_t sB = nullptr, sC = nullptr;
    static cudaEvent_t evRoot = nullptr, evB = nullptr, evC = nullptr;
    if (!pP) {
        cudaGetSymbolAddress((void**)&pP,     g_P);
        cudaGetSymbolAddress((void**)&pQ,     g_q);
        cudaGetSymbolAddress((void**)&pConvc, g_convc);
        cudaGetSymbolAddress((void**)&pLocc,  g_locc);
        cudaGetSymbolAddress((void**)&pAh,    g_Ah);
        cudaGetSymbolAddress((void**)&pBkh,   g_Bkh);
        cudaGetSymbolAddress((void**)&pBvh,   g_Bvh);
        cudaFuncSetAttribute(gemm_key_energy, cudaFuncAttributeMaxDynamicSharedMemorySize, GSMEM_BYTES);
        cudaFuncSetAttribute(gemm_val_ctx,    cudaFuncAttributeMaxDynamicSharedMemorySize, GSMEM_BYTES);
        cudaStreamCreateWithFlags(&sB, cudaStreamNonBlocking);
        cudaStreamCreateWithFlags(&sC, cudaStreamNonBlocking);
        cudaEventCreateWithFlags(&evRoot, cudaEventDisableTiming);
        cudaEventCreateWithFlags(&evB, cudaEventDisableTiming);
        cudaEventCreateWithFlags(&evC, cudaEventDisableTiming);
    }

    // ---- fork: three independent prologue branches ----
    cudaEventRecord(evRoot, 0);
    cudaStreamWaitEvent(sB, evRoot, 0);
    cudaStreamWaitEvent(sC, evRoot, 0);

    // branch B (stream sB): fp16 conversions
    {
        int nA4 = MDIM * VDIM / 4;
        f16_conv_kernel<<<(nA4 + 255) / 256, 256, 0, sB>>>((const float4*)enc_feat, (__half2*)pAh, nA4);
        int nB4 = NKV * VDIM / 4;
        f16_conv_kernel<<<(nB4 + 255) / 256, 256, 0, sB>>>((const float4*)Wk, (__half2*)pBkh, nB4);
        f16_conv_kernel<<<(nB4 + 255) / 256, 256, 0, sB>>>((const float4*)Wv, (__half2*)pBvh, nB4);
        cudaEventRecord(evB, sB);
    }

    // branch C (stream sC): query projection
    {
        query_kernel<<<(BS * NKV * 32 + 255) / 256, 256, 0, sC>>>(dec_state, Wq, bq, pQ);
        cudaEventRecord(evC, sC);
    }

    // main stream: loc path (prefix -> compact conv + zero init -> loc GEMM)
    prefix_kernel<<<1, 128>>>(loc_conv_w, pP);
    convc_kernel<<<(MLOC * KN + 255) / 256, 256>>>(enc_len, pConvc);
    {
        dim3 gl(DIM / 64, MLOC / 64);
        gemm_tanh64<<<gl, 256>>>(pConvc, loc_proj_w, pLocc, MLOC, DIM, KN);
    }

    // ---- join ----
    cudaStreamWaitEvent(0, evB, 0);
    cudaStreamWaitEvent(0, evC, 0);

    // key GEMM with fused energy reduction (tile-skipping)
    {
        dim3 gk(NKV / 128, MDIM / 128);
        gemm_key_energy<<<gk, 256, GSMEM_BYTES>>>(pAh, pBkh, bk, pQ, gen_w, enc_len);
    }

    // softmax -> attn (d_out)
    softmax_kernel<<<BS * NH, 256>>>(enc_len, out_attn, gen_b);

    // value GEMM with fused context reduction (tile-skipping)
    {
        dim3 gk(NKV / 128, MDIM / 128);
        gemm_val_ctx<<<gk, 256, GSMEM_BYTES>>>(pAh, pBvh, bv, out_attn, enc_len);
    }

    // merge
    merge_kernel<<<(BS * VDIM * 32 + 255) / 256, 256>>>(merge_w, merge_b, out_ctx);
}

// round 10
// speedup vs baseline: 7.7091x; 1.0156x over previous
#include <cuda_runtime.h>
#include <cuda_fp16.h>
#include <math.h>
#include <cstdint>

// Problem constants
#define BS   8
#define TS   2048
#define NH   4
#define DIM  512
#define VDIM 512
#define QDIM 1024
#define KS   100
#define KN   100
#define TEMP 0.5f

#define MDIM (BS*TS)         // 16384 rows for K/V GEMMs
#define NKV  (NH*DIM)        // 2048
#define LROWS 384            // padded compact loc rows (302 used), batch-independent
#define MLOC (BS*LROWS)      // 3072 expanded rows

// ---------------- scratch (static device allocations) ----------------
__device__ float g_P[KN * (2*KS+2)];             // prefix sums [100][202]
__device__ float g_q[BS * NKV];                  // tanh(query) [8][2048]
__device__ float g_convr[LROWS * KN];            // batch-independent C [384][100]
__device__ float g_G[LROWS * DIM];               // G = C @ proj^T [384][512]
__device__ float g_locc[(size_t)MLOC * DIM];     // per-batch loc = tanh(G/len) [3072][512]
__device__ float g_energy[BS * NH * TS];         // raw energy partial sums
__device__ float g_ctx[BS * NH * VDIM];
__device__ __half g_Ah[(size_t)MDIM * VDIM];     // fp16 enc_feat
__device__ __half g_Bkh[NKV * VDIM];             // fp16 Wk
__device__ __half g_Bvh[NKV * VDIM];             // fp16 Wv

// ---------------- fast tanh: 1 - 2/(e^{2x}+1), abs err ~1.2e-7 ----------------
__device__ __forceinline__ float fast_tanh(float x) {
    float e;
    asm("ex2.approx.f32 %0, %1;" : "=f"(e) : "f"(x * 2.8853900817779268f)); // 2*log2(e)
    float r;
    asm("rcp.approx.f32 %0, %1;" : "=f"(r) : "f"(e + 1.0f));
    return fmaf(-2.0f, r, 1.0f);
}

// compact loc row index for timestep t given len
__device__ __forceinline__ int idx_t(int t, int len) {
    if (t < KS) return t;
    if (t <= len - KS - 1) return KS;
    int j = t - (len - KS);
    if (j < 2 * KS) return KS + 1 + j;   // 101..300
    return 301;                          // zero row
}

// ---------------- kernel: fp32 -> fp16 conversion ----------------
__global__ void f16_conv_kernel(const float4* __restrict__ in, __half2* __restrict__ outp, int n4) {
    int i = blockIdx.x * blockDim.x + threadIdx.x;
    if (i >= n4) return;
    float4 v = in[i];
    outp[2*i]   = __floats2half2_rn(v.x, v.y);
    outp[2*i+1] = __floats2half2_rn(v.z, v.w);
}

// ---------------- kernel 0: conv-weight prefix sums ----------------
__global__ void prefix_kernel(const float* __restrict__ w, float* __restrict__ P) {
    int k = threadIdx.x;
    if (k >= KN) return;
    float s = 0.0f;
    P[k * 202 + 0] = 0.0f;
    for (int t = 0; t < 2*KS+1; t++) {
        float ws = 0.0f;
        #pragma unroll
        for (int h = 0; h < NH; h++) ws += w[(k*NH + h)*(2*KS+1) + t];
        s += ws;
        P[k * 202 + t + 1] = s;
    }
}

// ---------------- kernel 1: query projection ----------------
__global__ void query_kernel(const float* __restrict__ dec, const float* __restrict__ Wq,
                             const float* __restrict__ bq, float* __restrict__ q) {
    int gw = (blockIdx.x * blockDim.x + threadIdx.x) >> 5;
    int lane = threadIdx.x & 31;
    if (gw >= BS * NKV) return;
    int b = gw >> 11, n = gw & (NKV - 1);
    const float* x = dec + b * QDIM;
    const float* w = Wq + (size_t)n * QDIM;
    float acc = 0.0f;
    for (int k = lane; k < QDIM; k += 32) acc += x[k] * w[k];
    #pragma unroll
    for (int o = 16; o; o >>= 1) acc += __shfl_xor_sync(0xffffffffu, acc, o);
    if (!lane) q[gw] = fast_tanh(acc + bq[n]);
}

// ---------------- kernel 2: batch-independent conv rows (+ zero init) ----------------
// C[r,k] = P[k,hi(r)] - P[k,lo(r)]   (no /len — applied in expand)
__global__ void convr_kernel(float* __restrict__ conv) {
    int idx = blockIdx.x * blockDim.x + threadIdx.x;
    if (idx < BS * NH * TS) g_energy[idx] = 0.0f;
    if (idx < BS * NH * VDIM) g_ctx[idx] = 0.0f;
    if (idx >= LROWS * KN) return;
    int k = idx % KN;
    int r = idx / KN;
    int lo, hi;
    if (r < KS)        { lo = KS - r; hi = 2*KS + 1; }
    else if (r == KS)  { lo = 0;      hi = 2*KS + 1; }
    else if (r <= 3*KS){ lo = 0;      hi = 2*KS - (r - KS - 1); }
    else               { conv[idx] = 0.0f; return; }
    conv[idx] = (hi > lo) ? (g_P[k*202 + hi] - g_P[k*202 + lo]) : 0.0f;
}

// ---------------- G GEMM: 64x64-tile fp32, raw output (K=100) ----------------
#define LBK 20
__global__ __launch_bounds__(256)
void gemm_raw64(const float* __restrict__ A, const float* __restrict__ B,
                float* __restrict__ C, int M, int N, int K) {
    __shared__ float As[LBK][68];
    __shared__ float Bs[LBK][68];
    int bm = blockIdx.y * 64;
    int bn = blockIdx.x * 64;
    int tid = threadIdx.x;
    int trow = (tid >> 4) * 4;
    int tcol = (tid & 15) * 4;
    float acc[4][4];
    #pragma unroll
    for (int i = 0; i < 4; i++)
        #pragma unroll
        for (int j = 0; j < 4; j++) acc[i][j] = 0.0f;

    for (int k0 = 0; k0 < K; k0 += LBK) {
        #pragma unroll
        for (int s = 0; s < 5; ++s) {
            int e = tid + s * 256;
            int row = e / LBK, kk = e % LBK;
            As[kk][row] = A[(size_t)(bm + row) * K + k0 + kk];
            Bs[kk][row] = B[(size_t)(bn + row) * K + k0 + kk];
        }
        __syncthreads();
        #pragma unroll
        for (int kk = 0; kk < LBK; kk++) {
            float ra[4], rb[4];
            #pragma unroll
            for (int i = 0; i < 4; i++) ra[i] = As[kk][trow + i];
            #pragma unroll
            for (int j = 0; j < 4; j++) rb[j] = Bs[kk][tcol + j];
            #pragma unroll
            for (int i = 0; i < 4; i++)
                #pragma unroll
                for (int j = 0; j < 4; j++) acc[i][j] += ra[i] * rb[j];
        }
        __syncthreads();
    }

    #pragma unroll
    for (int i = 0; i < 4; i++) {
        size_t off = (size_t)(bm + trow + i) * N + bn + tcol;
        #pragma unroll
        for (int j = 0; j < 4; j++)
            C[off + j] = acc[i][j];
    }
}

// ---------------- expand: loc[b,r,d] = tanh(G[r,d]/len_b) ----------------
__global__ void loc_expand_kernel(const int* __restrict__ enc_len) {
    int idx = blockIdx.x * blockDim.x + threadIdx.x;   // one float4
    const int per_b = LROWS * DIM / 4;                 // 49152
    if (idx >= BS * per_b) return;
    int b = idx / per_b;
    int rd = idx - b * per_b;
    float invlen = 1.0f / (float)enc_len[b];
    float4 g = ((const float4*)g_G)[rd];
    float4 o;
    o.x = fast_tanh(g.x * invlen);
    o.y = fast_tanh(g.y * invlen);
    o.z = fast_tanh(g.z * invlen);
    o.w = fast_tanh(g.w * invlen);
    ((float4*)g_locc)[(size_t)b * per_b + rd] = o;
}

// ================= fp16 mma GEMM core macros =================
#define GSTAGES 3
#define BKK     32
#define PADH    40                        // halfs per smem row (80 B pitch)
#define ATILE_H (128 * PADH)
#define STAGE_H (2 * ATILE_H)
#define GSMEM_BYTES (GSTAGES * STAGE_H * 2)   // 61440 B

__device__ __forceinline__ void mma_f16(float* d,
                                        uint32_t a0, uint32_t a1, uint32_t a2, uint32_t a3,
                                        uint32_t b0, uint32_t b1) {
    asm volatile(
        "mma.sync.aligned.m16n8k16.row.col.f32.f16.f16.f32 "
        "{%0,%1,%2,%3}, {%4,%5,%6,%7}, {%8,%9}, {%0,%1,%2,%3};"
        : "+f"(d[0]), "+f"(d[1]), "+f"(d[2]), "+f"(d[3])
        : "r"(a0), "r"(a1), "r"(a2), "r"(a3), "r"(b0), "r"(b1));
}
__device__ __forceinline__ void cp_async16(uint32_t saddr, const void* gaddr) {
    asm volatile("cp.async.cg.shared.global [%0], [%1], 16;" :: "r"(saddr), "l"(gaddr) : "memory");
}
__device__ __forceinline__ uint32_t smem_u32(const void* p) {
    uint32_t a;
    asm("{ .reg .u64 t; cvta.to.shared.u64 t, %1; cvt.u32.u64 %0, t; }" : "=r"(a) : "l"(p));
    return a;
}
__device__ __forceinline__ void ldsm_x4(uint32_t& r0, uint32_t& r1, uint32_t& r2, uint32_t& r3,
                                        uint32_t addr) {
    asm volatile("ldmatrix.sync.aligned.m8n8.x4.shared.b16 {%0,%1,%2,%3}, [%4];"
                 : "=r"(r0), "=r"(r1), "=r"(r2), "=r"(r3) : "r"(addr));
}
__device__ __forceinline__ void ldsm_x2(uint32_t& r0, uint32_t& r1, uint32_t addr) {
    asm volatile("ldmatrix.sync.aligned.m8n8.x2.shared.b16 {%0,%1}, [%2];"
                 : "=r"(r0), "=r"(r1) : "r"(addr));
}

// mainloop shared by both fused GEMMs; leaves acc[4][4][4] filled.
// rows: bm + wm*64 + mt*16 + tr (+8), cols: bn + wn*32 + nt*8 + tc*2 (+1)
#define GEMM_MAINLOOP(A, B, K)                                                         \
    const int tid = threadIdx.x;                                                       \
    const int wid = tid >> 5, lane = tid & 31;                                         \
    const int wm = wid & 1, wn = wid >> 1;                                             \
    const int tr = lane >> 2, tc = lane & 3;                                           \
    const int bm = blockIdx.y * 128, bn = blockIdx.x * 128;                            \
    const int NT = (K) / BKK;                                                          \
    const uint32_t smb = smem_u32(smh);                                                \
    const int aRow = wm * 64 + (lane & 7) + ((lane >> 3) & 1) * 8;                     \
    const int aKh  = (lane >> 4) * 8;                                                  \
    const uint32_t aBase = smb + aRow * (PADH * 2) + aKh * 2;                          \
    const int lB   = lane & 15;                                                        \
    const int bRow = wn * 32 + (lB & 7);                                               \
    const int bKh  = (lB >> 3) * 8;                                                    \
    const uint32_t bBase = smb + ATILE_H * 2 + bRow * (PADH * 2) + bKh * 2;            \
    float acc[4][4][4];                                                                \
    _Pragma("unroll") for (int mt = 0; mt < 4; mt++)                                   \
        _Pragma("unroll") for (int nt = 0; nt < 4; nt++)                               \
            _Pragma("unroll") for (int r = 0; r < 4; r++) acc[mt][nt][r] = 0.0f;       \
    _Pragma("unroll") for (int s = 0; s < GSTAGES - 1; ++s) {                          \
        uint32_t sa = smb + s * (STAGE_H * 2);                                         \
        uint32_t sb = sa + ATILE_H * 2;                                                \
        int kbase = s * BKK;                                                           \
        _Pragma("unroll") for (int j = 0; j < 2; ++j) {                                \
            int c = tid + j * 256;                                                     \
            int row = c >> 2, kc = c & 3;                                              \
            uint32_t soff = row * (PADH * 2) + kc * 16;                                \
            cp_async16(sa + soff, (A) + (size_t)(bm + row) * (K) + kbase + kc * 8);    \
            cp_async16(sb + soff, (B) + (size_t)(bn + row) * (K) + kbase + kc * 8);    \
        }                                                                              \
        asm volatile("cp.async.commit_group;" ::: "memory");                           \
    }                                                                                  \
    for (int kt = 0; kt < NT; ++kt) {                                                  \
        asm volatile("cp.async.wait_group %0;" :: "n"(GSTAGES - 2) : "memory");        \
        __syncthreads();                                                               \
        {                                                                              \
            int tl = kt + GSTAGES - 1;                                                 \
            if (tl < NT) {                                                             \
                int s = tl % GSTAGES;                                                  \
                uint32_t sa = smb + s * (STAGE_H * 2);                                 \
                uint32_t sb = sa + ATILE_H * 2;                                        \
                int kbase = tl * BKK;                                                  \
                _Pragma("unroll") for (int j = 0; j < 2; ++j) {                        \
                    int c = tid + j * 256;                                             \
                    int row = c >> 2, kc = c & 3;                                      \
                    uint32_t soff = row * (PADH * 2) + kc * 16;                        \
                    cp_async16(sa + soff, (A) + (size_t)(bm + row) * (K) + kbase + kc * 8); \
                    cp_async16(sb + soff, (B) + (size_t)(bn + row) * (K) + kbase + kc * 8); \
                }                                                                      \
            }                                                                          \
            asm volatile("cp.async.commit_group;" ::: "memory");                       \
        }                                                                              \
        const uint32_t stOff = (uint32_t)(kt % GSTAGES) * (STAGE_H * 2);               \
        _Pragma("unroll") for (int ks = 0; ks < 2; ++ks) {                             \
            uint32_t af[4][4];                                                         \
            _Pragma("unroll") for (int mt = 0; mt < 4; mt++)                           \
                ldsm_x4(af[mt][0], af[mt][1], af[mt][2], af[mt][3],                    \
                        aBase + stOff + mt * (16 * PADH * 2) + ks * 32);               \
            uint32_t bf[4][2];                                                         \
            _Pragma("unroll") for (int nt = 0; nt < 4; nt++)                           \
                ldsm_x2(bf[nt][0], bf[nt][1],                                          \
                        bBase + stOff + nt * (8 * PADH * 2) + ks * 32);                \
            _Pragma("unroll") for (int mt = 0; mt < 4; mt++)                           \
                _Pragma("unroll") for (int nt = 0; nt < 4; nt++)                       \
                    mma_f16(acc[mt][nt], af[mt][0], af[mt][1], af[mt][2], af[mt][3],   \
                            bf[nt][0], bf[nt][1]);                                     \
        }                                                                              \
        __syncthreads();                                                               \
    }

// ---------------- key GEMM + fused energy (skips fully-masked tiles) ----------------
__global__ __launch_bounds__(256, 2)
void gemm_key_energy(const __half* __restrict__ A, const __half* __restrict__ B,
                     const float* __restrict__ bias, const float* __restrict__ q,
                     const float* __restrict__ gen_w, const int* __restrict__ enc_len) {
    extern __shared__ __half smh[];
    {
        int b0 = (int)(blockIdx.y >> 4);
        int t0 = (int)(blockIdx.y & 15) * 128;
        if (t0 >= enc_len[b0]) return;
    }
    GEMM_MAINLOOP(A, B, VDIM)

    const int b = bm >> 11;
    const int len = enc_len[b];
    const int h = bn >> 9;
    const int dbase = (bn & 511) + wn * 32;

    float qv[8], wv[8], bv8[8];
    #pragma unroll
    for (int nt = 0; nt < 4; nt++)
        #pragma unroll
        for (int u = 0; u < 2; u++) {
            int d = dbase + nt * 8 + tc * 2 + u;
            int n = (h << 9) + d;
            qv[nt*2+u]  = __ldg(q + b * NKV + n);
            wv[nt*2+u]  = __ldg(gen_w + d);
            bv8[nt*2+u] = __ldg(bias + n);
        }

    float rowsum[8];
    #pragma unroll
    for (int i = 0; i < 8; i++) rowsum[i] = 0.0f;

    #pragma unroll
    for (int mt = 0; mt < 4; mt++) {
        #pragma unroll
        for (int half = 0; half < 2; half++) {
            int r = bm + wm * 64 + mt * 16 + tr + half * 8;
            int t = r & (TS - 1);
            const float* locp = g_locc + (size_t)(b * LROWS + idx_t(t, len)) * DIM + dbase;
            float s = 0.0f;
            #pragma unroll
            for (int nt = 0; nt < 4; nt++)
                #pragma unroll
                for (int u = 0; u < 2; u++) {
                    float kk = fast_tanh(acc[mt][nt][half*2+u] + bv8[nt*2+u]);
                    float lv = locp[nt * 8 + tc * 2 + u];
                    s += wv[nt*2+u] * fast_tanh(kk + qv[nt*2+u] + lv);
                }
            rowsum[mt*2+half] = s;
        }
    }
    #pragma unroll
    for (int i = 0; i < 8; i++) {
        rowsum[i] += __shfl_xor_sync(0xffffffffu, rowsum[i], 1);
        rowsum[i] += __shfl_xor_sync(0xffffffffu, rowsum[i], 2);
    }
    if (tc == 0) {
        #pragma unroll
        for (int mt = 0; mt < 4; mt++)
            #pragma unroll
            for (int half = 0; half < 2; half++) {
                int r = bm + wm * 64 + mt * 16 + tr + half * 8;
                int t = r & (TS - 1);
                atomicAdd(&g_energy[(b * NH + h) * TS + t], rowsum[mt*2+half]);
            }
    }
}

// ---------------- value GEMM + fused context (skips fully-masked tiles) ----------------
__global__ __launch_bounds__(256, 2)
void gemm_val_ctx(const __half* __restrict__ A, const __half* __restrict__ B,
                  const float* __restrict__ bias, const float* __restrict__ attn,
                  const int* __restrict__ enc_len) {
    extern __shared__ __half smh[];
    {
        int b0 = (int)(blockIdx.y >> 4);
        int t0 = (int)(blockIdx.y & 15) * 128;
        if (t0 >= enc_len[b0]) return;
    }
    GEMM_MAINLOOP(A, B, VDIM)

    const int b = bm >> 11;
    const int h = bn >> 9;
    const int dbase = (bn & 511) + wn * 32;

    float bv8[8];
    #pragma unroll
    for (int nt = 0; nt < 4; nt++)
        #pragma unroll
        for (int u = 0; u < 2; u++)
            bv8[nt*2+u] = __ldg(bias + (h << 9) + dbase + nt * 8 + tc * 2 + u);

    float colsum[8];
    #pragma unroll
    for (int i = 0; i < 8; i++) colsum[i] = 0.0f;

    #pragma unroll
    for (int mt = 0; mt < 4; mt++) {
        #pragma unroll
        for (int half = 0; half < 2; half++) {
            int r = bm + wm * 64 + mt * 16 + tr + half * 8;
            int t = r & (TS - 1);
            float a_t = __ldg(attn + (b * NH + h) * TS + t);
            #pragma unroll
            for (int nt = 0; nt < 4; nt++)
                #pragma unroll
                for (int u = 0; u < 2; u++)
                    colsum[nt*2+u] += a_t * fast_tanh(acc[mt][nt][half*2+u] + bv8[nt*2+u]);
        }
    }
    #pragma unroll
    for (int i = 0; i < 8; i++) {
        colsum[i] += __shfl_xor_sync(0xffffffffu, colsum[i], 4);
        colsum[i] += __shfl_xor_sync(0xffffffffu, colsum[i], 8);
        colsum[i] += __shfl_xor_sync(0xffffffffu, colsum[i], 16);
    }
    if (tr == 0) {
        #pragma unroll
        for (int nt = 0; nt < 4; nt++)
            #pragma unroll
            for (int u = 0; u < 2; u++)
                atomicAdd(&g_ctx[(b * NH + h) * VDIM + dbase + nt * 8 + tc * 2 + u],
                          colsum[nt*2+u]);
    }
}

// ---------------- masked softmax (applies (x+gb)/TEMP) ----------------
__global__ void softmax_kernel(const int* __restrict__ enc_len, float* __restrict__ attn,
                               const float* __restrict__ gen_b) {
    __shared__ float red[8];
    __shared__ float bcast;
    int bh = blockIdx.x;
    int b = bh >> 2;
    int len = enc_len[b];
    float gb = gen_b[0];
    const float* e = g_energy + bh * TS;
    float* a = attn + bh * TS;
    int tid = threadIdx.x, lane = tid & 31, w = tid >> 5;

    float m = -INFINITY;
    for (int t = tid; t < len; t += 256) m = fmaxf(m, (e[t] + gb) * (1.0f / TEMP));
    #pragma unroll
    for (int o = 16; o; o >>= 1) m = fmaxf(m, __shfl_xor_sync(0xffffffffu, m, o));
    if (!lane) red[w] = m;
    __syncthreads();
    if (tid < 8) {
        float x = red[tid];
        #pragma unroll
        for (int o = 4; o; o >>= 1) x = fmaxf(x, __shfl_xor_sync(0xffu, x, o));
        if (!tid) bcast = x;
    }
    __syncthreads();
    m = bcast;
    __syncthreads();

    float s = 0.0f;
    for (int t = tid; t < len; t += 256) s += expf((e[t] + gb) * (1.0f / TEMP) - m);
    #pragma unroll
    for (int o = 16; o; o >>= 1) s += __shfl_xor_sync(0xffffffffu, s, o);
    if (!lane) red[w] = s;
    __syncthreads();
    if (tid < 8) {
        float x = red[tid];
        #pragma unroll
        for (int o = 4; o; o >>= 1) x += __shfl_xor_sync(0xffu, x, o);
        if (!tid) bcast = x;
    }
    __syncthreads();
    float inv = 1.0f / bcast;
    for (int t = tid; t < TS; t += 256)
        a[t] = (t < len) ? expf((e[t] + gb) * (1.0f / TEMP) - m) * inv : 0.0f;
}

// ---------------- merge projection ----------------
__global__ void merge_kernel(const float* __restrict__ Wm, const float* __restrict__ bm,
                             float* __restrict__ out) {
    int gw = (blockIdx.x * blockDim.x + threadIdx.x) >> 5;
    int lane = threadIdx.x & 31;
    if (gw >= BS * VDIM) return;
    int b = gw >> 9, j = gw & (VDIM - 1);
    const float* x = g_ctx + b * (NH * VDIM);
    const float* w = Wm + (size_t)j * (NH * VDIM);
    float acc = 0.0f;
    for (int k = lane; k < NH * VDIM; k += 32) acc += x[k] * w[k];
    #pragma unroll
    for (int o = 16; o; o >>= 1) acc += __shfl_xor_sync(0xffffffffu, acc, o);
    if (!lane) out[gw] = acc + bm[j];
}

// ---------------- launch ----------------
extern "C" void kernel_launch(void* const* d_in, const int* in_sizes, int n_in,
                              void* d_out, int out_size) {
    const float* dec_state  = (const float*)d_in[0];
    const float* enc_feat   = (const float*)d_in[1];
    const int*   enc_len    = (const int*)  d_in[2];
    const float* Wq         = (const float*)d_in[3];
    const float* bq         = (const float*)d_in[4];
    const float* Wk         = (const float*)d_in[5];
    const float* bk         = (const float*)d_in[6];
    const float* Wv         = (const float*)d_in[7];
    const float* bv         = (const float*)d_in[8];
    const float* loc_conv_w = (const float*)d_in[9];
    const float* loc_proj_w = (const float*)d_in[10];
    const float* gen_w      = (const float*)d_in[11];
    const float* gen_b      = (const float*)d_in[12];
    const float* merge_w    = (const float*)d_in[13];
    const float* merge_b    = (const float*)d_in[14];

    float* out = (float*)d_out;
    float* out_attn = out;                       // [8,4,2048]
    float* out_ctx  = out + BS * NH * TS;        // [8,512]

    static float *pP = nullptr, *pQ = nullptr, *pConvr = nullptr, *pG = nullptr;
    static __half *pAh = nullptr, *pBkh = nullptr, *pBvh = nullptr;
    static cudaStream_t sB = nullptr, sC = nullptr;
    static cudaEvent_t evRoot = nullptr, evB = nullptr, evC = nullptr;
    if (!pP) {
        cudaGetSymbolAddress((void**)&pP,     g_P);
        cudaGetSymbolAddress((void**)&pQ,     g_q);
        cudaGetSymbolAddress((void**)&pConvr, g_convr);
        cudaGetSymbolAddress((void**)&pG,     g_G);
        cudaGetSymbolAddress((void**)&pAh,    g_Ah);
        cudaGetSymbolAddress((void**)&pBkh,   g_Bkh);
        cudaGetSymbolAddress((void**)&pBvh,   g_Bvh);
        cudaFuncSetAttribute(gemm_key_energy, cudaFuncAttributeMaxDynamicSharedMemorySize, GSMEM_BYTES);
        cudaFuncSetAttribute(gemm_val_ctx,    cudaFuncAttributeMaxDynamicSharedMemorySize, GSMEM_BYTES);
        cudaStreamCreateWithFlags(&sB, cudaStreamNonBlocking);
        cudaStreamCreateWithFlags(&sC, cudaStreamNonBlocking);
        cudaEventCreateWithFlags(&evRoot, cudaEventDisableTiming);
        cudaEventCreateWithFlags(&evB, cudaEventDisableTiming);
        cudaEventCreateWithFlags(&evC, cudaEventDisableTiming);
    }

    // ---- fork: three independent prologue branches ----
    cudaEventRecord(evRoot, 0);
    cudaStreamWaitEvent(sB, evRoot, 0);
    cudaStreamWaitEvent(sC, evRoot, 0);

    // branch B (stream sB): fp16 conversions (A first — it feeds both GEMM mainloops)
    {
        int nA4 = MDIM * VDIM / 4;
        f16_conv_kernel<<<(nA4 + 255) / 256, 256, 0, sB>>>((const float4*)enc_feat, (__half2*)pAh, nA4);
        int nB4 = NKV * VDIM / 4;
        f16_conv_kernel<<<(nB4 + 255) / 256, 256, 0, sB>>>((const float4*)Wk, (__half2*)pBkh, nB4);
        f16_conv_kernel<<<(nB4 + 255) / 256, 256, 0, sB>>>((const float4*)Wv, (__half2*)pBvh, nB4);
        cudaEventRecord(evB, sB);
    }

    // branch C (stream sC): query projection
    {
        query_kernel<<<(BS * NKV * 32 + 255) / 256, 256, 0, sC>>>(dec_state, Wq, bq, pQ);
        cudaEventRecord(evC, sC);
    }

    // main stream: loc path (prefix -> batch-indep conv + zero -> G GEMM -> expand)
    prefix_kernel<<<1, 128>>>(loc_conv_w, pP);
    convr_kernel<<<(BS * NH * TS + 255) / 256, 256>>>(pConvr);   // 65536 threads: conv + zeroing
    {
        dim3 gl(DIM / 64, LROWS / 64);                           // 8 x 6 CTAs
        gemm_raw64<<<gl, 256>>>(pConvr, loc_proj_w, pG, LROWS, DIM, KN);
    }
    loc_expand_kernel<<<(BS * LROWS * DIM / 4 + 255) / 256, 256>>>(enc_len);

    // ---- join ----
    cudaStreamWaitEvent(0, evB, 0);
    cudaStreamWaitEvent(0, evC, 0);

    // key GEMM with fused energy reduction (tile-skipping)
    {
        dim3 gk(NKV / 128, MDIM / 128);
        gemm_key_energy<<<gk, 256, GSMEM_BYTES>>>(pAh, pBkh, bk, pQ, gen_w, enc_len);
    }

    // softmax -> attn (d_out)
    softmax_kernel<<<BS * NH, 256>>>(enc_len, out_attn, gen_b);

    // value GEMM with fused context reduction (tile-skipping)
    {
        dim3 gk(NKV / 128, MDIM / 128);
        gemm_val_ctx<<<gk, 256, GSMEM_BYTES>>>(pAh, pBvh, bv, out_attn, enc_len);
    }

    // merge
    merge_kernel<<<(BS * VDIM * 32 + 255) / 256, 256>>>(merge_w, merge_b, out_ctx);
}